// round 8
// baseline (speedup 1.0000x reference)
#include <cuda_runtime.h>
#include <cuda_bf16.h>
#include <cstdint>

// =============================================================================
// RAFF_8555574853896 — round 8: all GEMMs on int8 mma.sync.m16n8k32 (2x MACs
// per issue slot vs bf16 k16). Exact 16-bit fixed-point split:
//   x ~= (a1*256 + a0) * 2^-e,  a1,a0 in int8
//   a*b = 65536*a1b1 + 256*(a1b0 + a0b1) + a0b0   (all four terms kept, s32 acc)
// Algebra (validated):
//   scores = q Mt^T q^T / sqrt(D) + rank-1 bias,  Mt = (Wq^T Wk)^T
//   audio  = (w_a^T q) Cov^T + bcomb,             Cov = out_w Wv
// =============================================================================

namespace raff {

constexpr int B = 2048, S = 32, P = 16, D = 1024, H = 512, F = 512;
constexpr long NQ = (long)B * S * D;

constexpr float SQ = 4096.f;        // scale for q, qv, fusion/audio/video (2^12)
constexpr float SW = 131072.f;      // scale for weights, Mt, Cov (2^17)
constexpr float SC_WW = 1.f / (SW * SW);
constexpr float SC_QW = 1.f / (SQ * SW);

// ---------------- static device scratch ----------------
__device__ float g_vq[D], g_vk[D], g_bcomb[D];
__device__ float g_c0;
__device__ float g_MC[2 * D * D];              // [Mt; Cov] fp32
__device__ float g_qM[NQ];                     // 256 MB
__device__ float g_d[B * S];                   // classifier logits (atomic acc)
__device__ float g_av[2L * B * D];             // audio, video
__device__ float g_y[3L * B * F];              // pre-LN head outputs
__device__ float g_hbias[3 * F];               // packed head biases

__device__ signed char g_q_1[NQ], g_q_0[NQ];
__device__ signed char g_w1_1[(long)S * H * D], g_w1_0[(long)S * H * D];
__device__ signed char g_u_1[2 * D * D], g_u_0[2 * D * D];   // [WkT; out_w]
__device__ signed char g_v_1[2 * D * D], g_v_0[2 * D * D];   // [WqT; WvT]
__device__ signed char g_mc_1[2 * D * D], g_mc_0[2 * D * D]; // [Mt; Cov]
__device__ signed char g_qv_1[2L * B * D], g_qv_0[2L * B * D];
__device__ signed char g_x_1[3L * B * D], g_x_0[3L * B * D]; // fus,aud,vid
__device__ signed char g_hw_1[3L * F * D], g_hw_0[3L * F * D];

// ---------------- PTX helpers (base sm_103-legal) ----------------
__device__ __forceinline__ uint32_t smem_u32(const void* p) {
    uint32_t a;
    asm("{ .reg .u64 t; cvta.to.shared.u64 t, %1; cvt.u32.u64 %0, t; }"
        : "=r"(a) : "l"(p));
    return a;
}
#define CP16(dst, src) \
    asm volatile("cp.async.cg.shared.global [%0], [%1], 16;" :: "r"(dst), "l"(src))
#define CP_COMMIT() asm volatile("cp.async.commit_group;" ::: "memory")

__device__ __forceinline__ void ldsm_x4(uint32_t* r, uint32_t addr) {
    asm volatile("ldmatrix.sync.aligned.m8n8.x4.shared.b16 {%0,%1,%2,%3}, [%4];"
                 : "=r"(r[0]), "=r"(r[1]), "=r"(r[2]), "=r"(r[3]) : "r"(addr));
}
__device__ __forceinline__ void ldsm_x2(uint32_t* r, uint32_t addr) {
    asm volatile("ldmatrix.sync.aligned.m8n8.x2.shared.b16 {%0,%1}, [%2];"
                 : "=r"(r[0]), "=r"(r[1]) : "r"(addr));
}
// int8 MMA: m16n8k32, s32 accumulator. Fragment bytes identical to bf16 k16.
__device__ __forceinline__ void mma_s8(int* c, const uint32_t* a, const uint32_t* b) {
    asm volatile(
        "mma.sync.aligned.m16n8k32.row.col.s32.s8.s8.s32 "
        "{%0,%1,%2,%3}, {%4,%5,%6,%7}, {%8,%9}, {%0,%1,%2,%3};"
        : "+r"(c[0]), "+r"(c[1]), "+r"(c[2]), "+r"(c[3])
        : "r"(a[0]), "r"(a[1]), "r"(a[2]), "r"(a[3]), "r"(b[0]), "r"(b[1]));
}

// Swizzled tile address: rows of 64B, 4 x 16B chunks, XOR (r>>1)&3.
__device__ __forceinline__ uint32_t swz(int r, int c) {
    return (uint32_t)((r * 4 + (c ^ ((r >> 1) & 3))) * 16);
}

// 16-bit fixed-point split helper
__device__ __forceinline__ void qsplit(float x, float sc, signed char& hi, signed char& lo) {
    int a = __float2int_rn(x * sc);
    a = max(-32512, min(32512, a));
    const int h = (a + 128) >> 8;
    hi = (signed char)h;
    lo = (signed char)(a - (h << 8));
}

// =============================================================================
// int8 split GEMM: C[M,N] = A[M,K]*B[N,K]^T * scaleC (+bias[n]), fp32 out.
// K = 1024 (16 chunks of 64 int8). Block 64x64, 8 warps (2m x 4n),
// warp tile 32x16, 4-stage cp.async, 2 blocks/SM.
// CLSD: d = (C*scaleC+bias passed through relu).w2 partial dots, atomicAdd.
// =============================================================================
constexpr int STAGE = 16384;                 // A1 4K | A0 4K | B1 4K | B0 4K
constexpr int NSTG = 4;
constexpr int GEMM_SMEM = NSTG * STAGE;      // 64 KB

template <bool BIAS, bool CLSD>
__global__ void __launch_bounds__(256, 2) isgemm(
    const signed char* __restrict__ A1, const signed char* __restrict__ A0,
    long lda, long aOffZ,
    const signed char* __restrict__ B1, const signed char* __restrict__ B0,
    long bOffZ,
    float* __restrict__ C, int ldc, long cOffZ,
    const float* __restrict__ bias, long biasOffZ,
    const float* __restrict__ w2p, float scaleC)
{
    extern __shared__ char dsm[];
    const uint32_t base = smem_u32(dsm);

    const int tid = threadIdx.x, lane = tid & 31, w = tid >> 5;
    const int wm = w & 1, wn = w >> 1;            // 2 x 4 warp grid
    const int z = blockIdx.z;
    const long m0 = (long)blockIdx.y * 64;
    const long n0 = (long)blockIdx.x * 64;
    A1 += z * aOffZ; A0 += z * aOffZ;
    B1 += z * bOffZ; B0 += z * bOffZ;
    C += z * cOffZ;
    if (BIAS || CLSD) bias += z * biasOffZ;

    int acc1[2][2][4], accm[2][2][4], acc0[2][2][4];
#pragma unroll
    for (int i = 0; i < 2; i++)
#pragma unroll
        for (int j = 0; j < 2; j++)
#pragma unroll
            for (int k = 0; k < 4; k++) {
                acc1[i][j][k] = 0; accm[i][j][k] = 0; acc0[i][j][k] = 0;
            }

    // ---- loader: one K-chunk of 64 int8 into stage s (4 cp16/thread) ----
    auto loadChunk = [&](int s, int kc) {
        const long k0 = (long)kc * 64;
        const uint32_t pa1 = base + s * STAGE;
        const uint32_t pa0 = pa1 + 4096;
        const uint32_t pb1 = pa1 + 8192;
        const uint32_t pb0 = pa1 + 12288;
        const int r = tid >> 2, c = tid & 3;
        const uint32_t dst = swz(r, c);
        const long offA = (m0 + r) * lda + k0 + c * 16;
        CP16(pa1 + dst, A1 + offA);
        CP16(pa0 + dst, A0 + offA);
        const long offB = (n0 + r) * 1024 + k0 + c * 16;
        CP16(pb1 + dst, B1 + offB);
        CP16(pb0 + dst, B0 + offB);
        CP_COMMIT();
    };

    // ---- compute one chunk (K=64): term-major, 48 MMAs/warp ----
    auto computeChunk = [&](int s) {
        const uint32_t pa1 = base + s * STAGE;
        const uint32_t pa0 = pa1 + 4096;
        const uint32_t pb1 = pa1 + 8192;
        const uint32_t pb0 = pa1 + 12288;
#pragma unroll
        for (int ks = 0; ks < 2; ks++) {
            uint32_t af1[2][4], af0[2][4], bf[2][2];
            const int ar = lane & 15;
            const int akc = ks * 2 + (lane >> 4);
#pragma unroll
            for (int i = 0; i < 2; i++) {
                const uint32_t off = swz(wm * 32 + i * 16 + ar, akc);
                ldsm_x4(af1[i], pa1 + off);
                ldsm_x4(af0[i], pa0 + off);
            }
            const int brow = wn * 16 + (lane & 7);
            const int bkc = ks * 2 + ((lane >> 3) & 1);
#pragma unroll
            for (int j = 0; j < 2; j++)
                ldsm_x2(bf[j], pb1 + swz(brow + j * 8, bkc));
#pragma unroll
            for (int i = 0; i < 2; i++)
#pragma unroll
                for (int j = 0; j < 2; j++) mma_s8(acc1[i][j], af1[i], bf[j]);
#pragma unroll
            for (int i = 0; i < 2; i++)
#pragma unroll
                for (int j = 0; j < 2; j++) mma_s8(accm[i][j], af0[i], bf[j]);
#pragma unroll
            for (int j = 0; j < 2; j++)
                ldsm_x2(bf[j], pb0 + swz(brow + j * 8, bkc));
#pragma unroll
            for (int i = 0; i < 2; i++)
#pragma unroll
                for (int j = 0; j < 2; j++) mma_s8(accm[i][j], af1[i], bf[j]);
#pragma unroll
            for (int i = 0; i < 2; i++)
#pragma unroll
                for (int j = 0; j < 2; j++) mma_s8(acc0[i][j], af0[i], bf[j]);
        }
    };

    loadChunk(0, 0);
    loadChunk(1, 1);
    loadChunk(2, 2);

    for (int ch = 0; ch < 16; ch++) {
        asm volatile("cp.async.wait_group 2;" ::: "memory");
        __syncthreads();
        if (ch + 3 < 16) loadChunk((ch + 3) & 3, ch + 3);
        else CP_COMMIT();                       // keep wait_group count valid
        computeChunk(ch & 3);
    }

    const int gr = lane >> 2, qd = lane & 3;
    auto combine = [&](int i, int j, int k) -> float {
        return 65536.f * (float)acc1[i][j][k] + 256.f * (float)accm[i][j][k]
               + (float)acc0[i][j][k];
    };

    if (CLSD) {
        // ---- fused classifier layer 2: partial d += relu(C+b1).w2 ----
        float p[2][2] = {{0.f, 0.f}, {0.f, 0.f}};
        const float* w2 = w2p + (long)z * H;
#pragma unroll
        for (int j = 0; j < 2; j++) {
            const long c = n0 + wn * 16 + j * 8 + qd * 2;
            const float2 w2v = *(const float2*)&w2[c];
            const float2 bv = *(const float2*)&bias[c];
#pragma unroll
            for (int i = 0; i < 2; i++) {
                const float h0 = fmaxf(combine(i, j, 0) * scaleC + bv.x, 0.f);
                const float h1 = fmaxf(combine(i, j, 1) * scaleC + bv.y, 0.f);
                p[i][0] += h0 * w2v.x + h1 * w2v.y;
                const float h2 = fmaxf(combine(i, j, 2) * scaleC + bv.x, 0.f);
                const float h3 = fmaxf(combine(i, j, 3) * scaleC + bv.y, 0.f);
                p[i][1] += h2 * w2v.x + h3 * w2v.y;
            }
        }
#pragma unroll
        for (int i = 0; i < 2; i++) {
            p[i][0] += __shfl_xor_sync(~0u, p[i][0], 1);
            p[i][0] += __shfl_xor_sync(~0u, p[i][0], 2);
            p[i][1] += __shfl_xor_sync(~0u, p[i][1], 1);
            p[i][1] += __shfl_xor_sync(~0u, p[i][1], 2);
            if (qd == 0) {
                const long r = m0 + wm * 32 + i * 16 + gr;
                atomicAdd(&C[r * S + z], p[i][0]);
                atomicAdd(&C[(r + 8) * S + z], p[i][1]);
            }
        }
    } else {
        // ---- standard epilogue ----
#pragma unroll
        for (int j = 0; j < 2; j++) {
            const long c = n0 + wn * 16 + j * 8 + qd * 2;
            float2 bv = make_float2(0.f, 0.f);
            if (BIAS) bv = *(const float2*)&bias[c];
#pragma unroll
            for (int i = 0; i < 2; i++) {
                const long r0 = m0 + wm * 32 + i * 16 + gr;
                float2 v0 = make_float2(combine(i, j, 0) * scaleC + bv.x,
                                        combine(i, j, 1) * scaleC + bv.y);
                float2 v1 = make_float2(combine(i, j, 2) * scaleC + bv.x,
                                        combine(i, j, 3) * scaleC + bv.y);
                *(float2*)&C[r0 * ldc + c] = v0;
                *(float2*)&C[(r0 + 8) * ldc + c] = v1;
            }
        }
    }
}

// =============================================================================
// fp32 -> int8 hi/lo quantization (vectorized by 4)
// =============================================================================
__device__ __forceinline__ void qstore4(float4 v, float sc, signed char* q1,
                                        signed char* q0, long i4) {
    char4 h, l;
    qsplit(v.x, sc, h.x, l.x);
    qsplit(v.y, sc, h.y, l.y);
    qsplit(v.z, sc, h.z, l.z);
    qsplit(v.w, sc, h.w, l.w);
    ((char4*)q1)[i4] = h;
    ((char4*)q0)[i4] = l;
}

__global__ void quant4(const float* __restrict__ src, signed char* __restrict__ q1,
                       signed char* __restrict__ q0, long n4, float sc)
{
    const long i = (long)blockIdx.x * 256 + threadIdx.x;
    if (i >= n4) return;
    qstore4(((const float4*)src)[i], sc, q1, q0, i);
}

// 1024x1024 transpose + quant: dst[c][r] = src[r][c]
__global__ void tquant(const float* __restrict__ src, signed char* __restrict__ q1,
                       signed char* __restrict__ q0)
{
    __shared__ float t[32][33];
    const int bx = blockIdx.x * 32, by = blockIdx.y * 32;
    const int tx = threadIdx.x;
    for (int j = threadIdx.y; j < 32; j += 8)
        t[j][tx] = src[(long)(by + j) * 1024 + bx + tx];
    __syncthreads();
    for (int j = threadIdx.y; j < 32; j += 8) {
        const long o = (long)(bx + j) * 1024 + by + tx;
        signed char h, l;
        qsplit(t[tx][j], SW, h, l);
        q1[o] = h; q0[o] = l;
    }
}

// avquant: fusion = 0.5*(audio+video); quantize fusion, audio, video -> x
__global__ void avquant()
{
    const long i = (long)blockIdx.x * 256 + threadIdx.x;
    const long n4 = (long)B * D / 4;
    float4 a = ((const float4*)g_av)[i];
    float4 v = ((const float4*)g_av)[n4 + i];
    float4 f = make_float4(0.5f * (a.x + v.x), 0.5f * (a.y + v.y),
                           0.5f * (a.z + v.z), 0.5f * (a.w + v.w));
    qstore4(f, SQ, g_x_1, g_x_0, i);
    qstore4(a, SQ, g_x_1, g_x_0, n4 + i);
    qstore4(v, SQ, g_x_1, g_x_0, 2 * n4 + i);
}

__global__ void zero_d()
{
    g_d[blockIdx.x * 256 + threadIdx.x] = 0.f;
}

__global__ void pack_bias(const float* __restrict__ b0, const float* __restrict__ b1,
                          const float* __restrict__ b2)
{
    const int i = blockIdx.x * 256 + threadIdx.x;   // 0..1535
    const int hh = i >> 9, j = i & 511;
    g_hbias[i] = hh == 0 ? b0[j] : (hh == 1 ? b1[j] : b2[j]);
}

// =============================================================================
// bias-derived vectors (fp32, tiny)
// =============================================================================
__global__ void vec_pre(const float* __restrict__ in_proj_w,
                        const float* __restrict__ in_proj_b,
                        const float* __restrict__ out_w,
                        const float* __restrict__ out_b)
{
    const int i = blockIdx.x * 256 + threadIdx.x;
    const float* wq = in_proj_w;
    const float* wk = in_proj_w + (long)D * D;
    const float* bq = in_proj_b;
    const float* bk = in_proj_b + D;
    const float* bv = in_proj_b + 2 * D;
    float vq = 0.f, vk = 0.f, bc = 0.f;
    for (int e = 0; e < D; e++) {
        vq = fmaf(bq[e], wk[(long)e * D + i], vq);
        vk = fmaf(bk[e], wq[(long)e * D + i], vk);
        bc = fmaf(out_w[(long)i * D + e], bv[e], bc);
    }
    g_vq[i] = vq; g_vk[i] = vk; g_bcomb[i] = bc + out_b[i];
    if (i == 0) {
        float c = 0.f;
        for (int e = 0; e < D; e++) c = fmaf(bq[e], bk[e], c);
        g_c0 = c;
    }
}

// =============================================================================
// Per-batch attention (fp32); reads g_d + g_qM, writes qv int8 pairs
// =============================================================================
__global__ void __launch_bounds__(256) attn_kernel(
    const float* __restrict__ q, const float* __restrict__ cls_b2,
    float* __restrict__ out)
{
    const int b = blockIdx.x;
    __shared__ float qs[32][132];
    __shared__ float qms[32][132];
    __shared__ float sc[32][33];
    __shared__ float vks[128];
    __shared__ float dd[32], rk[32], wa[32], wvv[32], da[16], dv[16];

    const int tid = threadIdx.x;
    const int s = tid >> 3;
    const int tb = tid & 7;
    const float* qb = q + (long)b * S * D;
    const float* qmb = g_qM + (long)b * S * D;

    if (tid < 32) dd[tid] = fmaxf(g_d[b * S + tid] + cls_b2[tid], 0.f);

    float racc[4] = {0.f, 0.f, 0.f, 0.f};
    float rkacc = 0.f;

    for (int c = 0; c < D; c += 128) {
#pragma unroll
        for (int i = 0; i < 4; i++) {
            const int f = tid + 256 * i;
            const int r = f >> 5;
            const int c4 = (f & 31) << 2;
            *(float4*)&qs[r][c4] = *(const float4*)&qb[(long)r * D + c + c4];
            *(float4*)&qms[r][c4] = *(const float4*)&qmb[(long)r * D + c + c4];
        }
        if (tid < 32) *(float4*)&vks[tid * 4] = *(const float4*)&g_vk[c + tid * 4];
        __syncthreads();

#pragma unroll 4
        for (int k = 0; k < 128; k++) {
            const float av = qms[s][k];
#pragma unroll
            for (int j = 0; j < 4; j++)
                racc[j] = fmaf(av, qs[tb + 8 * j][k], racc[j]);
        }
        if (tid < 32) {
            float r2 = 0.f;
#pragma unroll 4
            for (int k = 0; k < 128; k++) r2 = fmaf(qs[tid][k], vks[k], r2);
            rkacc += r2;
        }
        __syncthreads();
    }

#pragma unroll
    for (int j = 0; j < 4; j++) sc[s][tb + 8 * j] = racc[j];
    if (tid < 32) rk[tid] = rkacc;
    __syncthreads();

    const int w = tid >> 5, lane = tid & 31;
    const float inv_sqrtD = 0.03125f;
    for (int rr = w * 4; rr < w * 4 + 4; rr++) {
        float v = (sc[rr][lane] + rk[rr] + g_c0) * inv_sqrtD;
        float mx = v;
#pragma unroll
        for (int o = 16; o > 0; o >>= 1) mx = fmaxf(mx, __shfl_xor_sync(~0u, mx, o));
        float e = __expf(v - mx);
        float sum = e;
#pragma unroll
        for (int o = 16; o > 0; o >>= 1) sum += __shfl_xor_sync(~0u, sum, o);
        sc[rr][lane] = e / sum;
    }
    __syncthreads();

    if (tid < 32) {
        const bool isA = tid < 16;
        const int i = tid & 15;
        float v = dd[tid];
        float mx = v;
#pragma unroll
        for (int o = 8; o > 0; o >>= 1) mx = fmaxf(mx, __shfl_xor_sync(~0u, mx, o));
        float e = __expf(v - mx);
        float sum = e;
#pragma unroll
        for (int o = 8; o > 0; o >>= 1) sum += __shfl_xor_sync(~0u, sum, o);
        const float p = e / sum;
        if (isA) da[i] = p; else dv[i] = p;
        const long bse = 3L * B * F;
        if (isA) out[bse + (long)b * P + i] = p;
        else     out[bse + (long)B * P + (long)b * P + i] = p;
    }
    __syncthreads();

    if (tid < 32) {
        float a = 0.f, v2 = 0.f;
#pragma unroll
        for (int ss = 0; ss < 16; ss++) a = fmaf(da[ss], sc[ss][tid], a);
#pragma unroll
        for (int ss = 0; ss < 16; ss++) v2 = fmaf(dv[ss], sc[16 + ss][tid], v2);
        wa[tid] = a;
        wvv[tid] = v2;
    }
    __syncthreads();

#pragma unroll
    for (int i = 0; i < 4; i++) {
        const int col = tid + 256 * i;
        float a = 0.f, v2 = 0.f;
#pragma unroll
        for (int t = 0; t < 32; t++) {
            const float x = qb[(long)t * D + col];
            a = fmaf(wa[t], x, a);
            v2 = fmaf(wvv[t], x, v2);
        }
        const long ia = (long)b * D + col;
        const long iv = (long)B * D + ia;
        signed char h, l;
        qsplit(a, SQ, h, l);
        g_qv_1[ia] = h; g_qv_0[ia] = l;
        qsplit(v2, SQ, h, l);
        g_qv_1[iv] = h; g_qv_0[iv] = l;
    }
}

__global__ void __launch_bounds__(128) ln_relu(
    const float* __restrict__ gm0, const float* __restrict__ be0,
    const float* __restrict__ gm1, const float* __restrict__ be1,
    const float* __restrict__ gm2, const float* __restrict__ be2,
    float* __restrict__ out)
{
    const int head = blockIdx.y, b = blockIdx.x, tid = threadIdx.x;
    const float* gm = head == 0 ? gm0 : (head == 1 ? gm1 : gm2);
    const float* be = head == 0 ? be0 : (head == 1 ? be1 : be2);
    const float* y = g_y + ((long)head * B + b) * F;

    float4 v = *(const float4*)&y[tid * 4];
    float s = v.x + v.y + v.z + v.w;
    float sq = v.x * v.x + v.y * v.y + v.z * v.z + v.w * v.w;
#pragma unroll
    for (int o = 16; o > 0; o >>= 1) {
        s += __shfl_xor_sync(~0u, s, o);
        sq += __shfl_xor_sync(~0u, sq, o);
    }
    __shared__ float ss[4], ssq[4];
    const int w = tid >> 5;
    if ((tid & 31) == 0) { ss[w] = s; ssq[w] = sq; }
    __syncthreads();
    s = ss[0] + ss[1] + ss[2] + ss[3];
    sq = ssq[0] + ssq[1] + ssq[2] + ssq[3];
    const float mean = s * (1.f / F);
    const float var = sq * (1.f / F) - mean * mean;
    const float rstd = rsqrtf(var + 1e-5f);

    float4 g4 = *(const float4*)&gm[tid * 4];
    float4 b4 = *(const float4*)&be[tid * 4];
    float4 o4;
    o4.x = fmaxf((v.x - mean) * rstd * g4.x + b4.x, 0.f);
    o4.y = fmaxf((v.y - mean) * rstd * g4.y + b4.y, 0.f);
    o4.z = fmaxf((v.z - mean) * rstd * g4.z + b4.z, 0.f);
    o4.w = fmaxf((v.w - mean) * rstd * g4.w + b4.w, 0.f);
    *(float4*)&out[((long)head * B + b) * F + tid * 4] = o4;
}

}  // namespace raff

// =============================================================================
// Launch
// =============================================================================
extern "C" void kernel_launch(void* const* d_in, const int* in_sizes, int n_in,
                              void* d_out, int out_size)
{
    using namespace raff;
    (void)in_sizes; (void)n_in; (void)out_size;

    const float* q         = (const float*)d_in[0];
    const float* in_proj_w = (const float*)d_in[1];
    const float* in_proj_b = (const float*)d_in[2];
    const float* out_w     = (const float*)d_in[3];
    const float* out_b     = (const float*)d_in[4];
    const float* cls_w1    = (const float*)d_in[5];
    const float* cls_b1    = (const float*)d_in[6];
    const float* cls_w2    = (const float*)d_in[7];
    const float* cls_b2    = (const float*)d_in[8];
    const float* fus_w     = (const float*)d_in[9];
    const float* fus_b     = (const float*)d_in[10];
    const float* fus_g     = (const float*)d_in[11];
    const float* fus_be    = (const float*)d_in[12];
    const float* pa_w      = (const float*)d_in[13];
    const float* pa_b      = (const float*)d_in[14];
    const float* pa_g      = (const float*)d_in[15];
    const float* pa_be     = (const float*)d_in[16];
    const float* pv_w      = (const float*)d_in[17];
    const float* pv_b      = (const float*)d_in[18];
    const float* pv_g      = (const float*)d_in[19];
    const float* pv_be     = (const float*)d_in[20];
    float* out = (float*)d_out;

    float *pMC, *pqM, *pd, *pav, *py, *pvq, *pbcomb, *phb;
    signed char *q1, *q0, *w11, *w10, *u1, *u0, *v1, *v0,
        *mc1, *mc0, *qv1, *qv0, *x1, *x0, *hw1, *hw0;
    cudaGetSymbolAddress((void**)&pMC, g_MC);
    cudaGetSymbolAddress((void**)&pqM, g_qM);
    cudaGetSymbolAddress((void**)&pd, g_d);
    cudaGetSymbolAddress((void**)&pav, g_av);
    cudaGetSymbolAddress((void**)&py, g_y);
    cudaGetSymbolAddress((void**)&pvq, g_vq);
    cudaGetSymbolAddress((void**)&pbcomb, g_bcomb);
    cudaGetSymbolAddress((void**)&phb, g_hbias);
    cudaGetSymbolAddress((void**)&q1, g_q_1);
    cudaGetSymbolAddress((void**)&q0, g_q_0);
    cudaGetSymbolAddress((void**)&w11, g_w1_1);
    cudaGetSymbolAddress((void**)&w10, g_w1_0);
    cudaGetSymbolAddress((void**)&u1, g_u_1);
    cudaGetSymbolAddress((void**)&u0, g_u_0);
    cudaGetSymbolAddress((void**)&v1, g_v_1);
    cudaGetSymbolAddress((void**)&v0, g_v_0);
    cudaGetSymbolAddress((void**)&mc1, g_mc_1);
    cudaGetSymbolAddress((void**)&mc0, g_mc_0);
    cudaGetSymbolAddress((void**)&qv1, g_qv_1);
    cudaGetSymbolAddress((void**)&qv0, g_qv_0);
    cudaGetSymbolAddress((void**)&x1, g_x_1);
    cudaGetSymbolAddress((void**)&x0, g_x_0);
    cudaGetSymbolAddress((void**)&hw1, g_hw_1);
    cudaGetSymbolAddress((void**)&hw0, g_hw_0);

    cudaFuncSetAttribute((const void*)isgemm<false, false>,
                         cudaFuncAttributeMaxDynamicSharedMemorySize, GEMM_SMEM);
    cudaFuncSetAttribute((const void*)isgemm<true, false>,
                         cudaFuncAttributeMaxDynamicSharedMemorySize, GEMM_SMEM);
    cudaFuncSetAttribute((const void*)isgemm<false, true>,
                         cudaFuncAttributeMaxDynamicSharedMemorySize, GEMM_SMEM);

    // 1) tiny precomputations
    vec_pre<<<D / 256, 256>>>(in_proj_w, in_proj_b, out_w, out_b);
    pack_bias<<<6, 256>>>(fus_b, pa_b, pv_b);
    zero_d<<<B * S / 256, 256>>>();

    // 2) quantize inputs
    quant4<<<(int)(NQ / 4 / 256), 256>>>(q, q1, q0, NQ / 4, SQ);
    quant4<<<(int)((long)S * H * D / 4 / 256), 256>>>(cls_w1, w11, w10,
                                                      (long)S * H * D / 4, SW);
    quant4<<<D * D / 4 / 256, 256>>>(out_w, u1 + (long)D * D, u0 + (long)D * D,
                                     D * D / 4, SW);
    quant4<<<F * D / 4 / 256, 256>>>(fus_w, hw1, hw0, (long)F * D / 4, SW);
    quant4<<<F * D / 4 / 256, 256>>>(pa_w, hw1 + (long)F * D, hw0 + (long)F * D,
                                     (long)F * D / 4, SW);
    quant4<<<F * D / 4 / 256, 256>>>(pv_w, hw1 + 2L * F * D, hw0 + 2L * F * D,
                                     (long)F * D / 4, SW);
    tquant<<<dim3(32, 32), dim3(32, 8)>>>(in_proj_w + (long)D * D, u1, u0);   // WkT
    tquant<<<dim3(32, 32), dim3(32, 8)>>>(in_proj_w, v1, v0);                 // WqT
    tquant<<<dim3(32, 32), dim3(32, 8)>>>(in_proj_w + 2L * D * D,
                                          v1 + (long)D * D, v0 + (long)D * D); // WvT

    // 3) [Mt; Cov] one z=2 launch, then quantize
    isgemm<false, false><<<dim3(16, 16, 2), 256, GEMM_SMEM>>>(
        u1, u0, D, (long)D * D, v1, v0, (long)D * D,
        pMC, D, (long)D * D, nullptr, 0L, nullptr, SC_WW);
    quant4<<<2 * D * D / 4 / 256, 256>>>(pMC, mc1, mc0, 2 * D * D / 4, SW);

    // 4) qM = q * Mt^T + vq   [65536 x 1024 x 1024]
    isgemm<true, false><<<dim3(16, 1024), 256, GEMM_SMEM>>>(
        q1, q0, (long)D, 0L, mc1, mc0, 0L, pqM, D, 0L, pvq, 0L, nullptr, SC_QW);

    // 5) classifier: fused h = relu(q w1^T + b1), d += h.w2 (atomic)
    isgemm<false, true><<<dim3(8, 32, 32), 256, GEMM_SMEM>>>(
        q1, q0, (long)S * D, (long)D, w11, w10, (long)H * D,
        pd, S, 0L, cls_b1, (long)H, cls_w2, SC_QW);

    // 6) attention + softmaxes + weighted q sums -> qv int8
    attn_kernel<<<B, 256>>>(q, cls_b2, out);

    // 7) [audio; video] = qv * Cov^T + bcomb
    isgemm<true, false><<<dim3(16, 64), 256, GEMM_SMEM>>>(
        qv1, qv0, (long)D, 0L, mc1 + (long)D * D, mc0 + (long)D * D, 0L,
        pav, D, 0L, pbcomb, 0L, nullptr, SC_QW);

    // 8) fusion + quantize head inputs
    avquant<<<(int)((long)B * D / 4 / 256), 256>>>();

    // 9) heads: one z=3 launch  y = x * W^T + b  [2048 x 512 x 1024]
    isgemm<true, false><<<dim3(8, 32, 3), 256, GEMM_SMEM>>>(
        x1, x0, (long)D, (long)B * D, hw1, hw0, (long)F * D,
        py, F, (long)B * F, phb, (long)F, nullptr, SC_QW);

    // 10) LayerNorm + ReLU -> final outputs
    ln_relu<<<dim3(B, 3), 128>>>(fus_g, fus_be, pa_g, pa_be, pv_g, pv_be, out);
}

// round 9
// speedup vs baseline: 2.7156x; 2.7156x over previous
#include <cuda_runtime.h>
#include <cuda_bf16.h>
#include <cstdint>

// =============================================================================
// RAFF_8555574853896 — round 9: bf16 split HMMA GEMMs with 64x64 warp tiles
// (block 128x256) to cut shared-crossbar bytes per MAC by 1.5x; 3-stage
// cp.async pipeline; fused classifier epilogue; fused conversions.
//
// Algebra (validated):
//   scores = q Mt^T q^T / sqrt(D) + rank-1 bias,  Mt = (Wq^T Wk)^T
//   audio  = (w_a^T q) Cov^T + bcomb,             Cov = out_w Wv
// Split: x = hi + lo (bf16); A*B ~= Ahi*Bhi + Ahi*Blo + Alo*Bhi  (~1e-5)
// =============================================================================

namespace raff {

constexpr int B = 2048, S = 32, P = 16, D = 1024, H = 512, F = 512;
constexpr long NQ = (long)B * S * D;

// ---------------- static device scratch ----------------
__device__ float g_vq[D], g_vk[D], g_bcomb[D];
__device__ float g_c0;
__device__ float g_MC[2 * D * D];              // [Mt; Cov]
__device__ float g_qM[NQ];                     // 256 MB
__device__ float g_d[B * S];                   // classifier logits (atomic acc)
__device__ float g_av[2L * B * D];             // audio, video
__device__ float g_y[3L * B * F];              // pre-LN head outputs
__device__ float g_hbias[3 * F];               // packed head biases

__device__ __nv_bfloat16 g_q_hi[NQ], g_q_lo[NQ];
__device__ __nv_bfloat16 g_w1_hi[(long)S * H * D], g_w1_lo[(long)S * H * D];
__device__ __nv_bfloat16 g_u_hi[2 * D * D], g_u_lo[2 * D * D];   // [WkT; out_w]
__device__ __nv_bfloat16 g_v_hi[2 * D * D], g_v_lo[2 * D * D];   // [WqT; WvT]
__device__ __nv_bfloat16 g_mc_hi[2 * D * D], g_mc_lo[2 * D * D]; // [Mt; Cov]
__device__ __nv_bfloat16 g_qv_hi[2L * B * D], g_qv_lo[2L * B * D];
__device__ __nv_bfloat16 g_x_hi[3L * B * D], g_x_lo[3L * B * D]; // fus,aud,vid
__device__ __nv_bfloat16 g_hw_hi[3L * F * D], g_hw_lo[3L * F * D];

// ---------------- PTX helpers (base sm_103-legal) ----------------
__device__ __forceinline__ uint32_t smem_u32(const void* p) {
    uint32_t a;
    asm("{ .reg .u64 t; cvta.to.shared.u64 t, %1; cvt.u32.u64 %0, t; }"
        : "=r"(a) : "l"(p));
    return a;
}
#define CP16(dst, src) \
    asm volatile("cp.async.cg.shared.global [%0], [%1], 16;" :: "r"(dst), "l"(src))
#define CP_COMMIT() asm volatile("cp.async.commit_group;" ::: "memory")

__device__ __forceinline__ void ldsm_x4(uint32_t* r, uint32_t addr) {
    asm volatile("ldmatrix.sync.aligned.m8n8.x4.shared.b16 {%0,%1,%2,%3}, [%4];"
                 : "=r"(r[0]), "=r"(r[1]), "=r"(r[2]), "=r"(r[3]) : "r"(addr));
}
__device__ __forceinline__ void mma_bf16(float* c, const uint32_t* a, const uint32_t* b) {
    asm volatile(
        "mma.sync.aligned.m16n8k16.row.col.f32.bf16.bf16.f32 "
        "{%0,%1,%2,%3}, {%4,%5,%6,%7}, {%8,%9}, {%0,%1,%2,%3};"
        : "+f"(c[0]), "+f"(c[1]), "+f"(c[2]), "+f"(c[3])
        : "r"(a[0]), "r"(a[1]), "r"(a[2]), "r"(a[3]), "r"(b[0]), "r"(b[1]));
}

// Swizzled tile address: rows of 64B (32 bf16), 4 x 16B chunks, XOR (r>>1)&3.
__device__ __forceinline__ uint32_t swz(int r, int c) {
    return (uint32_t)((r * 4 + (c ^ ((r >> 1) & 3))) * 16);
}

// =============================================================================
// HMMA split-bf16 GEMM: C[M,N] = A[M,K]*B[N,K]^T (+bias[n]), fp32 out.
// K = 1024 (32 chunks of 32). Block tile 128x256, 8 warps (2m x 4n),
// warp tile 64x64, 3-stage cp.async pipeline (144 KB smem, 1 block/SM).
// CLSD: d = relu(C+bias).w2 partial dots, atomicAdd into C (g_d), col z.
// =============================================================================
constexpr int STAGE = 49152;   // Ahi 8K | Alo 8K | Bhi 16K | Blo 16K
constexpr int NSTG = 3;
constexpr int GEMM_SMEM = NSTG * STAGE;      // 144 KB

template <bool BIAS, bool CLSD>
__global__ void __launch_bounds__(256) bsgemm(
    const __nv_bfloat16* __restrict__ Ahi, const __nv_bfloat16* __restrict__ Alo,
    long lda, long aOffZ,
    const __nv_bfloat16* __restrict__ Bhi, const __nv_bfloat16* __restrict__ Blo,
    long bOffZ,
    float* __restrict__ C, int ldc, long cOffZ,
    const float* __restrict__ bias, long biasOffZ,
    const float* __restrict__ w2p)
{
    extern __shared__ char dsm[];
    const uint32_t base = smem_u32(dsm);

    const int tid = threadIdx.x, lane = tid & 31, w = tid >> 5;
    const int wm = w & 1, wn = w >> 1;            // 2 x 4 warp grid
    const int z = blockIdx.z;
    const long m0 = (long)blockIdx.y * 128;
    const long n0 = (long)blockIdx.x * 256;
    Ahi += z * aOffZ; Alo += z * aOffZ;
    Bhi += z * bOffZ; Blo += z * bOffZ;
    C += z * cOffZ;
    if (BIAS || CLSD) bias += z * biasOffZ;

    float acc[4][8][4];
#pragma unroll
    for (int i = 0; i < 4; i++)
#pragma unroll
        for (int j = 0; j < 8; j++)
#pragma unroll
            for (int k = 0; k < 4; k++) acc[i][j][k] = 0.f;

    // ---- loader: one K-chunk of 32 into stage s (12 cp16/thread) ----
    auto loadChunk = [&](int s, int kc) {
        const long k0 = (long)kc * 32;
        const uint32_t ah = base + s * STAGE;
        const uint32_t al = ah + 8192;
        const uint32_t bh = ah + 16384;
        const uint32_t bl = ah + 32768;
#pragma unroll
        for (int i = 0; i < 2; i++) {               // A: 128 rows x 4 chunks
            const int idx = tid + 256 * i;
            const int r = idx >> 2, c = idx & 3;
            const uint32_t dst = swz(r, c);
            const long offA = (m0 + r) * lda + k0 + c * 8;
            CP16(ah + dst, Ahi + offA);
            CP16(al + dst, Alo + offA);
        }
#pragma unroll
        for (int i = 0; i < 4; i++) {               // B: 256 rows x 4 chunks
            const int idx = tid + 256 * i;
            const int r = idx >> 2, c = idx & 3;
            const uint32_t dst = swz(r, c);
            const long offB = (n0 + r) * 1024 + k0 + c * 8;
            CP16(bh + dst, Bhi + offB);
            CP16(bl + dst, Blo + offB);
        }
        CP_COMMIT();
    };

    // ---- compute one chunk (K=32), term-major, 96 MMAs/warp ----
    auto computeChunk = [&](int s) {
        const uint32_t ah = base + s * STAGE;
        const uint32_t al = ah + 8192;
        const uint32_t bh = ah + 16384;
        const uint32_t bl = ah + 32768;
#pragma unroll
        for (int ks = 0; ks < 2; ks++) {
            uint32_t afh[4][4], afl[4][4], bq[4][4];
            const int ar = lane & 15;
            const int akc = ks * 2 + (lane >> 4);
#pragma unroll
            for (int i = 0; i < 4; i++) {
                const uint32_t off = swz(wm * 64 + i * 16 + ar, akc);
                ldsm_x4(afh[i], ah + off);
                ldsm_x4(afl[i], al + off);
            }
            // B-hi: x4 loads 2 n-frags per instruction
            const int bnr = wn * 64 + ((lane >> 4) & 1) * 8 + (lane & 7);
            const int bkc = ks * 2 + ((lane >> 3) & 1);
#pragma unroll
            for (int jj = 0; jj < 4; jj++)
                ldsm_x4(bq[jj], bh + swz(bnr + jj * 16, bkc));
            // hh then lh (share B-hi frags)
#pragma unroll
            for (int i = 0; i < 4; i++)
#pragma unroll
                for (int j = 0; j < 8; j++)
                    mma_bf16(acc[i][j], afh[i], &bq[j >> 1][(j & 1) * 2]);
#pragma unroll
            for (int i = 0; i < 4; i++)
#pragma unroll
                for (int j = 0; j < 8; j++)
                    mma_bf16(acc[i][j], afl[i], &bq[j >> 1][(j & 1) * 2]);
            // overwrite with B-lo frags, hl
#pragma unroll
            for (int jj = 0; jj < 4; jj++)
                ldsm_x4(bq[jj], bl + swz(bnr + jj * 16, bkc));
#pragma unroll
            for (int i = 0; i < 4; i++)
#pragma unroll
                for (int j = 0; j < 8; j++)
                    mma_bf16(acc[i][j], afh[i], &bq[j >> 1][(j & 1) * 2]);
        }
    };

    loadChunk(0, 0);
    loadChunk(1, 1);

    for (int ch = 0; ch < 32; ch++) {
        asm volatile("cp.async.wait_group 1;" ::: "memory");
        __syncthreads();
        if (ch + 2 < 32) loadChunk((ch + 2) % 3, ch + 2);
        else CP_COMMIT();                       // keep wait_group count valid
        computeChunk(ch % 3);
    }

    const int gr = lane >> 2, qd = lane & 3;

    if (CLSD) {
        // ---- fused classifier layer 2: partial d += relu(acc+b1).w2 ----
        float p[4][2];
#pragma unroll
        for (int i = 0; i < 4; i++) { p[i][0] = 0.f; p[i][1] = 0.f; }
        const float* w2 = w2p + (long)z * H;
#pragma unroll
        for (int j = 0; j < 8; j++) {
            const long c = n0 + wn * 64 + j * 8 + qd * 2;
            const float2 w2v = *(const float2*)&w2[c];
            const float2 bv = *(const float2*)&bias[c];
#pragma unroll
            for (int i = 0; i < 4; i++) {
                const float h0 = fmaxf(acc[i][j][0] + bv.x, 0.f);
                const float h1 = fmaxf(acc[i][j][1] + bv.y, 0.f);
                p[i][0] += h0 * w2v.x + h1 * w2v.y;
                const float h2 = fmaxf(acc[i][j][2] + bv.x, 0.f);
                const float h3 = fmaxf(acc[i][j][3] + bv.y, 0.f);
                p[i][1] += h2 * w2v.x + h3 * w2v.y;
            }
        }
#pragma unroll
        for (int i = 0; i < 4; i++) {
            p[i][0] += __shfl_xor_sync(~0u, p[i][0], 1);
            p[i][0] += __shfl_xor_sync(~0u, p[i][0], 2);
            p[i][1] += __shfl_xor_sync(~0u, p[i][1], 1);
            p[i][1] += __shfl_xor_sync(~0u, p[i][1], 2);
            if (qd == 0) {
                const long r = m0 + wm * 64 + i * 16 + gr;
                atomicAdd(&C[r * S + z], p[i][0]);
                atomicAdd(&C[(r + 8) * S + z], p[i][1]);
            }
        }
    } else {
        // ---- standard epilogue ----
#pragma unroll
        for (int j = 0; j < 8; j++) {
            const long c = n0 + wn * 64 + j * 8 + qd * 2;
            float2 bv = make_float2(0.f, 0.f);
            if (BIAS) bv = *(const float2*)&bias[c];
#pragma unroll
            for (int i = 0; i < 4; i++) {
                const long r0 = m0 + wm * 64 + i * 16 + gr;
                float2 v0 = make_float2(acc[i][j][0] + bv.x, acc[i][j][1] + bv.y);
                float2 v1 = make_float2(acc[i][j][2] + bv.x, acc[i][j][3] + bv.y);
                *(float2*)&C[r0 * ldc + c] = v0;
                *(float2*)&C[(r0 + 8) * ldc + c] = v1;
            }
        }
    }
}

// =============================================================================
// fp32 -> bf16 hi/lo split (vectorized by 4)
// =============================================================================
__device__ __forceinline__ void store_split4(float4 v, __nv_bfloat16* hi,
                                             __nv_bfloat16* lo, long i4) {
    __nv_bfloat16 h0 = __float2bfloat16(v.x), h1 = __float2bfloat16(v.y);
    __nv_bfloat16 h2 = __float2bfloat16(v.z), h3 = __float2bfloat16(v.w);
    __nv_bfloat162 a, b;
    a.x = h0; a.y = h1; b.x = h2; b.y = h3;
    ((__nv_bfloat162*)hi)[2 * i4] = a; ((__nv_bfloat162*)hi)[2 * i4 + 1] = b;
    a.x = __float2bfloat16(v.x - __bfloat162float(h0));
    a.y = __float2bfloat16(v.y - __bfloat162float(h1));
    b.x = __float2bfloat16(v.z - __bfloat162float(h2));
    b.y = __float2bfloat16(v.w - __bfloat162float(h3));
    ((__nv_bfloat162*)lo)[2 * i4] = a; ((__nv_bfloat162*)lo)[2 * i4 + 1] = b;
}

__global__ void split4(const float* __restrict__ src, __nv_bfloat16* __restrict__ hi,
                       __nv_bfloat16* __restrict__ lo, long n4)
{
    const long i = (long)blockIdx.x * 256 + threadIdx.x;
    if (i >= n4) return;
    store_split4(((const float4*)src)[i], hi, lo, i);
}

// 1024x1024 transpose + split: dst[c][r] = src[r][c]
__global__ void tsplit(const float* __restrict__ src, __nv_bfloat16* __restrict__ hi,
                       __nv_bfloat16* __restrict__ lo)
{
    __shared__ float t[32][33];
    const int bx = blockIdx.x * 32, by = blockIdx.y * 32;
    const int tx = threadIdx.x;
    for (int j = threadIdx.y; j < 32; j += 8)
        t[j][tx] = src[(long)(by + j) * 1024 + bx + tx];
    __syncthreads();
    for (int j = threadIdx.y; j < 32; j += 8) {
        const float v = t[tx][j];
        const long o = (long)(bx + j) * 1024 + by + tx;
        __nv_bfloat16 h = __float2bfloat16(v);
        hi[o] = h;
        lo[o] = __float2bfloat16(v - __bfloat162float(h));
    }
}

// avsplit: fusion = 0.5*(audio+video); split fusion, audio, video -> x hi/lo
__global__ void avsplit()
{
    const long i = (long)blockIdx.x * 256 + threadIdx.x;
    const long n4 = (long)B * D / 4;
    float4 a = ((const float4*)g_av)[i];
    float4 v = ((const float4*)g_av)[n4 + i];
    float4 f = make_float4(0.5f * (a.x + v.x), 0.5f * (a.y + v.y),
                           0.5f * (a.z + v.z), 0.5f * (a.w + v.w));
    store_split4(f, g_x_hi, g_x_lo, i);
    store_split4(a, g_x_hi, g_x_lo, n4 + i);
    store_split4(v, g_x_hi, g_x_lo, 2 * n4 + i);
}

__global__ void zero_d()
{
    g_d[blockIdx.x * 256 + threadIdx.x] = 0.f;
}

__global__ void pack_bias(const float* __restrict__ b0, const float* __restrict__ b1,
                          const float* __restrict__ b2)
{
    const int i = blockIdx.x * 256 + threadIdx.x;   // 0..1535
    const int hh = i >> 9, j = i & 511;
    g_hbias[i] = hh == 0 ? b0[j] : (hh == 1 ? b1[j] : b2[j]);
}

// =============================================================================
// bias-derived vectors (fp32, tiny)
// =============================================================================
__global__ void vec_pre(const float* __restrict__ in_proj_w,
                        const float* __restrict__ in_proj_b,
                        const float* __restrict__ out_w,
                        const float* __restrict__ out_b)
{
    const int i = blockIdx.x * 256 + threadIdx.x;
    const float* wq = in_proj_w;
    const float* wk = in_proj_w + (long)D * D;
    const float* bq = in_proj_b;
    const float* bk = in_proj_b + D;
    const float* bv = in_proj_b + 2 * D;
    float vq = 0.f, vk = 0.f, bc = 0.f;
    for (int e = 0; e < D; e++) {
        vq = fmaf(bq[e], wk[(long)e * D + i], vq);
        vk = fmaf(bk[e], wq[(long)e * D + i], vk);
        bc = fmaf(out_w[(long)i * D + e], bv[e], bc);
    }
    g_vq[i] = vq; g_vk[i] = vk; g_bcomb[i] = bc + out_b[i];
    if (i == 0) {
        float c = 0.f;
        for (int e = 0; e < D; e++) c = fmaf(bq[e], bk[e], c);
        g_c0 = c;
    }
}

// =============================================================================
// Per-batch attention (fp32); reads g_d (pre-bias logits), writes qv hi/lo
// =============================================================================
__global__ void __launch_bounds__(256) attn_kernel(
    const float* __restrict__ q, const float* __restrict__ cls_b2,
    float* __restrict__ out)
{
    const int b = blockIdx.x;
    __shared__ float qs[32][132];
    __shared__ float qms[32][132];
    __shared__ float sc[32][33];
    __shared__ float vks[128];
    __shared__ float dd[32], rk[32], wa[32], wvv[32], da[16], dv[16];

    const int tid = threadIdx.x;
    const int s = tid >> 3;
    const int tb = tid & 7;
    const float* qb = q + (long)b * S * D;
    const float* qmb = g_qM + (long)b * S * D;

    if (tid < 32) dd[tid] = fmaxf(g_d[b * S + tid] + cls_b2[tid], 0.f);

    float racc[4] = {0.f, 0.f, 0.f, 0.f};
    float rkacc = 0.f;

    for (int c = 0; c < D; c += 128) {
#pragma unroll
        for (int i = 0; i < 4; i++) {
            const int f = tid + 256 * i;
            const int r = f >> 5;
            const int c4 = (f & 31) << 2;
            *(float4*)&qs[r][c4] = *(const float4*)&qb[(long)r * D + c + c4];
            *(float4*)&qms[r][c4] = *(const float4*)&qmb[(long)r * D + c + c4];
        }
        if (tid < 32) *(float4*)&vks[tid * 4] = *(const float4*)&g_vk[c + tid * 4];
        __syncthreads();

#pragma unroll 4
        for (int k = 0; k < 128; k++) {
            const float av = qms[s][k];
#pragma unroll
            for (int j = 0; j < 4; j++)
                racc[j] = fmaf(av, qs[tb + 8 * j][k], racc[j]);
        }
        if (tid < 32) {
            float r2 = 0.f;
#pragma unroll 4
            for (int k = 0; k < 128; k++) r2 = fmaf(qs[tid][k], vks[k], r2);
            rkacc += r2;
        }
        __syncthreads();
    }

#pragma unroll
    for (int j = 0; j < 4; j++) sc[s][tb + 8 * j] = racc[j];
    if (tid < 32) rk[tid] = rkacc;
    __syncthreads();

    const int w = tid >> 5, lane = tid & 31;
    const float inv_sqrtD = 0.03125f;
    for (int rr = w * 4; rr < w * 4 + 4; rr++) {
        float v = (sc[rr][lane] + rk[rr] + g_c0) * inv_sqrtD;
        float mx = v;
#pragma unroll
        for (int o = 16; o > 0; o >>= 1) mx = fmaxf(mx, __shfl_xor_sync(~0u, mx, o));
        float e = __expf(v - mx);
        float sum = e;
#pragma unroll
        for (int o = 16; o > 0; o >>= 1) sum += __shfl_xor_sync(~0u, sum, o);
        sc[rr][lane] = e / sum;
    }
    __syncthreads();

    if (tid < 32) {
        const bool isA = tid < 16;
        const int i = tid & 15;
        float v = dd[tid];
        float mx = v;
#pragma unroll
        for (int o = 8; o > 0; o >>= 1) mx = fmaxf(mx, __shfl_xor_sync(~0u, mx, o));
        float e = __expf(v - mx);
        float sum = e;
#pragma unroll
        for (int o = 8; o > 0; o >>= 1) sum += __shfl_xor_sync(~0u, sum, o);
        const float p = e / sum;
        if (isA) da[i] = p; else dv[i] = p;
        const long bse = 3L * B * F;
        if (isA) out[bse + (long)b * P + i] = p;
        else     out[bse + (long)B * P + (long)b * P + i] = p;
    }
    __syncthreads();

    if (tid < 32) {
        float a = 0.f, v2 = 0.f;
#pragma unroll
        for (int ss = 0; ss < 16; ss++) a = fmaf(da[ss], sc[ss][tid], a);
#pragma unroll
        for (int ss = 0; ss < 16; ss++) v2 = fmaf(dv[ss], sc[16 + ss][tid], v2);
        wa[tid] = a;
        wvv[tid] = v2;
    }
    __syncthreads();

#pragma unroll
    for (int i = 0; i < 4; i++) {
        const int col = tid + 256 * i;
        float a = 0.f, v2 = 0.f;
#pragma unroll
        for (int t = 0; t < 32; t++) {
            const float x = qb[(long)t * D + col];
            a = fmaf(wa[t], x, a);
            v2 = fmaf(wvv[t], x, v2);
        }
        const long ia = (long)b * D + col;
        const long iv = (long)B * D + ia;
        __nv_bfloat16 h = __float2bfloat16(a);
        g_qv_hi[ia] = h;
        g_qv_lo[ia] = __float2bfloat16(a - __bfloat162float(h));
        h = __float2bfloat16(v2);
        g_qv_hi[iv] = h;
        g_qv_lo[iv] = __float2bfloat16(v2 - __bfloat162float(h));
    }
}

__global__ void __launch_bounds__(128) ln_relu(
    const float* __restrict__ gm0, const float* __restrict__ be0,
    const float* __restrict__ gm1, const float* __restrict__ be1,
    const float* __restrict__ gm2, const float* __restrict__ be2,
    float* __restrict__ out)
{
    const int head = blockIdx.y, b = blockIdx.x, tid = threadIdx.x;
    const float* gm = head == 0 ? gm0 : (head == 1 ? gm1 : gm2);
    const float* be = head == 0 ? be0 : (head == 1 ? be1 : be2);
    const float* y = g_y + ((long)head * B + b) * F;

    float4 v = *(const float4*)&y[tid * 4];
    float s = v.x + v.y + v.z + v.w;
    float sq = v.x * v.x + v.y * v.y + v.z * v.z + v.w * v.w;
#pragma unroll
    for (int o = 16; o > 0; o >>= 1) {
        s += __shfl_xor_sync(~0u, s, o);
        sq += __shfl_xor_sync(~0u, sq, o);
    }
    __shared__ float ss[4], ssq[4];
    const int w = tid >> 5;
    if ((tid & 31) == 0) { ss[w] = s; ssq[w] = sq; }
    __syncthreads();
    s = ss[0] + ss[1] + ss[2] + ss[3];
    sq = ssq[0] + ssq[1] + ssq[2] + ssq[3];
    const float mean = s * (1.f / F);
    const float var = sq * (1.f / F) - mean * mean;
    const float rstd = rsqrtf(var + 1e-5f);

    float4 g4 = *(const float4*)&gm[tid * 4];
    float4 b4 = *(const float4*)&be[tid * 4];
    float4 o4;
    o4.x = fmaxf((v.x - mean) * rstd * g4.x + b4.x, 0.f);
    o4.y = fmaxf((v.y - mean) * rstd * g4.y + b4.y, 0.f);
    o4.z = fmaxf((v.z - mean) * rstd * g4.z + b4.z, 0.f);
    o4.w = fmaxf((v.w - mean) * rstd * g4.w + b4.w, 0.f);
    *(float4*)&out[((long)head * B + b) * F + tid * 4] = o4;
}

}  // namespace raff

// =============================================================================
// Launch
// =============================================================================
extern "C" void kernel_launch(void* const* d_in, const int* in_sizes, int n_in,
                              void* d_out, int out_size)
{
    using namespace raff;
    (void)in_sizes; (void)n_in; (void)out_size;

    const float* q         = (const float*)d_in[0];
    const float* in_proj_w = (const float*)d_in[1];
    const float* in_proj_b = (const float*)d_in[2];
    const float* out_w     = (const float*)d_in[3];
    const float* out_b     = (const float*)d_in[4];
    const float* cls_w1    = (const float*)d_in[5];
    const float* cls_b1    = (const float*)d_in[6];
    const float* cls_w2    = (const float*)d_in[7];
    const float* cls_b2    = (const float*)d_in[8];
    const float* fus_w     = (const float*)d_in[9];
    const float* fus_b     = (const float*)d_in[10];
    const float* fus_g     = (const float*)d_in[11];
    const float* fus_be    = (const float*)d_in[12];
    const float* pa_w      = (const float*)d_in[13];
    const float* pa_b      = (const float*)d_in[14];
    const float* pa_g      = (const float*)d_in[15];
    const float* pa_be     = (const float*)d_in[16];
    const float* pv_w      = (const float*)d_in[17];
    const float* pv_b      = (const float*)d_in[18];
    const float* pv_g      = (const float*)d_in[19];
    const float* pv_be     = (const float*)d_in[20];
    float* out = (float*)d_out;

    float *pMC, *pqM, *pd, *pav, *py, *pvq, *pbcomb, *phb;
    __nv_bfloat16 *qhi, *qlo, *w1hi, *w1lo, *uhi, *ulo, *vhi, *vlo,
        *mchi, *mclo, *qvhi, *qvlo, *xhi, *xlo, *hwhi, *hwlo;
    cudaGetSymbolAddress((void**)&pMC, g_MC);
    cudaGetSymbolAddress((void**)&pqM, g_qM);
    cudaGetSymbolAddress((void**)&pd, g_d);
    cudaGetSymbolAddress((void**)&pav, g_av);
    cudaGetSymbolAddress((void**)&py, g_y);
    cudaGetSymbolAddress((void**)&pvq, g_vq);
    cudaGetSymbolAddress((void**)&pbcomb, g_bcomb);
    cudaGetSymbolAddress((void**)&phb, g_hbias);
    cudaGetSymbolAddress((void**)&qhi, g_q_hi);
    cudaGetSymbolAddress((void**)&qlo, g_q_lo);
    cudaGetSymbolAddress((void**)&w1hi, g_w1_hi);
    cudaGetSymbolAddress((void**)&w1lo, g_w1_lo);
    cudaGetSymbolAddress((void**)&uhi, g_u_hi);
    cudaGetSymbolAddress((void**)&ulo, g_u_lo);
    cudaGetSymbolAddress((void**)&vhi, g_v_hi);
    cudaGetSymbolAddress((void**)&vlo, g_v_lo);
    cudaGetSymbolAddress((void**)&mchi, g_mc_hi);
    cudaGetSymbolAddress((void**)&mclo, g_mc_lo);
    cudaGetSymbolAddress((void**)&qvhi, g_qv_hi);
    cudaGetSymbolAddress((void**)&qvlo, g_qv_lo);
    cudaGetSymbolAddress((void**)&xhi, g_x_hi);
    cudaGetSymbolAddress((void**)&xlo, g_x_lo);
    cudaGetSymbolAddress((void**)&hwhi, g_hw_hi);
    cudaGetSymbolAddress((void**)&hwlo, g_hw_lo);

    cudaFuncSetAttribute((const void*)bsgemm<false, false>,
                         cudaFuncAttributeMaxDynamicSharedMemorySize, GEMM_SMEM);
    cudaFuncSetAttribute((const void*)bsgemm<true, false>,
                         cudaFuncAttributeMaxDynamicSharedMemorySize, GEMM_SMEM);
    cudaFuncSetAttribute((const void*)bsgemm<false, true>,
                         cudaFuncAttributeMaxDynamicSharedMemorySize, GEMM_SMEM);

    // 1) tiny precomputations
    vec_pre<<<D / 256, 256>>>(in_proj_w, in_proj_b, out_w, out_b);
    pack_bias<<<6, 256>>>(fus_b, pa_b, pv_b);
    zero_d<<<B * S / 256, 256>>>();

    // 2) conversions of inputs
    split4<<<(int)(NQ / 4 / 256), 256>>>(q, qhi, qlo, NQ / 4);
    split4<<<(int)((long)S * H * D / 4 / 256), 256>>>(cls_w1, w1hi, w1lo,
                                                      (long)S * H * D / 4);
    split4<<<D * D / 4 / 256, 256>>>(out_w, uhi + (long)D * D, ulo + (long)D * D,
                                     D * D / 4);
    split4<<<F * D / 4 / 256, 256>>>(fus_w, hwhi, hwlo, (long)F * D / 4);
    split4<<<F * D / 4 / 256, 256>>>(pa_w, hwhi + (long)F * D, hwlo + (long)F * D,
                                     (long)F * D / 4);
    split4<<<F * D / 4 / 256, 256>>>(pv_w, hwhi + 2L * F * D, hwlo + 2L * F * D,
                                     (long)F * D / 4);
    tsplit<<<dim3(32, 32), dim3(32, 8)>>>(in_proj_w + (long)D * D, uhi, ulo);    // WkT
    tsplit<<<dim3(32, 32), dim3(32, 8)>>>(in_proj_w, vhi, vlo);                  // WqT
    tsplit<<<dim3(32, 32), dim3(32, 8)>>>(in_proj_w + 2L * D * D,
                                          vhi + (long)D * D, vlo + (long)D * D); // WvT

    // 3) [Mt; Cov] in one z=2 launch: z0 = WkT*WqT^T, z1 = out_w*WvT^T
    bsgemm<false, false><<<dim3(4, 8, 2), 256, GEMM_SMEM>>>(
        uhi, ulo, D, (long)D * D, vhi, vlo, (long)D * D,
        pMC, D, (long)D * D, nullptr, 0L, nullptr);
    split4<<<2 * D * D / 4 / 256, 256>>>(pMC, mchi, mclo, 2 * D * D / 4);

    // 4) qM = q * Mt^T + vq   [65536 x 1024 x 1024]
    bsgemm<true, false><<<dim3(4, 512), 256, GEMM_SMEM>>>(
        qhi, qlo, (long)D, 0L, mchi, mclo, 0L, pqM, D, 0L, pvq, 0L, nullptr);

    // 5) classifier: fused h = relu(q w1^T + b1), d += h.w2 (atomic)
    bsgemm<false, true><<<dim3(2, 16, 32), 256, GEMM_SMEM>>>(
        qhi, qlo, (long)S * D, (long)D, w1hi, w1lo, (long)H * D,
        pd, S, 0L, cls_b1, (long)H, cls_w2);

    // 6) attention + softmaxes + weighted q sums -> qv hi/lo
    attn_kernel<<<B, 256>>>(q, cls_b2, out);

    // 7) [audio; video] = qv * Cov^T + bcomb
    bsgemm<true, false><<<dim3(4, 32), 256, GEMM_SMEM>>>(
        qvhi, qvlo, (long)D, 0L, mchi + (long)D * D, mclo + (long)D * D, 0L,
        pav, D, 0L, pbcomb, 0L, nullptr);

    // 8) fusion + splits of head inputs
    avsplit<<<(int)((long)B * D / 4 / 256), 256>>>();

    // 9) heads: one z=3 launch  y = x * W^T + b  [2048 x 512 x 1024]
    bsgemm<true, false><<<dim3(2, 16, 3), 256, GEMM_SMEM>>>(
        xhi, xlo, (long)D, (long)B * D, hwhi, hwlo, (long)F * D,
        py, F, (long)B * F, phb, (long)F, nullptr);

    // 10) LayerNorm + ReLU -> final outputs
    ln_relu<<<dim3(B, 3), 128>>>(fus_g, fus_be, pa_g, pa_be, pv_g, pv_be, out);
}

// round 10
// speedup vs baseline: 3.5079x; 1.2918x over previous
#include <cuda_runtime.h>
#include <cuda_fp16.h>
#include <cstdint>

// =============================================================================
// RAFF_8555574853896 — round 10: fp16 split HMMA GEMMs. Big GEMMs (qM, cls)
// use a 2-term split (ah*bh + ah*bl, rel err ~2.8e-4); small GEMMs keep 3
// terms. Round-7 geometry (128x128 block, 64x32 warp tile, 3-stage, 2 blk/SM).
// Weight-side operands pre-scaled x32 (sigma->1), undone by scaleC in epilogue.
//
// Algebra (validated):
//   scores = q Mt^T q^T / sqrt(D) + rank-1 bias,  Mt = (Wq^T Wk)^T
//   audio  = (w_a^T q) Cov^T + bcomb,             Cov = out_w Wv
// =============================================================================

namespace raff {

constexpr int B = 2048, S = 32, P = 16, D = 1024, H = 512, F = 512;
constexpr long NQ = (long)B * S * D;

constexpr float SWT = 32.f;                    // weight-side fp16 scale
constexpr float SC_QW = 1.f / SWT;             // activation(1) x weight(32)
constexpr float SC_WW = 1.f / (SWT * SWT);     // weight x weight

// ---------------- static device scratch ----------------
__device__ float g_vq[D], g_vk[D], g_bcomb[D];
__device__ float g_c0;
__device__ float g_MC[2 * D * D];              // [Mt; Cov] fp32
__device__ float g_qM[NQ];                     // 256 MB
__device__ float g_d[B * S];                   // classifier logits (atomic acc)
__device__ float g_av[2L * B * D];             // audio, video
__device__ float g_y[3L * B * F];              // pre-LN head outputs
__device__ float g_hbias[3 * F];               // packed head biases

__device__ __half g_q_hi[NQ];                              // q lo never needed
__device__ __half g_w1_hi[(long)S * H * D], g_w1_lo[(long)S * H * D];
__device__ __half g_u_hi[2 * D * D], g_u_lo[2 * D * D];    // [WkT; out_w] x32
__device__ __half g_v_hi[2 * D * D], g_v_lo[2 * D * D];    // [WqT; WvT] x32
__device__ __half g_mc_hi[2 * D * D], g_mc_lo[2 * D * D];  // [Mt; Cov] x32
__device__ __half g_qv_hi[2L * B * D], g_qv_lo[2L * B * D];
__device__ __half g_x_hi[3L * B * D], g_x_lo[3L * B * D];  // fus,aud,vid
__device__ __half g_hw_hi[3L * F * D], g_hw_lo[3L * F * D];

// ---------------- PTX helpers (base sm_103-legal) ----------------
__device__ __forceinline__ uint32_t smem_u32(const void* p) {
    uint32_t a;
    asm("{ .reg .u64 t; cvta.to.shared.u64 t, %1; cvt.u32.u64 %0, t; }"
        : "=r"(a) : "l"(p));
    return a;
}
#define CP16(dst, src) \
    asm volatile("cp.async.cg.shared.global [%0], [%1], 16;" :: "r"(dst), "l"(src))
#define CP_COMMIT() asm volatile("cp.async.commit_group;" ::: "memory")

__device__ __forceinline__ void ldsm_x4(uint32_t* r, uint32_t addr) {
    asm volatile("ldmatrix.sync.aligned.m8n8.x4.shared.b16 {%0,%1,%2,%3}, [%4];"
                 : "=r"(r[0]), "=r"(r[1]), "=r"(r[2]), "=r"(r[3]) : "r"(addr));
}
__device__ __forceinline__ void ldsm_x2(uint32_t* r, uint32_t addr) {
    asm volatile("ldmatrix.sync.aligned.m8n8.x2.shared.b16 {%0,%1}, [%2];"
                 : "=r"(r[0]), "=r"(r[1]) : "r"(addr));
}
__device__ __forceinline__ void mma_f16(float* c, const uint32_t* a, const uint32_t* b) {
    asm volatile(
        "mma.sync.aligned.m16n8k16.row.col.f32.f16.f16.f32 "
        "{%0,%1,%2,%3}, {%4,%5,%6,%7}, {%8,%9}, {%0,%1,%2,%3};"
        : "+f"(c[0]), "+f"(c[1]), "+f"(c[2]), "+f"(c[3])
        : "r"(a[0]), "r"(a[1]), "r"(a[2]), "r"(a[3]), "r"(b[0]), "r"(b[1]));
}

// Swizzled tile address: rows of 64B (32 halves), 4 x 16B chunks, XOR (r>>1)&3.
__device__ __forceinline__ uint32_t swz(int r, int c) {
    return (uint32_t)((r * 4 + (c ^ ((r >> 1) & 3))) * 16);
}

__device__ __forceinline__ void hsplit(float x, float s, __half& hi, __half& lo) {
    const float xs = x * s;
    hi = __float2half_rn(xs);
    lo = __float2half_rn(xs - __half2float(hi));
}

// =============================================================================
// fp16 split GEMM: C[M,N] = A[M,K]*B[N,K]^T * scaleC (+bias[n]), fp32 out.
// K = 1024 (32 chunks of 32). Block 128x128, 8 warps (2m x 4n), warp 64x32,
// 3-stage cp.async, 2 blocks/SM.
// TWO: 2-term (A-hi only; terms ah*bh + ah*bl). else 3-term (+ al*bh).
// CLSD: d = relu(C*scaleC+bias).w2 partial dots, atomicAdd into C (g_d).
// =============================================================================
constexpr int STAGE = 32768;                 // Ahi 8K | Alo 8K | Bhi 8K | Blo 8K
constexpr int NSTG = 3;
constexpr int GEMM_SMEM = NSTG * STAGE;      // 96 KB -> 2 blocks/SM

template <bool BIAS, bool CLSD, bool TWO>
__global__ void __launch_bounds__(256, 2) bsgemm(
    const __half* __restrict__ Ahi, const __half* __restrict__ Alo,
    long lda, long aOffZ,
    const __half* __restrict__ Bhi, const __half* __restrict__ Blo,
    long bOffZ,
    float* __restrict__ C, int ldc, long cOffZ,
    const float* __restrict__ bias, long biasOffZ,
    const float* __restrict__ w2p, float scaleC)
{
    extern __shared__ char dsm[];
    const uint32_t base = smem_u32(dsm);

    const int tid = threadIdx.x, lane = tid & 31, w = tid >> 5;
    const int wm = w & 1, wn = w >> 1;            // 2 x 4 warp grid
    const int z = blockIdx.z;
    const long m0 = (long)blockIdx.y * 128;
    const long n0 = (long)blockIdx.x * 128;
    Ahi += z * aOffZ;
    if (!TWO) Alo += z * aOffZ;
    Bhi += z * bOffZ; Blo += z * bOffZ;
    C += z * cOffZ;
    if (BIAS || CLSD) bias += z * biasOffZ;

    float acc[4][4][4];
#pragma unroll
    for (int i = 0; i < 4; i++)
#pragma unroll
        for (int j = 0; j < 4; j++)
#pragma unroll
            for (int k = 0; k < 4; k++) acc[i][j][k] = 0.f;

    // ---- loader: one K-chunk of 32 into stage s ----
    auto loadChunk = [&](int s, int kc) {
        const long k0 = (long)kc * 32;
        const uint32_t ah = base + s * STAGE;
        const uint32_t al = ah + 8192;
        const uint32_t bh = ah + 16384;
        const uint32_t bl = ah + 24576;
#pragma unroll
        for (int i = 0; i < 2; i++) {
            const int idx = tid + 256 * i;
            const int r = idx >> 2, c = idx & 3;
            const uint32_t dst = swz(r, c);
            const long offA = (m0 + r) * lda + k0 + c * 8;
            CP16(ah + dst, Ahi + offA);
            if (!TWO) CP16(al + dst, Alo + offA);
            const long offB = (n0 + r) * 1024 + k0 + c * 8;
            CP16(bh + dst, Bhi + offB);
            CP16(bl + dst, Blo + offB);
        }
        CP_COMMIT();
    };

    // ---- compute one chunk, term-major ----
    auto computeChunk = [&](int s) {
        const uint32_t ah = base + s * STAGE;
        const uint32_t al = ah + 8192;
        const uint32_t bh = ah + 16384;
        const uint32_t bl = ah + 24576;
#pragma unroll
        for (int ks = 0; ks < 2; ks++) {
            uint32_t afh[4][4], afl[4][4], bf[4][2];
            const int arow = wm * 64 + (lane & 15);
            const int akc = ks * 2 + (lane >> 4);
#pragma unroll
            for (int i = 0; i < 4; i++) {
                const uint32_t off = swz(arow + i * 16, akc);
                ldsm_x4(afh[i], ah + off);
                if (!TWO) ldsm_x4(afl[i], al + off);
            }
            const int brow = wn * 32 + (lane & 7);
            const int bkc = ks * 2 + ((lane >> 3) & 1);
#pragma unroll
            for (int j = 0; j < 4; j++)
                ldsm_x2(bf[j], bh + swz(brow + j * 8, bkc));
            // hh (and lh if 3-term) share B-hi frags
#pragma unroll
            for (int i = 0; i < 4; i++)
#pragma unroll
                for (int j = 0; j < 4; j++) mma_f16(acc[i][j], afh[i], bf[j]);
            if (!TWO) {
#pragma unroll
                for (int i = 0; i < 4; i++)
#pragma unroll
                    for (int j = 0; j < 4; j++) mma_f16(acc[i][j], afl[i], bf[j]);
            }
            // overwrite with B-lo frags, hl
#pragma unroll
            for (int j = 0; j < 4; j++)
                ldsm_x2(bf[j], bl + swz(brow + j * 8, bkc));
#pragma unroll
            for (int i = 0; i < 4; i++)
#pragma unroll
                for (int j = 0; j < 4; j++) mma_f16(acc[i][j], afh[i], bf[j]);
        }
    };

    loadChunk(0, 0);
    loadChunk(1, 1);

    for (int ch = 0; ch < 32; ch++) {
        asm volatile("cp.async.wait_group 1;" ::: "memory");
        __syncthreads();
        if (ch + 2 < 32) loadChunk((ch + 2) % 3, ch + 2);
        else CP_COMMIT();                       // keep wait_group count valid
        computeChunk(ch % 3);
    }

    const int gr = lane >> 2, qd = lane & 3;

    if (CLSD) {
        // ---- fused classifier layer 2: partial d += relu(C*sc+b1).w2 ----
        float p[4][2];
#pragma unroll
        for (int i = 0; i < 4; i++) { p[i][0] = 0.f; p[i][1] = 0.f; }
        const float* w2 = w2p + (long)z * H;
#pragma unroll
        for (int j = 0; j < 4; j++) {
            const long c = n0 + wn * 32 + j * 8 + qd * 2;
            const float2 w2v = *(const float2*)&w2[c];
            const float2 bv = *(const float2*)&bias[c];
#pragma unroll
            for (int i = 0; i < 4; i++) {
                const float h0 = fmaxf(acc[i][j][0] * scaleC + bv.x, 0.f);
                const float h1 = fmaxf(acc[i][j][1] * scaleC + bv.y, 0.f);
                p[i][0] += h0 * w2v.x + h1 * w2v.y;
                const float h2 = fmaxf(acc[i][j][2] * scaleC + bv.x, 0.f);
                const float h3 = fmaxf(acc[i][j][3] * scaleC + bv.y, 0.f);
                p[i][1] += h2 * w2v.x + h3 * w2v.y;
            }
        }
#pragma unroll
        for (int i = 0; i < 4; i++) {
            p[i][0] += __shfl_xor_sync(~0u, p[i][0], 1);
            p[i][0] += __shfl_xor_sync(~0u, p[i][0], 2);
            p[i][1] += __shfl_xor_sync(~0u, p[i][1], 1);
            p[i][1] += __shfl_xor_sync(~0u, p[i][1], 2);
            if (qd == 0) {
                const long r = m0 + wm * 64 + i * 16 + gr;
                atomicAdd(&C[r * S + z], p[i][0]);
                atomicAdd(&C[(r + 8) * S + z], p[i][1]);
            }
        }
    } else {
        // ---- standard epilogue ----
#pragma unroll
        for (int j = 0; j < 4; j++) {
            const long c = n0 + wn * 32 + j * 8 + qd * 2;
            float2 bv = make_float2(0.f, 0.f);
            if (BIAS) bv = *(const float2*)&bias[c];
#pragma unroll
            for (int i = 0; i < 4; i++) {
                const long r0 = m0 + wm * 64 + i * 16 + gr;
                float2 v0 = make_float2(acc[i][j][0] * scaleC + bv.x,
                                        acc[i][j][1] * scaleC + bv.y);
                float2 v1 = make_float2(acc[i][j][2] * scaleC + bv.x,
                                        acc[i][j][3] * scaleC + bv.y);
                *(float2*)&C[r0 * ldc + c] = v0;
                *(float2*)&C[(r0 + 8) * ldc + c] = v1;
            }
        }
    }
}

// =============================================================================
// fp32 -> fp16 hi/lo split (scaled), vectorized by 4
// =============================================================================
__device__ __forceinline__ void store_split4(float4 v, float s, __half* hi,
                                             __half* lo, long i4) {
    __half h0, h1, h2, h3, l0, l1, l2, l3;
    hsplit(v.x, s, h0, l0);
    hsplit(v.y, s, h1, l1);
    hsplit(v.z, s, h2, l2);
    hsplit(v.w, s, h3, l3);
    __half2 a, b;
    a.x = h0; a.y = h1; b.x = h2; b.y = h3;
    ((__half2*)hi)[2 * i4] = a; ((__half2*)hi)[2 * i4 + 1] = b;
    a.x = l0; a.y = l1; b.x = l2; b.y = l3;
    ((__half2*)lo)[2 * i4] = a; ((__half2*)lo)[2 * i4 + 1] = b;
}

__global__ void split4(const float* __restrict__ src, __half* __restrict__ hi,
                       __half* __restrict__ lo, long n4, float s)
{
    const long i = (long)blockIdx.x * 256 + threadIdx.x;
    if (i >= n4) return;
    store_split4(((const float4*)src)[i], s, hi, lo, i);
}

// hi-only split for q (lo never consumed)
__global__ void split_hi(const float* __restrict__ src, __half* __restrict__ hi,
                         long n4)
{
    const long i = (long)blockIdx.x * 256 + threadIdx.x;
    if (i >= n4) return;
    float4 v = ((const float4*)src)[i];
    __half2 a, b;
    a.x = __float2half_rn(v.x); a.y = __float2half_rn(v.y);
    b.x = __float2half_rn(v.z); b.y = __float2half_rn(v.w);
    ((__half2*)hi)[2 * i] = a; ((__half2*)hi)[2 * i + 1] = b;
}

// 1024x1024 transpose + scaled split: dst[c][r] = src[r][c] * SWT
__global__ void tsplit(const float* __restrict__ src, __half* __restrict__ hi,
                       __half* __restrict__ lo)
{
    __shared__ float t[32][33];
    const int bx = blockIdx.x * 32, by = blockIdx.y * 32;
    const int tx = threadIdx.x;
    for (int j = threadIdx.y; j < 32; j += 8)
        t[j][tx] = src[(long)(by + j) * 1024 + bx + tx];
    __syncthreads();
    for (int j = threadIdx.y; j < 32; j += 8) {
        const long o = (long)(bx + j) * 1024 + by + tx;
        __half h, l;
        hsplit(t[tx][j], SWT, h, l);
        hi[o] = h; lo[o] = l;
    }
}

// avsplit: fusion = 0.5*(audio+video); split fusion, audio, video -> x (s=1)
__global__ void avsplit()
{
    const long i = (long)blockIdx.x * 256 + threadIdx.x;
    const long n4 = (long)B * D / 4;
    float4 a = ((const float4*)g_av)[i];
    float4 v = ((const float4*)g_av)[n4 + i];
    float4 f = make_float4(0.5f * (a.x + v.x), 0.5f * (a.y + v.y),
                           0.5f * (a.z + v.z), 0.5f * (a.w + v.w));
    store_split4(f, 1.f, g_x_hi, g_x_lo, i);
    store_split4(a, 1.f, g_x_hi, g_x_lo, n4 + i);
    store_split4(v, 1.f, g_x_hi, g_x_lo, 2 * n4 + i);
}

__global__ void zero_d()
{
    g_d[blockIdx.x * 256 + threadIdx.x] = 0.f;
}

__global__ void pack_bias(const float* __restrict__ b0, const float* __restrict__ b1,
                          const float* __restrict__ b2)
{
    const int i = blockIdx.x * 256 + threadIdx.x;   // 0..1535
    const int hh = i >> 9, j = i & 511;
    g_hbias[i] = hh == 0 ? b0[j] : (hh == 1 ? b1[j] : b2[j]);
}

// =============================================================================
// bias-derived vectors (fp32, tiny)
// =============================================================================
__global__ void vec_pre(const float* __restrict__ in_proj_w,
                        const float* __restrict__ in_proj_b,
                        const float* __restrict__ out_w,
                        const float* __restrict__ out_b)
{
    const int i = blockIdx.x * 256 + threadIdx.x;
    const float* wq = in_proj_w;
    const float* wk = in_proj_w + (long)D * D;
    const float* bq = in_proj_b;
    const float* bk = in_proj_b + D;
    const float* bv = in_proj_b + 2 * D;
    float vq = 0.f, vk = 0.f, bc = 0.f;
    for (int e = 0; e < D; e++) {
        vq = fmaf(bq[e], wk[(long)e * D + i], vq);
        vk = fmaf(bk[e], wq[(long)e * D + i], vk);
        bc = fmaf(out_w[(long)i * D + e], bv[e], bc);
    }
    g_vq[i] = vq; g_vk[i] = vk; g_bcomb[i] = bc + out_b[i];
    if (i == 0) {
        float c = 0.f;
        for (int e = 0; e < D; e++) c = fmaf(bq[e], bk[e], c);
        g_c0 = c;
    }
}

// =============================================================================
// Per-batch attention (fp32); reads g_d (pre-bias logits), writes qv hi/lo
// =============================================================================
__global__ void __launch_bounds__(256) attn_kernel(
    const float* __restrict__ q, const float* __restrict__ cls_b2,
    float* __restrict__ out)
{
    const int b = blockIdx.x;
    __shared__ float qs[32][132];
    __shared__ float qms[32][132];
    __shared__ float sc[32][33];
    __shared__ float vks[128];
    __shared__ float dd[32], rk[32], wa[32], wvv[32], da[16], dv[16];

    const int tid = threadIdx.x;
    const int s = tid >> 3;
    const int tb = tid & 7;
    const float* qb = q + (long)b * S * D;
    const float* qmb = g_qM + (long)b * S * D;

    if (tid < 32) dd[tid] = fmaxf(g_d[b * S + tid] + cls_b2[tid], 0.f);

    float racc[4] = {0.f, 0.f, 0.f, 0.f};
    float rkacc = 0.f;

    for (int c = 0; c < D; c += 128) {
#pragma unroll
        for (int i = 0; i < 4; i++) {
            const int f = tid + 256 * i;
            const int r = f >> 5;
            const int c4 = (f & 31) << 2;
            *(float4*)&qs[r][c4] = *(const float4*)&qb[(long)r * D + c + c4];
            *(float4*)&qms[r][c4] = *(const float4*)&qmb[(long)r * D + c + c4];
        }
        if (tid < 32) *(float4*)&vks[tid * 4] = *(const float4*)&g_vk[c + tid * 4];
        __syncthreads();

#pragma unroll 4
        for (int k = 0; k < 128; k++) {
            const float av = qms[s][k];
#pragma unroll
            for (int j = 0; j < 4; j++)
                racc[j] = fmaf(av, qs[tb + 8 * j][k], racc[j]);
        }
        if (tid < 32) {
            float r2 = 0.f;
#pragma unroll 4
            for (int k = 0; k < 128; k++) r2 = fmaf(qs[tid][k], vks[k], r2);
            rkacc += r2;
        }
        __syncthreads();
    }

#pragma unroll
    for (int j = 0; j < 4; j++) sc[s][tb + 8 * j] = racc[j];
    if (tid < 32) rk[tid] = rkacc;
    __syncthreads();

    const int w = tid >> 5, lane = tid & 31;
    const float inv_sqrtD = 0.03125f;
    for (int rr = w * 4; rr < w * 4 + 4; rr++) {
        float v = (sc[rr][lane] + rk[rr] + g_c0) * inv_sqrtD;
        float mx = v;
#pragma unroll
        for (int o = 16; o > 0; o >>= 1) mx = fmaxf(mx, __shfl_xor_sync(~0u, mx, o));
        float e = __expf(v - mx);
        float sum = e;
#pragma unroll
        for (int o = 16; o > 0; o >>= 1) sum += __shfl_xor_sync(~0u, sum, o);
        sc[rr][lane] = e / sum;
    }
    __syncthreads();

    if (tid < 32) {
        const bool isA = tid < 16;
        const int i = tid & 15;
        float v = dd[tid];
        float mx = v;
#pragma unroll
        for (int o = 8; o > 0; o >>= 1) mx = fmaxf(mx, __shfl_xor_sync(~0u, mx, o));
        float e = __expf(v - mx);
        float sum = e;
#pragma unroll
        for (int o = 8; o > 0; o >>= 1) sum += __shfl_xor_sync(~0u, sum, o);
        const float p = e / sum;
        if (isA) da[i] = p; else dv[i] = p;
        const long bse = 3L * B * F;
        if (isA) out[bse + (long)b * P + i] = p;
        else     out[bse + (long)B * P + (long)b * P + i] = p;
    }
    __syncthreads();

    if (tid < 32) {
        float a = 0.f, v2 = 0.f;
#pragma unroll
        for (int ss = 0; ss < 16; ss++) a = fmaf(da[ss], sc[ss][tid], a);
#pragma unroll
        for (int ss = 0; ss < 16; ss++) v2 = fmaf(dv[ss], sc[16 + ss][tid], v2);
        wa[tid] = a;
        wvv[tid] = v2;
    }
    __syncthreads();

#pragma unroll
    for (int i = 0; i < 4; i++) {
        const int col = tid + 256 * i;
        float a = 0.f, v2 = 0.f;
#pragma unroll
        for (int t = 0; t < 32; t++) {
            const float x = qb[(long)t * D + col];
            a = fmaf(wa[t], x, a);
            v2 = fmaf(wvv[t], x, v2);
        }
        const long ia = (long)b * D + col;
        const long iv = (long)B * D + ia;
        __half h, l;
        hsplit(a, 1.f, h, l);
        g_qv_hi[ia] = h; g_qv_lo[ia] = l;
        hsplit(v2, 1.f, h, l);
        g_qv_hi[iv] = h; g_qv_lo[iv] = l;
    }
}

__global__ void __launch_bounds__(128) ln_relu(
    const float* __restrict__ gm0, const float* __restrict__ be0,
    const float* __restrict__ gm1, const float* __restrict__ be1,
    const float* __restrict__ gm2, const float* __restrict__ be2,
    float* __restrict__ out)
{
    const int head = blockIdx.y, b = blockIdx.x, tid = threadIdx.x;
    const float* gm = head == 0 ? gm0 : (head == 1 ? gm1 : gm2);
    const float* be = head == 0 ? be0 : (head == 1 ? be1 : be2);
    const float* y = g_y + ((long)head * B + b) * F;

    float4 v = *(const float4*)&y[tid * 4];
    float s = v.x + v.y + v.z + v.w;
    float sq = v.x * v.x + v.y * v.y + v.z * v.z + v.w * v.w;
#pragma unroll
    for (int o = 16; o > 0; o >>= 1) {
        s += __shfl_xor_sync(~0u, s, o);
        sq += __shfl_xor_sync(~0u, sq, o);
    }
    __shared__ float ss[4], ssq[4];
    const int w = tid >> 5;
    if ((tid & 31) == 0) { ss[w] = s; ssq[w] = sq; }
    __syncthreads();
    s = ss[0] + ss[1] + ss[2] + ss[3];
    sq = ssq[0] + ssq[1] + ssq[2] + ssq[3];
    const float mean = s * (1.f / F);
    const float var = sq * (1.f / F) - mean * mean;
    const float rstd = rsqrtf(var + 1e-5f);

    float4 g4 = *(const float4*)&gm[tid * 4];
    float4 b4 = *(const float4*)&be[tid * 4];
    float4 o4;
    o4.x = fmaxf((v.x - mean) * rstd * g4.x + b4.x, 0.f);
    o4.y = fmaxf((v.y - mean) * rstd * g4.y + b4.y, 0.f);
    o4.z = fmaxf((v.z - mean) * rstd * g4.z + b4.z, 0.f);
    o4.w = fmaxf((v.w - mean) * rstd * g4.w + b4.w, 0.f);
    *(float4*)&out[((long)head * B + b) * F + tid * 4] = o4;
}

}  // namespace raff

// =============================================================================
// Launch
// =============================================================================
extern "C" void kernel_launch(void* const* d_in, const int* in_sizes, int n_in,
                              void* d_out, int out_size)
{
    using namespace raff;
    (void)in_sizes; (void)n_in; (void)out_size;

    const float* q         = (const float*)d_in[0];
    const float* in_proj_w = (const float*)d_in[1];
    const float* in_proj_b = (const float*)d_in[2];
    const float* out_w     = (const float*)d_in[3];
    const float* out_b     = (const float*)d_in[4];
    const float* cls_w1    = (const float*)d_in[5];
    const float* cls_b1    = (const float*)d_in[6];
    const float* cls_w2    = (const float*)d_in[7];
    const float* cls_b2    = (const float*)d_in[8];
    const float* fus_w     = (const float*)d_in[9];
    const float* fus_b     = (const float*)d_in[10];
    const float* fus_g     = (const float*)d_in[11];
    const float* fus_be    = (const float*)d_in[12];
    const float* pa_w      = (const float*)d_in[13];
    const float* pa_b      = (const float*)d_in[14];
    const float* pa_g      = (const float*)d_in[15];
    const float* pa_be     = (const float*)d_in[16];
    const float* pv_w      = (const float*)d_in[17];
    const float* pv_b      = (const float*)d_in[18];
    const float* pv_g      = (const float*)d_in[19];
    const float* pv_be     = (const float*)d_in[20];
    float* out = (float*)d_out;

    float *pMC, *pqM, *pd, *pav, *py, *pvq, *pbcomb, *phb;
    __half *qhi, *w1hi, *w1lo, *uhi, *ulo, *vhi, *vlo,
        *mchi, *mclo, *qvhi, *qvlo, *xhi, *xlo, *hwhi, *hwlo;
    cudaGetSymbolAddress((void**)&pMC, g_MC);
    cudaGetSymbolAddress((void**)&pqM, g_qM);
    cudaGetSymbolAddress((void**)&pd, g_d);
    cudaGetSymbolAddress((void**)&pav, g_av);
    cudaGetSymbolAddress((void**)&py, g_y);
    cudaGetSymbolAddress((void**)&pvq, g_vq);
    cudaGetSymbolAddress((void**)&pbcomb, g_bcomb);
    cudaGetSymbolAddress((void**)&phb, g_hbias);
    cudaGetSymbolAddress((void**)&qhi, g_q_hi);
    cudaGetSymbolAddress((void**)&w1hi, g_w1_hi);
    cudaGetSymbolAddress((void**)&w1lo, g_w1_lo);
    cudaGetSymbolAddress((void**)&uhi, g_u_hi);
    cudaGetSymbolAddress((void**)&ulo, g_u_lo);
    cudaGetSymbolAddress((void**)&vhi, g_v_hi);
    cudaGetSymbolAddress((void**)&vlo, g_v_lo);
    cudaGetSymbolAddress((void**)&mchi, g_mc_hi);
    cudaGetSymbolAddress((void**)&mclo, g_mc_lo);
    cudaGetSymbolAddress((void**)&qvhi, g_qv_hi);
    cudaGetSymbolAddress((void**)&qvlo, g_qv_lo);
    cudaGetSymbolAddress((void**)&xhi, g_x_hi);
    cudaGetSymbolAddress((void**)&xlo, g_x_lo);
    cudaGetSymbolAddress((void**)&hwhi, g_hw_hi);
    cudaGetSymbolAddress((void**)&hwlo, g_hw_lo);

    cudaFuncSetAttribute((const void*)bsgemm<false, false, false>,
                         cudaFuncAttributeMaxDynamicSharedMemorySize, GEMM_SMEM);
    cudaFuncSetAttribute((const void*)bsgemm<true, false, false>,
                         cudaFuncAttributeMaxDynamicSharedMemorySize, GEMM_SMEM);
    cudaFuncSetAttribute((const void*)bsgemm<true, false, true>,
                         cudaFuncAttributeMaxDynamicSharedMemorySize, GEMM_SMEM);
    cudaFuncSetAttribute((const void*)bsgemm<false, true, true>,
                         cudaFuncAttributeMaxDynamicSharedMemorySize, GEMM_SMEM);

    // 1) tiny precomputations
    vec_pre<<<D / 256, 256>>>(in_proj_w, in_proj_b, out_w, out_b);
    pack_bias<<<6, 256>>>(fus_b, pa_b, pv_b);
    zero_d<<<B * S / 256, 256>>>();

    // 2) conversions of inputs
    split_hi<<<(int)(NQ / 4 / 256), 256>>>(q, qhi, NQ / 4);
    split4<<<(int)((long)S * H * D / 4 / 256), 256>>>(cls_w1, w1hi, w1lo,
                                                      (long)S * H * D / 4, SWT);
    split4<<<D * D / 4 / 256, 256>>>(out_w, uhi + (long)D * D, ulo + (long)D * D,
                                     D * D / 4, SWT);
    split4<<<F * D / 4 / 256, 256>>>(fus_w, hwhi, hwlo, (long)F * D / 4, SWT);
    split4<<<F * D / 4 / 256, 256>>>(pa_w, hwhi + (long)F * D, hwlo + (long)F * D,
                                     (long)F * D / 4, SWT);
    split4<<<F * D / 4 / 256, 256>>>(pv_w, hwhi + 2L * F * D, hwlo + 2L * F * D,
                                     (long)F * D / 4, SWT);
    tsplit<<<dim3(32, 32), dim3(32, 8)>>>(in_proj_w + (long)D * D, uhi, ulo);    // WkT
    tsplit<<<dim3(32, 32), dim3(32, 8)>>>(in_proj_w, vhi, vlo);                  // WqT
    tsplit<<<dim3(32, 32), dim3(32, 8)>>>(in_proj_w + 2L * D * D,
                                          vhi + (long)D * D, vlo + (long)D * D); // WvT

    // 3) [Mt; Cov] one z=2 launch (3-term), then split (x32)
    bsgemm<false, false, false><<<dim3(8, 8, 2), 256, GEMM_SMEM>>>(
        uhi, ulo, D, (long)D * D, vhi, vlo, (long)D * D,
        pMC, D, (long)D * D, nullptr, 0L, nullptr, SC_WW);
    split4<<<2 * D * D / 4 / 256, 256>>>(pMC, mchi, mclo, 2 * D * D / 4, SWT);

    // 4) qM = q * Mt^T + vq   [65536 x 1024 x 1024]  (2-term)
    bsgemm<true, false, true><<<dim3(8, 512), 256, GEMM_SMEM>>>(
        qhi, nullptr, (long)D, 0L, mchi, mclo, 0L, pqM, D, 0L, pvq, 0L,
        nullptr, SC_QW);

    // 5) classifier: fused h = relu(q w1^T + b1), d += h.w2 (2-term, atomic)
    bsgemm<false, true, true><<<dim3(4, 16, 32), 256, GEMM_SMEM>>>(
        qhi, nullptr, (long)S * D, (long)D, w1hi, w1lo, (long)H * D,
        pd, S, 0L, cls_b1, (long)H, cls_w2, SC_QW);

    // 6) attention + softmaxes + weighted q sums -> qv hi/lo
    attn_kernel<<<B, 256>>>(q, cls_b2, out);

    // 7) [audio; video] = qv * Cov^T + bcomb  (3-term)
    bsgemm<true, false, false><<<dim3(8, 32), 256, GEMM_SMEM>>>(
        qvhi, qvlo, (long)D, 0L, mchi + (long)D * D, mclo + (long)D * D, 0L,
        pav, D, 0L, pbcomb, 0L, nullptr, SC_QW);

    // 8) fusion + splits of head inputs
    avsplit<<<(int)((long)B * D / 4 / 256), 256>>>();

    // 9) heads: one z=3 launch  y = x * W^T + b  (3-term)
    bsgemm<true, false, false><<<dim3(4, 16, 3), 256, GEMM_SMEM>>>(
        xhi, xlo, (long)D, (long)B * D, hwhi, hwlo, (long)F * D,
        py, F, (long)B * F, phb, (long)F, nullptr, SC_QW);

    // 10) LayerNorm + ReLU -> final outputs
    ln_relu<<<dim3(B, 3), 128>>>(fus_g, fus_be, pa_g, pa_be, pv_g, pv_be, out);
}

// round 11
// speedup vs baseline: 4.1967x; 1.1963x over previous
#include <cuda_runtime.h>
#include <cuda_fp16.h>
#include <cstdint>

// =============================================================================
// RAFF_8555574853896 — round 11: fp16 split HMMA GEMMs with per-GEMM term
// count: qM 1-term (q_hi x Mt_hi), cls 2-term, small GEMMs 3-term.
// attn score phase: 2x2 register tiles, pitch-133 shared (conflict-free).
//
// Algebra (validated):
//   scores = q Mt^T q^T / sqrt(D) + rank-1 bias,  Mt = (Wq^T Wk)^T
//   audio  = (w_a^T q) Cov^T + bcomb,             Cov = out_w Wv
// =============================================================================

namespace raff {

constexpr int B = 2048, S = 32, P = 16, D = 1024, H = 512, F = 512;
constexpr long NQ = (long)B * S * D;

constexpr float SWT = 32.f;                    // weight-side fp16 scale
constexpr float SC_QW = 1.f / SWT;             // activation(1) x weight(32)
constexpr float SC_WW = 1.f / (SWT * SWT);     // weight x weight

// ---------------- static device scratch ----------------
__device__ float g_vq[D], g_vk[D], g_bcomb[D];
__device__ float g_c0;
__device__ float g_MC[2 * D * D];              // [Mt; Cov] fp32
__device__ float g_qM[NQ];                     // 256 MB
__device__ float g_d[B * S];                   // classifier logits (atomic acc)
__device__ float g_av[2L * B * D];             // audio, video
__device__ float g_y[3L * B * F];              // pre-LN head outputs
__device__ float g_hbias[3 * F];               // packed head biases

__device__ __half g_q_hi[NQ];                              // q lo never needed
__device__ __half g_w1_hi[(long)S * H * D], g_w1_lo[(long)S * H * D];
__device__ __half g_u_hi[2 * D * D], g_u_lo[2 * D * D];    // [WkT; out_w] x32
__device__ __half g_v_hi[2 * D * D], g_v_lo[2 * D * D];    // [WqT; WvT] x32
__device__ __half g_mc_hi[2 * D * D], g_mc_lo[2 * D * D];  // [Mt; Cov] x32
__device__ __half g_qv_hi[2L * B * D], g_qv_lo[2L * B * D];
__device__ __half g_x_hi[3L * B * D], g_x_lo[3L * B * D];  // fus,aud,vid
__device__ __half g_hw_hi[3L * F * D], g_hw_lo[3L * F * D];

// ---------------- PTX helpers (base sm_103-legal) ----------------
__device__ __forceinline__ uint32_t smem_u32(const void* p) {
    uint32_t a;
    asm("{ .reg .u64 t; cvta.to.shared.u64 t, %1; cvt.u32.u64 %0, t; }"
        : "=r"(a) : "l"(p));
    return a;
}
#define CP16(dst, src) \
    asm volatile("cp.async.cg.shared.global [%0], [%1], 16;" :: "r"(dst), "l"(src))
#define CP_COMMIT() asm volatile("cp.async.commit_group;" ::: "memory")

__device__ __forceinline__ void ldsm_x4(uint32_t* r, uint32_t addr) {
    asm volatile("ldmatrix.sync.aligned.m8n8.x4.shared.b16 {%0,%1,%2,%3}, [%4];"
                 : "=r"(r[0]), "=r"(r[1]), "=r"(r[2]), "=r"(r[3]) : "r"(addr));
}
__device__ __forceinline__ void ldsm_x2(uint32_t* r, uint32_t addr) {
    asm volatile("ldmatrix.sync.aligned.m8n8.x2.shared.b16 {%0,%1}, [%2];"
                 : "=r"(r[0]), "=r"(r[1]) : "r"(addr));
}
__device__ __forceinline__ void mma_f16(float* c, const uint32_t* a, const uint32_t* b) {
    asm volatile(
        "mma.sync.aligned.m16n8k16.row.col.f32.f16.f16.f32 "
        "{%0,%1,%2,%3}, {%4,%5,%6,%7}, {%8,%9}, {%0,%1,%2,%3};"
        : "+f"(c[0]), "+f"(c[1]), "+f"(c[2]), "+f"(c[3])
        : "r"(a[0]), "r"(a[1]), "r"(a[2]), "r"(a[3]), "r"(b[0]), "r"(b[1]));
}

// Swizzled tile address: rows of 64B (32 halves), 4 x 16B chunks, XOR (r>>1)&3.
__device__ __forceinline__ uint32_t swz(int r, int c) {
    return (uint32_t)((r * 4 + (c ^ ((r >> 1) & 3))) * 16);
}

__device__ __forceinline__ void hsplit(float x, float s, __half& hi, __half& lo) {
    const float xs = x * s;
    hi = __float2half_rn(xs);
    lo = __float2half_rn(xs - __half2float(hi));
}

// =============================================================================
// fp16 split GEMM: C[M,N] = A[M,K]*B[N,K]^T * scaleC (+bias[n]), fp32 out.
// K = 1024 (32 chunks of 32). Block 128x128, 8 warps (2m x 4n), warp 64x32,
// 3-stage cp.async, 2 blocks/SM.
// TERMS: 1 = ah*bh; 2 = + ah*bl; 3 = + al*bh.
// CLSD: d = relu(C*scaleC+bias).w2 partial dots, atomicAdd into C (g_d).
// =============================================================================
constexpr int STAGE = 32768;                 // Ahi 8K | Alo 8K | Bhi 8K | Blo 8K
constexpr int NSTG = 3;
constexpr int GEMM_SMEM = NSTG * STAGE;      // 96 KB -> 2 blocks/SM

template <int TERMS, bool BIAS, bool CLSD>
__global__ void __launch_bounds__(256, 2) bsgemm(
    const __half* __restrict__ Ahi, const __half* __restrict__ Alo,
    long lda, long aOffZ,
    const __half* __restrict__ Bhi, const __half* __restrict__ Blo,
    long bOffZ,
    float* __restrict__ C, int ldc, long cOffZ,
    const float* __restrict__ bias, long biasOffZ,
    const float* __restrict__ w2p, float scaleC)
{
    extern __shared__ char dsm[];
    const uint32_t base = smem_u32(dsm);

    const int tid = threadIdx.x, lane = tid & 31, w = tid >> 5;
    const int wm = w & 1, wn = w >> 1;            // 2 x 4 warp grid
    const int z = blockIdx.z;
    const long m0 = (long)blockIdx.y * 128;
    const long n0 = (long)blockIdx.x * 128;
    Ahi += z * aOffZ;
    if (TERMS >= 3) Alo += z * aOffZ;
    Bhi += z * bOffZ;
    if (TERMS >= 2) Blo += z * bOffZ;
    C += z * cOffZ;
    if (BIAS || CLSD) bias += z * biasOffZ;

    float acc[4][4][4];
#pragma unroll
    for (int i = 0; i < 4; i++)
#pragma unroll
        for (int j = 0; j < 4; j++)
#pragma unroll
            for (int k = 0; k < 4; k++) acc[i][j][k] = 0.f;

    // ---- loader: one K-chunk of 32 into stage s ----
    auto loadChunk = [&](int s, int kc) {
        const long k0 = (long)kc * 32;
        const uint32_t ah = base + s * STAGE;
        const uint32_t al = ah + 8192;
        const uint32_t bh = ah + 16384;
        const uint32_t bl = ah + 24576;
#pragma unroll
        for (int i = 0; i < 2; i++) {
            const int idx = tid + 256 * i;
            const int r = idx >> 2, c = idx & 3;
            const uint32_t dst = swz(r, c);
            const long offA = (m0 + r) * lda + k0 + c * 8;
            CP16(ah + dst, Ahi + offA);
            if (TERMS >= 3) CP16(al + dst, Alo + offA);
            const long offB = (n0 + r) * 1024 + k0 + c * 8;
            CP16(bh + dst, Bhi + offB);
            if (TERMS >= 2) CP16(bl + dst, Blo + offB);
        }
        CP_COMMIT();
    };

    // ---- compute one chunk, term-major ----
    auto computeChunk = [&](int s) {
        const uint32_t ah = base + s * STAGE;
        const uint32_t al = ah + 8192;
        const uint32_t bh = ah + 16384;
        const uint32_t bl = ah + 24576;
#pragma unroll
        for (int ks = 0; ks < 2; ks++) {
            uint32_t afh[4][4], afl[4][4], bf[4][2];
            const int arow = wm * 64 + (lane & 15);
            const int akc = ks * 2 + (lane >> 4);
#pragma unroll
            for (int i = 0; i < 4; i++) {
                const uint32_t off = swz(arow + i * 16, akc);
                ldsm_x4(afh[i], ah + off);
                if (TERMS >= 3) ldsm_x4(afl[i], al + off);
            }
            const int brow = wn * 32 + (lane & 7);
            const int bkc = ks * 2 + ((lane >> 3) & 1);
#pragma unroll
            for (int j = 0; j < 4; j++)
                ldsm_x2(bf[j], bh + swz(brow + j * 8, bkc));
            // hh (and lh if 3-term) share B-hi frags
#pragma unroll
            for (int i = 0; i < 4; i++)
#pragma unroll
                for (int j = 0; j < 4; j++) mma_f16(acc[i][j], afh[i], bf[j]);
            if (TERMS >= 3) {
#pragma unroll
                for (int i = 0; i < 4; i++)
#pragma unroll
                    for (int j = 0; j < 4; j++) mma_f16(acc[i][j], afl[i], bf[j]);
            }
            if (TERMS >= 2) {
                // overwrite with B-lo frags, hl
#pragma unroll
                for (int j = 0; j < 4; j++)
                    ldsm_x2(bf[j], bl + swz(brow + j * 8, bkc));
#pragma unroll
                for (int i = 0; i < 4; i++)
#pragma unroll
                    for (int j = 0; j < 4; j++) mma_f16(acc[i][j], afh[i], bf[j]);
            }
        }
    };

    loadChunk(0, 0);
    loadChunk(1, 1);

    for (int ch = 0; ch < 32; ch++) {
        asm volatile("cp.async.wait_group 1;" ::: "memory");
        __syncthreads();
        if (ch + 2 < 32) loadChunk((ch + 2) % 3, ch + 2);
        else CP_COMMIT();                       // keep wait_group count valid
        computeChunk(ch % 3);
    }

    const int gr = lane >> 2, qd = lane & 3;

    if (CLSD) {
        // ---- fused classifier layer 2: partial d += relu(C*sc+b1).w2 ----
        float p[4][2];
#pragma unroll
        for (int i = 0; i < 4; i++) { p[i][0] = 0.f; p[i][1] = 0.f; }
        const float* w2 = w2p + (long)z * H;
#pragma unroll
        for (int j = 0; j < 4; j++) {
            const long c = n0 + wn * 32 + j * 8 + qd * 2;
            const float2 w2v = *(const float2*)&w2[c];
            const float2 bv = *(const float2*)&bias[c];
#pragma unroll
            for (int i = 0; i < 4; i++) {
                const float h0 = fmaxf(acc[i][j][0] * scaleC + bv.x, 0.f);
                const float h1 = fmaxf(acc[i][j][1] * scaleC + bv.y, 0.f);
                p[i][0] += h0 * w2v.x + h1 * w2v.y;
                const float h2 = fmaxf(acc[i][j][2] * scaleC + bv.x, 0.f);
                const float h3 = fmaxf(acc[i][j][3] * scaleC + bv.y, 0.f);
                p[i][1] += h2 * w2v.x + h3 * w2v.y;
            }
        }
#pragma unroll
        for (int i = 0; i < 4; i++) {
            p[i][0] += __shfl_xor_sync(~0u, p[i][0], 1);
            p[i][0] += __shfl_xor_sync(~0u, p[i][0], 2);
            p[i][1] += __shfl_xor_sync(~0u, p[i][1], 1);
            p[i][1] += __shfl_xor_sync(~0u, p[i][1], 2);
            if (qd == 0) {
                const long r = m0 + wm * 64 + i * 16 + gr;
                atomicAdd(&C[r * S + z], p[i][0]);
                atomicAdd(&C[(r + 8) * S + z], p[i][1]);
            }
        }
    } else {
        // ---- standard epilogue ----
#pragma unroll
        for (int j = 0; j < 4; j++) {
            const long c = n0 + wn * 32 + j * 8 + qd * 2;
            float2 bv = make_float2(0.f, 0.f);
            if (BIAS) bv = *(const float2*)&bias[c];
#pragma unroll
            for (int i = 0; i < 4; i++) {
                const long r0 = m0 + wm * 64 + i * 16 + gr;
                float2 v0 = make_float2(acc[i][j][0] * scaleC + bv.x,
                                        acc[i][j][1] * scaleC + bv.y);
                float2 v1 = make_float2(acc[i][j][2] * scaleC + bv.x,
                                        acc[i][j][3] * scaleC + bv.y);
                *(float2*)&C[r0 * ldc + c] = v0;
                *(float2*)&C[(r0 + 8) * ldc + c] = v1;
            }
        }
    }
}

// =============================================================================
// fp32 -> fp16 hi/lo split (scaled), vectorized by 4
// =============================================================================
__device__ __forceinline__ void store_split4(float4 v, float s, __half* hi,
                                             __half* lo, long i4) {
    __half h0, h1, h2, h3, l0, l1, l2, l3;
    hsplit(v.x, s, h0, l0);
    hsplit(v.y, s, h1, l1);
    hsplit(v.z, s, h2, l2);
    hsplit(v.w, s, h3, l3);
    __half2 a, b;
    a.x = h0; a.y = h1; b.x = h2; b.y = h3;
    ((__half2*)hi)[2 * i4] = a; ((__half2*)hi)[2 * i4 + 1] = b;
    a.x = l0; a.y = l1; b.x = l2; b.y = l3;
    ((__half2*)lo)[2 * i4] = a; ((__half2*)lo)[2 * i4 + 1] = b;
}

__global__ void split4(const float* __restrict__ src, __half* __restrict__ hi,
                       __half* __restrict__ lo, long n4, float s)
{
    const long i = (long)blockIdx.x * 256 + threadIdx.x;
    if (i >= n4) return;
    store_split4(((const float4*)src)[i], s, hi, lo, i);
}

// hi-only split for q (lo never consumed)
__global__ void split_hi(const float* __restrict__ src, __half* __restrict__ hi,
                         long n4)
{
    const long i = (long)blockIdx.x * 256 + threadIdx.x;
    if (i >= n4) return;
    float4 v = ((const float4*)src)[i];
    __half2 a, b;
    a.x = __float2half_rn(v.x); a.y = __float2half_rn(v.y);
    b.x = __float2half_rn(v.z); b.y = __float2half_rn(v.w);
    ((__half2*)hi)[2 * i] = a; ((__half2*)hi)[2 * i + 1] = b;
}

// 1024x1024 transpose + scaled split: dst[c][r] = src[r][c] * SWT
__global__ void tsplit(const float* __restrict__ src, __half* __restrict__ hi,
                       __half* __restrict__ lo)
{
    __shared__ float t[32][33];
    const int bx = blockIdx.x * 32, by = blockIdx.y * 32;
    const int tx = threadIdx.x;
    for (int j = threadIdx.y; j < 32; j += 8)
        t[j][tx] = src[(long)(by + j) * 1024 + bx + tx];
    __syncthreads();
    for (int j = threadIdx.y; j < 32; j += 8) {
        const long o = (long)(bx + j) * 1024 + by + tx;
        __half h, l;
        hsplit(t[tx][j], SWT, h, l);
        hi[o] = h; lo[o] = l;
    }
}

// avsplit: fusion = 0.5*(audio+video); split fusion, audio, video -> x (s=1)
__global__ void avsplit()
{
    const long i = (long)blockIdx.x * 256 + threadIdx.x;
    const long n4 = (long)B * D / 4;
    float4 a = ((const float4*)g_av)[i];
    float4 v = ((const float4*)g_av)[n4 + i];
    float4 f = make_float4(0.5f * (a.x + v.x), 0.5f * (a.y + v.y),
                           0.5f * (a.z + v.z), 0.5f * (a.w + v.w));
    store_split4(f, 1.f, g_x_hi, g_x_lo, i);
    store_split4(a, 1.f, g_x_hi, g_x_lo, n4 + i);
    store_split4(v, 1.f, g_x_hi, g_x_lo, 2 * n4 + i);
}

__global__ void zero_d()
{
    g_d[blockIdx.x * 256 + threadIdx.x] = 0.f;
}

__global__ void pack_bias(const float* __restrict__ b0, const float* __restrict__ b1,
                          const float* __restrict__ b2)
{
    const int i = blockIdx.x * 256 + threadIdx.x;   // 0..1535
    const int hh = i >> 9, j = i & 511;
    g_hbias[i] = hh == 0 ? b0[j] : (hh == 1 ? b1[j] : b2[j]);
}

// =============================================================================
// bias-derived vectors (fp32, tiny)
// =============================================================================
__global__ void vec_pre(const float* __restrict__ in_proj_w,
                        const float* __restrict__ in_proj_b,
                        const float* __restrict__ out_w,
                        const float* __restrict__ out_b)
{
    const int i = blockIdx.x * 256 + threadIdx.x;
    const float* wq = in_proj_w;
    const float* wk = in_proj_w + (long)D * D;
    const float* bq = in_proj_b;
    const float* bk = in_proj_b + D;
    const float* bv = in_proj_b + 2 * D;
    float vq = 0.f, vk = 0.f, bc = 0.f;
    for (int e = 0; e < D; e++) {
        vq = fmaf(bq[e], wk[(long)e * D + i], vq);
        vk = fmaf(bk[e], wq[(long)e * D + i], vk);
        bc = fmaf(out_w[(long)i * D + e], bv[e], bc);
    }
    g_vq[i] = vq; g_vk[i] = vk; g_bcomb[i] = bc + out_b[i];
    if (i == 0) {
        float c = 0.f;
        for (int e = 0; e < D; e++) c = fmaf(bq[e], bk[e], c);
        g_c0 = c;
    }
}

// =============================================================================
// Per-batch attention (fp32); 2x2 register-tiled scores, pitch-133 shared.
// Reads g_d (pre-bias logits) + g_qM, writes qv hi/lo.
// =============================================================================
constexpr int QPITCH = 133;   // 133 mod 32 = 5; 2*133 mod 32 = 10 -> both coprime-ish, conflict-free

__global__ void __launch_bounds__(256) attn_kernel(
    const float* __restrict__ q, const float* __restrict__ cls_b2,
    float* __restrict__ out)
{
    const int b = blockIdx.x;
    __shared__ float qs[32][QPITCH];
    __shared__ float qms[32][QPITCH];
    __shared__ float sc[32][33];
    __shared__ float vks[128];
    __shared__ float dd[32], rk[32], wa[32], wvv[32], da[16], dv[16];

    const int tid = threadIdx.x;
    const int s0 = (tid >> 4) << 1;   // 0,2,...,30
    const int t0 = (tid & 15) << 1;   // 0,2,...,30
    const float* qb = q + (long)b * S * D;
    const float* qmb = g_qM + (long)b * S * D;

    if (tid < 32) dd[tid] = fmaxf(g_d[b * S + tid] + cls_b2[tid], 0.f);

    float racc[2][2] = {{0.f, 0.f}, {0.f, 0.f}};
    float rkacc = 0.f;

    for (int c = 0; c < D; c += 128) {
#pragma unroll
        for (int i = 0; i < 4; i++) {
            const int f = tid + 256 * i;
            const int r = f >> 5;
            const int c4 = (f & 31) << 2;
            float4 v = *(const float4*)&qb[(long)r * D + c + c4];
            qs[r][c4] = v.x; qs[r][c4 + 1] = v.y;
            qs[r][c4 + 2] = v.z; qs[r][c4 + 3] = v.w;
            v = *(const float4*)&qmb[(long)r * D + c + c4];
            qms[r][c4] = v.x; qms[r][c4 + 1] = v.y;
            qms[r][c4 + 2] = v.z; qms[r][c4 + 3] = v.w;
        }
        if (tid < 32) *(float4*)&vks[tid * 4] = *(const float4*)&g_vk[c + tid * 4];
        __syncthreads();

#pragma unroll 4
        for (int k = 0; k < 128; k++) {
            const float a0 = qms[s0][k];
            const float a1 = qms[s0 + 1][k];
            const float b0 = qs[t0][k];
            const float b1 = qs[t0 + 1][k];
            racc[0][0] = fmaf(a0, b0, racc[0][0]);
            racc[0][1] = fmaf(a0, b1, racc[0][1]);
            racc[1][0] = fmaf(a1, b0, racc[1][0]);
            racc[1][1] = fmaf(a1, b1, racc[1][1]);
        }
        if (tid < 32) {
            float r2 = 0.f;
#pragma unroll 4
            for (int k = 0; k < 128; k++) r2 = fmaf(qs[tid][k], vks[k], r2);
            rkacc += r2;
        }
        __syncthreads();
    }

    sc[s0][t0] = racc[0][0];
    sc[s0][t0 + 1] = racc[0][1];
    sc[s0 + 1][t0] = racc[1][0];
    sc[s0 + 1][t0 + 1] = racc[1][1];
    if (tid < 32) rk[tid] = rkacc;
    __syncthreads();

    const int w = tid >> 5, lane = tid & 31;
    const float inv_sqrtD = 0.03125f;
    for (int rr = w * 4; rr < w * 4 + 4; rr++) {
        float v = (sc[rr][lane] + rk[rr] + g_c0) * inv_sqrtD;
        float mx = v;
#pragma unroll
        for (int o = 16; o > 0; o >>= 1) mx = fmaxf(mx, __shfl_xor_sync(~0u, mx, o));
        float e = __expf(v - mx);
        float sum = e;
#pragma unroll
        for (int o = 16; o > 0; o >>= 1) sum += __shfl_xor_sync(~0u, sum, o);
        sc[rr][lane] = e / sum;
    }
    __syncthreads();

    if (tid < 32) {
        const bool isA = tid < 16;
        const int i = tid & 15;
        float v = dd[tid];
        float mx = v;
#pragma unroll
        for (int o = 8; o > 0; o >>= 1) mx = fmaxf(mx, __shfl_xor_sync(~0u, mx, o));
        float e = __expf(v - mx);
        float sum = e;
#pragma unroll
        for (int o = 8; o > 0; o >>= 1) sum += __shfl_xor_sync(~0u, sum, o);
        const float p = e / sum;
        if (isA) da[i] = p; else dv[i] = p;
        const long bse = 3L * B * F;
        if (isA) out[bse + (long)b * P + i] = p;
        else     out[bse + (long)B * P + (long)b * P + i] = p;
    }
    __syncthreads();

    if (tid < 32) {
        float a = 0.f, v2 = 0.f;
#pragma unroll
        for (int ss = 0; ss < 16; ss++) a = fmaf(da[ss], sc[ss][tid], a);
#pragma unroll
        for (int ss = 0; ss < 16; ss++) v2 = fmaf(dv[ss], sc[16 + ss][tid], v2);
        wa[tid] = a;
        wvv[tid] = v2;
    }
    __syncthreads();

#pragma unroll
    for (int i = 0; i < 4; i++) {
        const int col = tid + 256 * i;
        float a = 0.f, v2 = 0.f;
#pragma unroll
        for (int t = 0; t < 32; t++) {
            const float x = qb[(long)t * D + col];
            a = fmaf(wa[t], x, a);
            v2 = fmaf(wvv[t], x, v2);
        }
        const long ia = (long)b * D + col;
        const long iv = (long)B * D + ia;
        __half h, l;
        hsplit(a, 1.f, h, l);
        g_qv_hi[ia] = h; g_qv_lo[ia] = l;
        hsplit(v2, 1.f, h, l);
        g_qv_hi[iv] = h; g_qv_lo[iv] = l;
    }
}

__global__ void __launch_bounds__(128) ln_relu(
    const float* __restrict__ gm0, const float* __restrict__ be0,
    const float* __restrict__ gm1, const float* __restrict__ be1,
    const float* __restrict__ gm2, const float* __restrict__ be2,
    float* __restrict__ out)
{
    const int head = blockIdx.y, b = blockIdx.x, tid = threadIdx.x;
    const float* gm = head == 0 ? gm0 : (head == 1 ? gm1 : gm2);
    const float* be = head == 0 ? be0 : (head == 1 ? be1 : be2);
    const float* y = g_y + ((long)head * B + b) * F;

    float4 v = *(const float4*)&y[tid * 4];
    float s = v.x + v.y + v.z + v.w;
    float sq = v.x * v.x + v.y * v.y + v.z * v.z + v.w * v.w;
#pragma unroll
    for (int o = 16; o > 0; o >>= 1) {
        s += __shfl_xor_sync(~0u, s, o);
        sq += __shfl_xor_sync(~0u, sq, o);
    }
    __shared__ float ss[4], ssq[4];
    const int w = tid >> 5;
    if ((tid & 31) == 0) { ss[w] = s; ssq[w] = sq; }
    __syncthreads();
    s = ss[0] + ss[1] + ss[2] + ss[3];
    sq = ssq[0] + ssq[1] + ssq[2] + ssq[3];
    const float mean = s * (1.f / F);
    const float var = sq * (1.f / F) - mean * mean;
    const float rstd = rsqrtf(var + 1e-5f);

    float4 g4 = *(const float4*)&gm[tid * 4];
    float4 b4 = *(const float4*)&be[tid * 4];
    float4 o4;
    o4.x = fmaxf((v.x - mean) * rstd * g4.x + b4.x, 0.f);
    o4.y = fmaxf((v.y - mean) * rstd * g4.y + b4.y, 0.f);
    o4.z = fmaxf((v.z - mean) * rstd * g4.z + b4.z, 0.f);
    o4.w = fmaxf((v.w - mean) * rstd * g4.w + b4.w, 0.f);
    *(float4*)&out[((long)head * B + b) * F + tid * 4] = o4;
}

}  // namespace raff

// =============================================================================
// Launch
// =============================================================================
extern "C" void kernel_launch(void* const* d_in, const int* in_sizes, int n_in,
                              void* d_out, int out_size)
{
    using namespace raff;
    (void)in_sizes; (void)n_in; (void)out_size;

    const float* q         = (const float*)d_in[0];
    const float* in_proj_w = (const float*)d_in[1];
    const float* in_proj_b = (const float*)d_in[2];
    const float* out_w     = (const float*)d_in[3];
    const float* out_b     = (const float*)d_in[4];
    const float* cls_w1    = (const float*)d_in[5];
    const float* cls_b1    = (const float*)d_in[6];
    const float* cls_w2    = (const float*)d_in[7];
    const float* cls_b2    = (const float*)d_in[8];
    const float* fus_w     = (const float*)d_in[9];
    const float* fus_b     = (const float*)d_in[10];
    const float* fus_g     = (const float*)d_in[11];
    const float* fus_be    = (const float*)d_in[12];
    const float* pa_w      = (const float*)d_in[13];
    const float* pa_b      = (const float*)d_in[14];
    const float* pa_g      = (const float*)d_in[15];
    const float* pa_be     = (const float*)d_in[16];
    const float* pv_w      = (const float*)d_in[17];
    const float* pv_b      = (const float*)d_in[18];
    const float* pv_g      = (const float*)d_in[19];
    const float* pv_be     = (const float*)d_in[20];
    float* out = (float*)d_out;

    float *pMC, *pqM, *pd, *pav, *py, *pvq, *pbcomb, *phb;
    __half *qhi, *w1hi, *w1lo, *uhi, *ulo, *vhi, *vlo,
        *mchi, *mclo, *qvhi, *qvlo, *xhi, *xlo, *hwhi, *hwlo;
    cudaGetSymbolAddress((void**)&pMC, g_MC);
    cudaGetSymbolAddress((void**)&pqM, g_qM);
    cudaGetSymbolAddress((void**)&pd, g_d);
    cudaGetSymbolAddress((void**)&pav, g_av);
    cudaGetSymbolAddress((void**)&py, g_y);
    cudaGetSymbolAddress((void**)&pvq, g_vq);
    cudaGetSymbolAddress((void**)&pbcomb, g_bcomb);
    cudaGetSymbolAddress((void**)&phb, g_hbias);
    cudaGetSymbolAddress((void**)&qhi, g_q_hi);
    cudaGetSymbolAddress((void**)&w1hi, g_w1_hi);
    cudaGetSymbolAddress((void**)&w1lo, g_w1_lo);
    cudaGetSymbolAddress((void**)&uhi, g_u_hi);
    cudaGetSymbolAddress((void**)&ulo, g_u_lo);
    cudaGetSymbolAddress((void**)&vhi, g_v_hi);
    cudaGetSymbolAddress((void**)&vlo, g_v_lo);
    cudaGetSymbolAddress((void**)&mchi, g_mc_hi);
    cudaGetSymbolAddress((void**)&mclo, g_mc_lo);
    cudaGetSymbolAddress((void**)&qvhi, g_qv_hi);
    cudaGetSymbolAddress((void**)&qvlo, g_qv_lo);
    cudaGetSymbolAddress((void**)&xhi, g_x_hi);
    cudaGetSymbolAddress((void**)&xlo, g_x_lo);
    cudaGetSymbolAddress((void**)&hwhi, g_hw_hi);
    cudaGetSymbolAddress((void**)&hwlo, g_hw_lo);

    cudaFuncSetAttribute((const void*)bsgemm<3, false, false>,
                         cudaFuncAttributeMaxDynamicSharedMemorySize, GEMM_SMEM);
    cudaFuncSetAttribute((const void*)bsgemm<3, true, false>,
                         cudaFuncAttributeMaxDynamicSharedMemorySize, GEMM_SMEM);
    cudaFuncSetAttribute((const void*)bsgemm<1, true, false>,
                         cudaFuncAttributeMaxDynamicSharedMemorySize, GEMM_SMEM);
    cudaFuncSetAttribute((const void*)bsgemm<2, false, true>,
                         cudaFuncAttributeMaxDynamicSharedMemorySize, GEMM_SMEM);

    // 1) tiny precomputations
    vec_pre<<<D / 256, 256>>>(in_proj_w, in_proj_b, out_w, out_b);
    pack_bias<<<6, 256>>>(fus_b, pa_b, pv_b);
    zero_d<<<B * S / 256, 256>>>();

    // 2) conversions of inputs
    split_hi<<<(int)(NQ / 4 / 256), 256>>>(q, qhi, NQ / 4);
    split4<<<(int)((long)S * H * D / 4 / 256), 256>>>(cls_w1, w1hi, w1lo,
                                                      (long)S * H * D / 4, SWT);
    split4<<<D * D / 4 / 256, 256>>>(out_w, uhi + (long)D * D, ulo + (long)D * D,
                                     D * D / 4, SWT);
    split4<<<F * D / 4 / 256, 256>>>(fus_w, hwhi, hwlo, (long)F * D / 4, SWT);
    split4<<<F * D / 4 / 256, 256>>>(pa_w, hwhi + (long)F * D, hwlo + (long)F * D,
                                     (long)F * D / 4, SWT);
    split4<<<F * D / 4 / 256, 256>>>(pv_w, hwhi + 2L * F * D, hwlo + 2L * F * D,
                                     (long)F * D / 4, SWT);
    tsplit<<<dim3(32, 32), dim3(32, 8)>>>(in_proj_w + (long)D * D, uhi, ulo);    // WkT
    tsplit<<<dim3(32, 32), dim3(32, 8)>>>(in_proj_w, vhi, vlo);                  // WqT
    tsplit<<<dim3(32, 32), dim3(32, 8)>>>(in_proj_w + 2L * D * D,
                                          vhi + (long)D * D, vlo + (long)D * D); // WvT

    // 3) [Mt; Cov] one z=2 launch (3-term), then split (x32)
    bsgemm<3, false, false><<<dim3(8, 8, 2), 256, GEMM_SMEM>>>(
        uhi, ulo, D, (long)D * D, vhi, vlo, (long)D * D,
        pMC, D, (long)D * D, nullptr, 0L, nullptr, SC_WW);
    split4<<<2 * D * D / 4 / 256, 256>>>(pMC, mchi, mclo, 2 * D * D / 4, SWT);

    // 4) qM = q * Mt^T + vq   [65536 x 1024 x 1024]  (1-term)
    bsgemm<1, true, false><<<dim3(8, 512), 256, GEMM_SMEM>>>(
        qhi, nullptr, (long)D, 0L, mchi, nullptr, 0L, pqM, D, 0L, pvq, 0L,
        nullptr, SC_QW);

    // 5) classifier: fused h = relu(q w1^T + b1), d += h.w2 (2-term, atomic)
    bsgemm<2, false, true><<<dim3(4, 16, 32), 256, GEMM_SMEM>>>(
        qhi, nullptr, (long)S * D, (long)D, w1hi, w1lo, (long)H * D,
        pd, S, 0L, cls_b1, (long)H, cls_w2, SC_QW);

    // 6) attention + softmaxes + weighted q sums -> qv hi/lo
    attn_kernel<<<B, 256>>>(q, cls_b2, out);

    // 7) [audio; video] = qv * Cov^T + bcomb  (3-term)
    bsgemm<3, true, false><<<dim3(8, 32), 256, GEMM_SMEM>>>(
        qvhi, qvlo, (long)D, 0L, mchi + (long)D * D, mclo + (long)D * D, 0L,
        pav, D, 0L, pbcomb, 0L, nullptr, SC_QW);

    // 8) fusion + splits of head inputs
    avsplit<<<(int)((long)B * D / 4 / 256), 256>>>();

    // 9) heads: one z=3 launch  y = x * W^T + b  (3-term)
    bsgemm<3, true, false><<<dim3(4, 16, 3), 256, GEMM_SMEM>>>(
        xhi, xlo, (long)D, (long)B * D, hwhi, hwlo, (long)F * D,
        py, F, (long)B * F, phb, (long)F, nullptr, SC_QW);

    // 10) LayerNorm + ReLU -> final outputs
    ln_relu<<<dim3(B, 3), 128>>>(fus_g, fus_be, pa_g, pa_be, pv_g, pv_be, out);
}

// round 12
// speedup vs baseline: 5.7344x; 1.3664x over previous
#include <cuda_runtime.h>
#include <cuda_fp16.h>
#include <cstdint>

// =============================================================================
// RAFF_8555574853896 — round 12: fp16 HMMA GEMMs with per-GEMM terms:
// qM 1-term -> fp16 output, cls 1-term, small GEMMs 3-term. attn score phase
// fully fp16 (shared + DRAM), weighted sum fp32. vec_pre parallelized.
//
// Algebra (validated):
//   scores = q Mt^T q^T / sqrt(D) + rank-1 bias,  Mt = (Wq^T Wk)^T
//   audio  = (w_a^T q) Cov^T + bcomb,             Cov = out_w Wv
// =============================================================================

namespace raff {

constexpr int B = 2048, S = 32, P = 16, D = 1024, H = 512, F = 512;
constexpr long NQ = (long)B * S * D;

constexpr float SWT = 32.f;                    // weight-side fp16 scale
constexpr float SC_QW = 1.f / SWT;
constexpr float SC_WW = 1.f / (SWT * SWT);

// ---------------- static device scratch ----------------
__device__ float g_vq[D], g_vk[D], g_bcomb[D];
__device__ float g_c0;
__device__ float g_MC[2 * D * D];              // [Mt; Cov] fp32
__device__ float g_d[B * S];                   // classifier logits (atomic acc)
__device__ float g_av[2L * B * D];             // audio, video
__device__ float g_y[3L * B * F];              // pre-LN head outputs
__device__ float g_hbias[3 * F];               // packed head biases

__device__ __half g_qM_h[NQ];                  // qM in fp16 (128 MB)
__device__ __half g_q_hi[NQ];
__device__ __half g_w1_hi[(long)S * H * D];    // unscaled, 1-term
__device__ __half g_u_hi[2 * D * D], g_u_lo[2 * D * D];    // [WkT; out_w] x32
__device__ __half g_v_hi[2 * D * D], g_v_lo[2 * D * D];    // [WqT; WvT] x32
__device__ __half g_mc_hi[2 * D * D], g_mc_lo[2 * D * D];  // [Mt; Cov] x32
__device__ __half g_qv_hi[2L * B * D], g_qv_lo[2L * B * D];
__device__ __half g_x_hi[3L * B * D], g_x_lo[3L * B * D];  // fus,aud,vid
__device__ __half g_hw_hi[3L * F * D], g_hw_lo[3L * F * D];

// ---------------- PTX helpers (base sm_103-legal) ----------------
__device__ __forceinline__ uint32_t smem_u32(const void* p) {
    uint32_t a;
    asm("{ .reg .u64 t; cvta.to.shared.u64 t, %1; cvt.u32.u64 %0, t; }"
        : "=r"(a) : "l"(p));
    return a;
}
#define CP16(dst, src) \
    asm volatile("cp.async.cg.shared.global [%0], [%1], 16;" :: "r"(dst), "l"(src))
#define CP_COMMIT() asm volatile("cp.async.commit_group;" ::: "memory")

__device__ __forceinline__ void ldsm_x4(uint32_t* r, uint32_t addr) {
    asm volatile("ldmatrix.sync.aligned.m8n8.x4.shared.b16 {%0,%1,%2,%3}, [%4];"
                 : "=r"(r[0]), "=r"(r[1]), "=r"(r[2]), "=r"(r[3]) : "r"(addr));
}
__device__ __forceinline__ void ldsm_x2(uint32_t* r, uint32_t addr) {
    asm volatile("ldmatrix.sync.aligned.m8n8.x2.shared.b16 {%0,%1}, [%2];"
                 : "=r"(r[0]), "=r"(r[1]) : "r"(addr));
}
__device__ __forceinline__ void mma_f16(float* c, const uint32_t* a, const uint32_t* b) {
    asm volatile(
        "mma.sync.aligned.m16n8k16.row.col.f32.f16.f16.f32 "
        "{%0,%1,%2,%3}, {%4,%5,%6,%7}, {%8,%9}, {%0,%1,%2,%3};"
        : "+f"(c[0]), "+f"(c[1]), "+f"(c[2]), "+f"(c[3])
        : "r"(a[0]), "r"(a[1]), "r"(a[2]), "r"(a[3]), "r"(b[0]), "r"(b[1]));
}

// Swizzled tile address: rows of 64B (32 halves), 4 x 16B chunks, XOR (r>>1)&3.
__device__ __forceinline__ uint32_t swz(int r, int c) {
    return (uint32_t)((r * 4 + (c ^ ((r >> 1) & 3))) * 16);
}

__device__ __forceinline__ void hsplit(float x, float s, __half& hi, __half& lo) {
    const float xs = x * s;
    hi = __float2half_rn(xs);
    lo = __float2half_rn(xs - __half2float(hi));
}

// =============================================================================
// fp16 split GEMM: C[M,N] = A[M,K]*B[N,K]^T * scaleC (+bias[n]).
// K = 1024 (32 chunks of 32). Block 128x128, 8 warps (2m x 4n), warp 64x32,
// 3-stage cp.async, 2 blocks/SM.
// TERMS: 1 = ah*bh; 2 = + ah*bl; 3 = + al*bh.
// HOUT: write __half output. CLSD: fused classifier layer 2 (atomicAdd d).
// =============================================================================
constexpr int STAGE = 32768;
constexpr int NSTG = 3;
constexpr int GEMM_SMEM = NSTG * STAGE;      // 96 KB -> 2 blocks/SM

template <int TERMS, bool BIAS, bool CLSD, bool HOUT>
__global__ void __launch_bounds__(256, 2) bsgemm(
    const __half* __restrict__ Ahi, const __half* __restrict__ Alo,
    long lda, long aOffZ,
    const __half* __restrict__ Bhi, const __half* __restrict__ Blo,
    long bOffZ,
    float* __restrict__ C, int ldc, long cOffZ,
    const float* __restrict__ bias, long biasOffZ,
    const float* __restrict__ w2p, float scaleC)
{
    extern __shared__ char dsm[];
    const uint32_t base = smem_u32(dsm);

    const int tid = threadIdx.x, lane = tid & 31, w = tid >> 5;
    const int wm = w & 1, wn = w >> 1;
    const int z = blockIdx.z;
    const long m0 = (long)blockIdx.y * 128;
    const long n0 = (long)blockIdx.x * 128;
    Ahi += z * aOffZ;
    if (TERMS >= 3) Alo += z * aOffZ;
    Bhi += z * bOffZ;
    if (TERMS >= 2) Blo += z * bOffZ;
    C += z * cOffZ;
    if (BIAS || CLSD) bias += z * biasOffZ;

    float acc[4][4][4];
#pragma unroll
    for (int i = 0; i < 4; i++)
#pragma unroll
        for (int j = 0; j < 4; j++)
#pragma unroll
            for (int k = 0; k < 4; k++) acc[i][j][k] = 0.f;

    auto loadChunk = [&](int s, int kc) {
        const long k0 = (long)kc * 32;
        const uint32_t ah = base + s * STAGE;
        const uint32_t al = ah + 8192;
        const uint32_t bh = ah + 16384;
        const uint32_t bl = ah + 24576;
#pragma unroll
        for (int i = 0; i < 2; i++) {
            const int idx = tid + 256 * i;
            const int r = idx >> 2, c = idx & 3;
            const uint32_t dst = swz(r, c);
            const long offA = (m0 + r) * lda + k0 + c * 8;
            CP16(ah + dst, Ahi + offA);
            if (TERMS >= 3) CP16(al + dst, Alo + offA);
            const long offB = (n0 + r) * 1024 + k0 + c * 8;
            CP16(bh + dst, Bhi + offB);
            if (TERMS >= 2) CP16(bl + dst, Blo + offB);
        }
        CP_COMMIT();
    };

    auto computeChunk = [&](int s) {
        const uint32_t ah = base + s * STAGE;
        const uint32_t al = ah + 8192;
        const uint32_t bh = ah + 16384;
        const uint32_t bl = ah + 24576;
#pragma unroll
        for (int ks = 0; ks < 2; ks++) {
            uint32_t afh[4][4], afl[4][4], bf[4][2];
            const int arow = wm * 64 + (lane & 15);
            const int akc = ks * 2 + (lane >> 4);
#pragma unroll
            for (int i = 0; i < 4; i++) {
                const uint32_t off = swz(arow + i * 16, akc);
                ldsm_x4(afh[i], ah + off);
                if (TERMS >= 3) ldsm_x4(afl[i], al + off);
            }
            const int brow = wn * 32 + (lane & 7);
            const int bkc = ks * 2 + ((lane >> 3) & 1);
#pragma unroll
            for (int j = 0; j < 4; j++)
                ldsm_x2(bf[j], bh + swz(brow + j * 8, bkc));
#pragma unroll
            for (int i = 0; i < 4; i++)
#pragma unroll
                for (int j = 0; j < 4; j++) mma_f16(acc[i][j], afh[i], bf[j]);
            if (TERMS >= 3) {
#pragma unroll
                for (int i = 0; i < 4; i++)
#pragma unroll
                    for (int j = 0; j < 4; j++) mma_f16(acc[i][j], afl[i], bf[j]);
            }
            if (TERMS >= 2) {
#pragma unroll
                for (int j = 0; j < 4; j++)
                    ldsm_x2(bf[j], bl + swz(brow + j * 8, bkc));
#pragma unroll
                for (int i = 0; i < 4; i++)
#pragma unroll
                    for (int j = 0; j < 4; j++) mma_f16(acc[i][j], afh[i], bf[j]);
            }
        }
    };

    loadChunk(0, 0);
    loadChunk(1, 1);

    for (int ch = 0; ch < 32; ch++) {
        asm volatile("cp.async.wait_group 1;" ::: "memory");
        __syncthreads();
        if (ch + 2 < 32) loadChunk((ch + 2) % 3, ch + 2);
        else CP_COMMIT();
        computeChunk(ch % 3);
    }

    const int gr = lane >> 2, qd = lane & 3;

    if (CLSD) {
        float p[4][2];
#pragma unroll
        for (int i = 0; i < 4; i++) { p[i][0] = 0.f; p[i][1] = 0.f; }
        const float* w2 = w2p + (long)z * H;
#pragma unroll
        for (int j = 0; j < 4; j++) {
            const long c = n0 + wn * 32 + j * 8 + qd * 2;
            const float2 w2v = *(const float2*)&w2[c];
            const float2 bv = *(const float2*)&bias[c];
#pragma unroll
            for (int i = 0; i < 4; i++) {
                const float h0 = fmaxf(acc[i][j][0] * scaleC + bv.x, 0.f);
                const float h1 = fmaxf(acc[i][j][1] * scaleC + bv.y, 0.f);
                p[i][0] += h0 * w2v.x + h1 * w2v.y;
                const float h2 = fmaxf(acc[i][j][2] * scaleC + bv.x, 0.f);
                const float h3 = fmaxf(acc[i][j][3] * scaleC + bv.y, 0.f);
                p[i][1] += h2 * w2v.x + h3 * w2v.y;
            }
        }
#pragma unroll
        for (int i = 0; i < 4; i++) {
            p[i][0] += __shfl_xor_sync(~0u, p[i][0], 1);
            p[i][0] += __shfl_xor_sync(~0u, p[i][0], 2);
            p[i][1] += __shfl_xor_sync(~0u, p[i][1], 1);
            p[i][1] += __shfl_xor_sync(~0u, p[i][1], 2);
            if (qd == 0) {
                const long r = m0 + wm * 64 + i * 16 + gr;
                atomicAdd(&C[r * S + z], p[i][0]);
                atomicAdd(&C[(r + 8) * S + z], p[i][1]);
            }
        }
    } else {
#pragma unroll
        for (int j = 0; j < 4; j++) {
            const long c = n0 + wn * 32 + j * 8 + qd * 2;
            float2 bv = make_float2(0.f, 0.f);
            if (BIAS) bv = *(const float2*)&bias[c];
#pragma unroll
            for (int i = 0; i < 4; i++) {
                const long r0 = m0 + wm * 64 + i * 16 + gr;
                float2 v0 = make_float2(acc[i][j][0] * scaleC + bv.x,
                                        acc[i][j][1] * scaleC + bv.y);
                float2 v1 = make_float2(acc[i][j][2] * scaleC + bv.x,
                                        acc[i][j][3] * scaleC + bv.y);
                if (HOUT) {
                    __half* Ch = (__half*)C;
                    *(__half2*)&Ch[r0 * ldc + c] = __floats2half2_rn(v0.x, v0.y);
                    *(__half2*)&Ch[(r0 + 8) * ldc + c] = __floats2half2_rn(v1.x, v1.y);
                } else {
                    *(float2*)&C[r0 * ldc + c] = v0;
                    *(float2*)&C[(r0 + 8) * ldc + c] = v1;
                }
            }
        }
    }
}

// =============================================================================
// conversion kernels
// =============================================================================
__device__ __forceinline__ void store_split4(float4 v, float s, __half* hi,
                                             __half* lo, long i4) {
    __half h0, h1, h2, h3, l0, l1, l2, l3;
    hsplit(v.x, s, h0, l0);
    hsplit(v.y, s, h1, l1);
    hsplit(v.z, s, h2, l2);
    hsplit(v.w, s, h3, l3);
    __half2 a, b;
    a.x = h0; a.y = h1; b.x = h2; b.y = h3;
    ((__half2*)hi)[2 * i4] = a; ((__half2*)hi)[2 * i4 + 1] = b;
    a.x = l0; a.y = l1; b.x = l2; b.y = l3;
    ((__half2*)lo)[2 * i4] = a; ((__half2*)lo)[2 * i4 + 1] = b;
}

__global__ void split4(const float* __restrict__ src, __half* __restrict__ hi,
                       __half* __restrict__ lo, long n4, float s)
{
    const long i = (long)blockIdx.x * 256 + threadIdx.x;
    if (i >= n4) return;
    store_split4(((const float4*)src)[i], s, hi, lo, i);
}

__global__ void split_hi(const float* __restrict__ src, __half* __restrict__ hi,
                         long n4)
{
    const long i = (long)blockIdx.x * 256 + threadIdx.x;
    if (i >= n4) return;
    float4 v = ((const float4*)src)[i];
    __half2 a, b;
    a.x = __float2half_rn(v.x); a.y = __float2half_rn(v.y);
    b.x = __float2half_rn(v.z); b.y = __float2half_rn(v.w);
    ((__half2*)hi)[2 * i] = a; ((__half2*)hi)[2 * i + 1] = b;
}

// 1024x1024 transpose + scaled split: dst[c][r] = src[r][c] * SWT
__global__ void tsplit(const float* __restrict__ src, __half* __restrict__ hi,
                       __half* __restrict__ lo)
{
    __shared__ float t[32][33];
    const int bx = blockIdx.x * 32, by = blockIdx.y * 32;
    const int tx = threadIdx.x;
    for (int j = threadIdx.y; j < 32; j += 8)
        t[j][tx] = src[(long)(by + j) * 1024 + bx + tx];
    __syncthreads();
    for (int j = threadIdx.y; j < 32; j += 8) {
        const long o = (long)(bx + j) * 1024 + by + tx;
        __half h, l;
        hsplit(t[tx][j], SWT, h, l);
        hi[o] = h; lo[o] = l;
    }
}

__global__ void avsplit()
{
    const long i = (long)blockIdx.x * 256 + threadIdx.x;
    const long n4 = (long)B * D / 4;
    float4 a = ((const float4*)g_av)[i];
    float4 v = ((const float4*)g_av)[n4 + i];
    float4 f = make_float4(0.5f * (a.x + v.x), 0.5f * (a.y + v.y),
                           0.5f * (a.z + v.z), 0.5f * (a.w + v.w));
    store_split4(f, 1.f, g_x_hi, g_x_lo, i);
    store_split4(a, 1.f, g_x_hi, g_x_lo, n4 + i);
    store_split4(v, 1.f, g_x_hi, g_x_lo, 2 * n4 + i);
}

__global__ void zero_d()
{
    g_d[blockIdx.x * 256 + threadIdx.x] = 0.f;
}

__global__ void pack_bias(const float* __restrict__ b0, const float* __restrict__ b1,
                          const float* __restrict__ b2)
{
    const int i = blockIdx.x * 256 + threadIdx.x;
    const int hh = i >> 9, j = i & 511;
    g_hbias[i] = hh == 0 ? b0[j] : (hh == 1 ? b1[j] : b2[j]);
}

// =============================================================================
// bias-derived vectors: one block per output element (parallel reduce)
// blocks 0..D-1 -> vq/vk/bcomb[i]; block D -> c0.
// =============================================================================
__global__ void __launch_bounds__(256) vec_pre(
    const float* __restrict__ in_proj_w, const float* __restrict__ in_proj_b,
    const float* __restrict__ out_w, const float* __restrict__ out_b)
{
    const float* wq = in_proj_w;
    const float* wk = in_proj_w + (long)D * D;
    const float* bq = in_proj_b;
    const float* bk = in_proj_b + D;
    const float* bv = in_proj_b + 2 * D;
    __shared__ float rs[3][8];
    const int t = threadIdx.x, w = t >> 5, lane = t & 31;
    const int i = blockIdx.x;
    float v0 = 0.f, v1 = 0.f, v2 = 0.f;
    if (i < D) {
        for (int e = t; e < D; e += 256) {
            v0 = fmaf(bq[e], wk[(long)e * D + i], v0);
            v1 = fmaf(bk[e], wq[(long)e * D + i], v1);
            v2 = fmaf(out_w[(long)i * D + e], bv[e], v2);
        }
    } else {
        for (int e = t; e < D; e += 256) v0 = fmaf(bq[e], bk[e], v0);
    }
#pragma unroll
    for (int o = 16; o > 0; o >>= 1) {
        v0 += __shfl_xor_sync(~0u, v0, o);
        v1 += __shfl_xor_sync(~0u, v1, o);
        v2 += __shfl_xor_sync(~0u, v2, o);
    }
    if (lane == 0) { rs[0][w] = v0; rs[1][w] = v1; rs[2][w] = v2; }
    __syncthreads();
    if (t == 0) {
        float s0 = 0.f, s1 = 0.f, s2 = 0.f;
#pragma unroll
        for (int j = 0; j < 8; j++) { s0 += rs[0][j]; s1 += rs[1][j]; s2 += rs[2][j]; }
        if (i < D) { g_vq[i] = s0; g_vk[i] = s1; g_bcomb[i] = s2 + out_b[i]; }
        else g_c0 = s0;
    }
}

// =============================================================================
// Per-batch attention: score phase fp16 (shared + DRAM), weighted sum fp32.
// pitch 132 halves (264B): 8B-aligned rows, 2-row t0 stride = 66 words.
// =============================================================================
constexpr int QP = 132;

__global__ void __launch_bounds__(256) attn_kernel(
    const float* __restrict__ q, const float* __restrict__ cls_b2,
    float* __restrict__ out)
{
    const int b = blockIdx.x;
    __shared__ __half qsh[32][QP];
    __shared__ __half qmsh[32][QP];
    __shared__ float sc[32][33];
    __shared__ float vks[128];
    __shared__ float dd[32], rk[32], wa[32], wvv[32], da[16], dv[16];

    const int tid = threadIdx.x;
    const int s0 = (tid >> 4) << 1;
    const int t0 = (tid & 15) << 1;
    const float* qb = q + (long)b * S * D;
    const __half* qbh = g_q_hi + (long)b * S * D;
    const __half* qmbh = g_qM_h + (long)b * S * D;

    if (tid < 32) dd[tid] = fmaxf(g_d[b * S + tid] + cls_b2[tid], 0.f);

    float racc[2][2] = {{0.f, 0.f}, {0.f, 0.f}};
    float rkacc = 0.f;

    for (int c = 0; c < D; c += 128) {
#pragma unroll
        for (int i = 0; i < 4; i++) {
            const int idx = tid + 256 * i;      // 0..1023
            const int r = idx >> 5;             // 0..31
            const int c4 = (idx & 31) << 2;     // 0..124
            *(uint2*)&qsh[r][c4] = *(const uint2*)&qbh[(long)r * D + c + c4];
            *(uint2*)&qmsh[r][c4] = *(const uint2*)&qmbh[(long)r * D + c + c4];
        }
        if (tid < 32) *(float4*)&vks[tid * 4] = *(const float4*)&g_vk[c + tid * 4];
        __syncthreads();

#pragma unroll 4
        for (int k = 0; k < 128; k++) {
            const float a0 = __half2float(qmsh[s0][k]);
            const float a1 = __half2float(qmsh[s0 + 1][k]);
            const float b0 = __half2float(qsh[t0][k]);
            const float b1 = __half2float(qsh[t0 + 1][k]);
            racc[0][0] = fmaf(a0, b0, racc[0][0]);
            racc[0][1] = fmaf(a0, b1, racc[0][1]);
            racc[1][0] = fmaf(a1, b0, racc[1][0]);
            racc[1][1] = fmaf(a1, b1, racc[1][1]);
        }
        if (tid < 32) {
            float r2 = 0.f;
#pragma unroll 4
            for (int k = 0; k < 128; k++)
                r2 = fmaf(__half2float(qsh[tid][k]), vks[k], r2);
            rkacc += r2;
        }
        __syncthreads();
    }

    sc[s0][t0] = racc[0][0];
    sc[s0][t0 + 1] = racc[0][1];
    sc[s0 + 1][t0] = racc[1][0];
    sc[s0 + 1][t0 + 1] = racc[1][1];
    if (tid < 32) rk[tid] = rkacc;
    __syncthreads();

    const int w = tid >> 5, lane = tid & 31;
    const float inv_sqrtD = 0.03125f;
    for (int rr = w * 4; rr < w * 4 + 4; rr++) {
        float v = (sc[rr][lane] + rk[rr] + g_c0) * inv_sqrtD;
        float mx = v;
#pragma unroll
        for (int o = 16; o > 0; o >>= 1) mx = fmaxf(mx, __shfl_xor_sync(~0u, mx, o));
        float e = __expf(v - mx);
        float sum = e;
#pragma unroll
        for (int o = 16; o > 0; o >>= 1) sum += __shfl_xor_sync(~0u, sum, o);
        sc[rr][lane] = e / sum;
    }
    __syncthreads();

    if (tid < 32) {
        const bool isA = tid < 16;
        const int i = tid & 15;
        float v = dd[tid];
        float mx = v;
#pragma unroll
        for (int o = 8; o > 0; o >>= 1) mx = fmaxf(mx, __shfl_xor_sync(~0u, mx, o));
        float e = __expf(v - mx);
        float sum = e;
#pragma unroll
        for (int o = 8; o > 0; o >>= 1) sum += __shfl_xor_sync(~0u, sum, o);
        const float p = e / sum;
        if (isA) da[i] = p; else dv[i] = p;
        const long bse = 3L * B * F;
        if (isA) out[bse + (long)b * P + i] = p;
        else     out[bse + (long)B * P + (long)b * P + i] = p;
    }
    __syncthreads();

    if (tid < 32) {
        float a = 0.f, v2 = 0.f;
#pragma unroll
        for (int ss = 0; ss < 16; ss++) a = fmaf(da[ss], sc[ss][tid], a);
#pragma unroll
        for (int ss = 0; ss < 16; ss++) v2 = fmaf(dv[ss], sc[16 + ss][tid], v2);
        wa[tid] = a;
        wvv[tid] = v2;
    }
    __syncthreads();

    // weighted sums over fp32 q (preserves qv precision)
#pragma unroll
    for (int i = 0; i < 4; i++) {
        const int col = tid + 256 * i;
        float a = 0.f, v2 = 0.f;
#pragma unroll
        for (int t = 0; t < 32; t++) {
            const float x = qb[(long)t * D + col];
            a = fmaf(wa[t], x, a);
            v2 = fmaf(wvv[t], x, v2);
        }
        const long ia = (long)b * D + col;
        const long iv = (long)B * D + ia;
        __half h, l;
        hsplit(a, 1.f, h, l);
        g_qv_hi[ia] = h; g_qv_lo[ia] = l;
        hsplit(v2, 1.f, h, l);
        g_qv_hi[iv] = h; g_qv_lo[iv] = l;
    }
}

__global__ void __launch_bounds__(128) ln_relu(
    const float* __restrict__ gm0, const float* __restrict__ be0,
    const float* __restrict__ gm1, const float* __restrict__ be1,
    const float* __restrict__ gm2, const float* __restrict__ be2,
    float* __restrict__ out)
{
    const int head = blockIdx.y, b = blockIdx.x, tid = threadIdx.x;
    const float* gm = head == 0 ? gm0 : (head == 1 ? gm1 : gm2);
    const float* be = head == 0 ? be0 : (head == 1 ? be1 : be2);
    const float* y = g_y + ((long)head * B + b) * F;

    float4 v = *(const float4*)&y[tid * 4];
    float s = v.x + v.y + v.z + v.w;
    float sq = v.x * v.x + v.y * v.y + v.z * v.z + v.w * v.w;
#pragma unroll
    for (int o = 16; o > 0; o >>= 1) {
        s += __shfl_xor_sync(~0u, s, o);
        sq += __shfl_xor_sync(~0u, sq, o);
    }
    __shared__ float ss[4], ssq[4];
    const int w = tid >> 5;
    if ((tid & 31) == 0) { ss[w] = s; ssq[w] = sq; }
    __syncthreads();
    s = ss[0] + ss[1] + ss[2] + ss[3];
    sq = ssq[0] + ssq[1] + ssq[2] + ssq[3];
    const float mean = s * (1.f / F);
    const float var = sq * (1.f / F) - mean * mean;
    const float rstd = rsqrtf(var + 1e-5f);

    float4 g4 = *(const float4*)&gm[tid * 4];
    float4 b4 = *(const float4*)&be[tid * 4];
    float4 o4;
    o4.x = fmaxf((v.x - mean) * rstd * g4.x + b4.x, 0.f);
    o4.y = fmaxf((v.y - mean) * rstd * g4.y + b4.y, 0.f);
    o4.z = fmaxf((v.z - mean) * rstd * g4.z + b4.z, 0.f);
    o4.w = fmaxf((v.w - mean) * rstd * g4.w + b4.w, 0.f);
    *(float4*)&out[((long)head * B + b) * F + tid * 4] = o4;
}

}  // namespace raff

// =============================================================================
// Launch
// =============================================================================
extern "C" void kernel_launch(void* const* d_in, const int* in_sizes, int n_in,
                              void* d_out, int out_size)
{
    using namespace raff;
    (void)in_sizes; (void)n_in; (void)out_size;

    const float* q         = (const float*)d_in[0];
    const float* in_proj_w = (const float*)d_in[1];
    const float* in_proj_b = (const float*)d_in[2];
    const float* out_w     = (const float*)d_in[3];
    const float* out_b     = (const float*)d_in[4];
    const float* cls_w1    = (const float*)d_in[5];
    const float* cls_b1    = (const float*)d_in[6];
    const float* cls_w2    = (const float*)d_in[7];
    const float* cls_b2    = (const float*)d_in[8];
    const float* fus_w     = (const float*)d_in[9];
    const float* fus_b     = (const float*)d_in[10];
    const float* fus_g     = (const float*)d_in[11];
    const float* fus_be    = (const float*)d_in[12];
    const float* pa_w      = (const float*)d_in[13];
    const float* pa_b      = (const float*)d_in[14];
    const float* pa_g      = (const float*)d_in[15];
    const float* pa_be     = (const float*)d_in[16];
    const float* pv_w      = (const float*)d_in[17];
    const float* pv_b      = (const float*)d_in[18];
    const float* pv_g      = (const float*)d_in[19];
    const float* pv_be     = (const float*)d_in[20];
    float* out = (float*)d_out;

    float *pMC, *pd, *pav, *py, *pvq, *pbcomb, *phb;
    __half *pqMh, *qhi, *w1hi, *uhi, *ulo, *vhi, *vlo,
        *mchi, *mclo, *qvhi, *qvlo, *xhi, *xlo, *hwhi, *hwlo;
    cudaGetSymbolAddress((void**)&pMC, g_MC);
    cudaGetSymbolAddress((void**)&pqMh, g_qM_h);
    cudaGetSymbolAddress((void**)&pd, g_d);
    cudaGetSymbolAddress((void**)&pav, g_av);
    cudaGetSymbolAddress((void**)&py, g_y);
    cudaGetSymbolAddress((void**)&pvq, g_vq);
    cudaGetSymbolAddress((void**)&pbcomb, g_bcomb);
    cudaGetSymbolAddress((void**)&phb, g_hbias);
    cudaGetSymbolAddress((void**)&qhi, g_q_hi);
    cudaGetSymbolAddress((void**)&w1hi, g_w1_hi);
    cudaGetSymbolAddress((void**)&uhi, g_u_hi);
    cudaGetSymbolAddress((void**)&ulo, g_u_lo);
    cudaGetSymbolAddress((void**)&vhi, g_v_hi);
    cudaGetSymbolAddress((void**)&vlo, g_v_lo);
    cudaGetSymbolAddress((void**)&mchi, g_mc_hi);
    cudaGetSymbolAddress((void**)&mclo, g_mc_lo);
    cudaGetSymbolAddress((void**)&qvhi, g_qv_hi);
    cudaGetSymbolAddress((void**)&qvlo, g_qv_lo);
    cudaGetSymbolAddress((void**)&xhi, g_x_hi);
    cudaGetSymbolAddress((void**)&xlo, g_x_lo);
    cudaGetSymbolAddress((void**)&hwhi, g_hw_hi);
    cudaGetSymbolAddress((void**)&hwlo, g_hw_lo);

    cudaFuncSetAttribute((const void*)bsgemm<3, false, false, false>,
                         cudaFuncAttributeMaxDynamicSharedMemorySize, GEMM_SMEM);
    cudaFuncSetAttribute((const void*)bsgemm<3, true, false, false>,
                         cudaFuncAttributeMaxDynamicSharedMemorySize, GEMM_SMEM);
    cudaFuncSetAttribute((const void*)bsgemm<1, true, false, true>,
                         cudaFuncAttributeMaxDynamicSharedMemorySize, GEMM_SMEM);
    cudaFuncSetAttribute((const void*)bsgemm<1, false, true, false>,
                         cudaFuncAttributeMaxDynamicSharedMemorySize, GEMM_SMEM);

    // 1) tiny precomputations
    vec_pre<<<D + 1, 256>>>(in_proj_w, in_proj_b, out_w, out_b);
    pack_bias<<<6, 256>>>(fus_b, pa_b, pv_b);
    zero_d<<<B * S / 256, 256>>>();

    // 2) conversions of inputs
    split_hi<<<(int)(NQ / 4 / 256), 256>>>(q, qhi, NQ / 4);
    split_hi<<<(int)((long)S * H * D / 4 / 256), 256>>>(cls_w1, w1hi,
                                                        (long)S * H * D / 4);
    split4<<<D * D / 4 / 256, 256>>>(out_w, uhi + (long)D * D, ulo + (long)D * D,
                                     D * D / 4, SWT);
    split4<<<F * D / 4 / 256, 256>>>(fus_w, hwhi, hwlo, (long)F * D / 4, SWT);
    split4<<<F * D / 4 / 256, 256>>>(pa_w, hwhi + (long)F * D, hwlo + (long)F * D,
                                     (long)F * D / 4, SWT);
    split4<<<F * D / 4 / 256, 256>>>(pv_w, hwhi + 2L * F * D, hwlo + 2L * F * D,
                                     (long)F * D / 4, SWT);
    tsplit<<<dim3(32, 32), dim3(32, 8)>>>(in_proj_w + (long)D * D, uhi, ulo);    // WkT
    tsplit<<<dim3(32, 32), dim3(32, 8)>>>(in_proj_w, vhi, vlo);                  // WqT
    tsplit<<<dim3(32, 32), dim3(32, 8)>>>(in_proj_w + 2L * D * D,
                                          vhi + (long)D * D, vlo + (long)D * D); // WvT

    // 3) [Mt; Cov] one z=2 launch (3-term), then split (x32)
    bsgemm<3, false, false, false><<<dim3(8, 8, 2), 256, GEMM_SMEM>>>(
        uhi, ulo, D, (long)D * D, vhi, vlo, (long)D * D,
        pMC, D, (long)D * D, nullptr, 0L, nullptr, SC_WW);
    split4<<<2 * D * D / 4 / 256, 256>>>(pMC, mchi, mclo, 2 * D * D / 4, SWT);

    // 4) qM = q * Mt^T + vq  (1-term, fp16 output)
    bsgemm<1, true, false, true><<<dim3(8, 512), 256, GEMM_SMEM>>>(
        qhi, nullptr, (long)D, 0L, mchi, nullptr, 0L, (float*)pqMh, D, 0L,
        pvq, 0L, nullptr, SC_QW);

    // 5) classifier: h = relu(q w1^T + b1), d += h.w2 (1-term, atomic)
    bsgemm<1, false, true, false><<<dim3(4, 16, 32), 256, GEMM_SMEM>>>(
        qhi, nullptr, (long)S * D, (long)D, w1hi, nullptr, (long)H * D,
        pd, S, 0L, cls_b1, (long)H, cls_w2, 1.f);

    // 6) attention + softmaxes + weighted q sums -> qv hi/lo
    attn_kernel<<<B, 256>>>(q, cls_b2, out);

    // 7) [audio; video] = qv * Cov^T + bcomb  (3-term)
    bsgemm<3, true, false, false><<<dim3(8, 32), 256, GEMM_SMEM>>>(
        qvhi, qvlo, (long)D, 0L, mchi + (long)D * D, mclo + (long)D * D, 0L,
        pav, D, 0L, pbcomb, 0L, nullptr, SC_QW);

    // 8) fusion + splits of head inputs
    avsplit<<<(int)((long)B * D / 4 / 256), 256>>>();

    // 9) heads: one z=3 launch  y = x * W^T + b  (3-term)
    bsgemm<3, true, false, false><<<dim3(4, 16, 3), 256, GEMM_SMEM>>>(
        xhi, xlo, (long)D, (long)B * D, hwhi, hwlo, (long)F * D,
        py, F, (long)B * F, phb, (long)F, nullptr, SC_QW);

    // 10) LayerNorm + ReLU -> final outputs
    ln_relu<<<dim3(B, 3), 128>>>(fus_g, fus_be, pa_g, pa_be, pv_g, pv_be, out);
}

// round 13
// speedup vs baseline: 6.3739x; 1.1115x over previous
#include <cuda_runtime.h>
#include <cuda_fp16.h>
#include <cstdint>

// =============================================================================
// RAFF_8555574853896 — round 13: attn scores on HMMA (per-batch fp16 tiles,
// 8-warp K-split + shared reduce); av/heads GEMMs 2-term (qv/x hi-only).
// qM 1-term fp16-out, cls 1-term, Mt/Cov 3-term.
//
// Algebra (validated):
//   scores = q Mt^T q^T / sqrt(D) + rank-1 bias,  Mt = (Wq^T Wk)^T
//   audio  = (w_a^T q) Cov^T + bcomb,             Cov = out_w Wv
// =============================================================================

namespace raff {

constexpr int B = 2048, S = 32, P = 16, D = 1024, H = 512, F = 512;
constexpr long NQ = (long)B * S * D;

constexpr float SWT = 32.f;
constexpr float SC_QW = 1.f / SWT;
constexpr float SC_WW = 1.f / (SWT * SWT);

// ---------------- static device scratch ----------------
__device__ float g_vq[D], g_vk[D], g_bcomb[D];
__device__ float g_c0;
__device__ float g_MC[2 * D * D];              // [Mt; Cov] fp32
__device__ float g_d[B * S];
__device__ float g_av[2L * B * D];
__device__ float g_y[3L * B * F];
__device__ float g_hbias[3 * F];

__device__ __half g_qM_h[NQ];                  // qM fp16 (128 MB)
__device__ __half g_q_hi[NQ];
__device__ __half g_w1_hi[(long)S * H * D];
__device__ __half g_u_hi[2 * D * D], g_u_lo[2 * D * D];    // [WkT; out_w] x32
__device__ __half g_v_hi[2 * D * D], g_v_lo[2 * D * D];    // [WqT; WvT] x32
__device__ __half g_mc_hi[2 * D * D], g_mc_lo[2 * D * D];  // [Mt; Cov] x32
__device__ __half g_qv_hi[2L * B * D];
__device__ __half g_x_hi[3L * B * D];
__device__ __half g_hw_hi[3L * F * D], g_hw_lo[3L * F * D];

// ---------------- PTX helpers (base sm_103-legal) ----------------
__device__ __forceinline__ uint32_t smem_u32(const void* p) {
    uint32_t a;
    asm("{ .reg .u64 t; cvta.to.shared.u64 t, %1; cvt.u32.u64 %0, t; }"
        : "=r"(a) : "l"(p));
    return a;
}
#define CP16(dst, src) \
    asm volatile("cp.async.cg.shared.global [%0], [%1], 16;" :: "r"(dst), "l"(src))
#define CP_COMMIT() asm volatile("cp.async.commit_group;" ::: "memory")

__device__ __forceinline__ void ldsm_x4(uint32_t* r, uint32_t addr) {
    asm volatile("ldmatrix.sync.aligned.m8n8.x4.shared.b16 {%0,%1,%2,%3}, [%4];"
                 : "=r"(r[0]), "=r"(r[1]), "=r"(r[2]), "=r"(r[3]) : "r"(addr));
}
__device__ __forceinline__ void ldsm_x2(uint32_t* r, uint32_t addr) {
    asm volatile("ldmatrix.sync.aligned.m8n8.x2.shared.b16 {%0,%1}, [%2];"
                 : "=r"(r[0]), "=r"(r[1]) : "r"(addr));
}
__device__ __forceinline__ void mma_f16(float* c, const uint32_t* a, const uint32_t* b) {
    asm volatile(
        "mma.sync.aligned.m16n8k16.row.col.f32.f16.f16.f32 "
        "{%0,%1,%2,%3}, {%4,%5,%6,%7}, {%8,%9}, {%0,%1,%2,%3};"
        : "+f"(c[0]), "+f"(c[1]), "+f"(c[2]), "+f"(c[3])
        : "r"(a[0]), "r"(a[1]), "r"(a[2]), "r"(a[3]), "r"(b[0]), "r"(b[1]));
}

// Swizzled address within a 32x32-half chunk (rows of 64B, 4x16B, XOR).
__device__ __forceinline__ uint32_t swz(int r, int c) {
    return (uint32_t)((r * 4 + (c ^ ((r >> 1) & 3))) * 16);
}

__device__ __forceinline__ void hsplit(float x, float s, __half& hi, __half& lo) {
    const float xs = x * s;
    hi = __float2half_rn(xs);
    lo = __float2half_rn(xs - __half2float(hi));
}

// =============================================================================
// fp16 split GEMM (unchanged geometry): block 128x128, warp 64x32, 3-stage.
// TERMS: 1 = ah*bh; 2 = + ah*bl; 3 = + al*bh.
// =============================================================================
constexpr int STAGE = 32768;
constexpr int NSTG = 3;
constexpr int GEMM_SMEM = NSTG * STAGE;

template <int TERMS, bool BIAS, bool CLSD, bool HOUT>
__global__ void __launch_bounds__(256, 2) bsgemm(
    const __half* __restrict__ Ahi, const __half* __restrict__ Alo,
    long lda, long aOffZ,
    const __half* __restrict__ Bhi, const __half* __restrict__ Blo,
    long bOffZ,
    float* __restrict__ C, int ldc, long cOffZ,
    const float* __restrict__ bias, long biasOffZ,
    const float* __restrict__ w2p, float scaleC)
{
    extern __shared__ char dsm[];
    const uint32_t base = smem_u32(dsm);

    const int tid = threadIdx.x, lane = tid & 31, w = tid >> 5;
    const int wm = w & 1, wn = w >> 1;
    const int z = blockIdx.z;
    const long m0 = (long)blockIdx.y * 128;
    const long n0 = (long)blockIdx.x * 128;
    Ahi += z * aOffZ;
    if (TERMS >= 3) Alo += z * aOffZ;
    Bhi += z * bOffZ;
    if (TERMS >= 2) Blo += z * bOffZ;
    C += z * cOffZ;
    if (BIAS || CLSD) bias += z * biasOffZ;

    float acc[4][4][4];
#pragma unroll
    for (int i = 0; i < 4; i++)
#pragma unroll
        for (int j = 0; j < 4; j++)
#pragma unroll
            for (int k = 0; k < 4; k++) acc[i][j][k] = 0.f;

    auto loadChunk = [&](int s, int kc) {
        const long k0 = (long)kc * 32;
        const uint32_t ah = base + s * STAGE;
        const uint32_t al = ah + 8192;
        const uint32_t bh = ah + 16384;
        const uint32_t bl = ah + 24576;
#pragma unroll
        for (int i = 0; i < 2; i++) {
            const int idx = tid + 256 * i;
            const int r = idx >> 2, c = idx & 3;
            const uint32_t dst = swz(r, c);
            const long offA = (m0 + r) * lda + k0 + c * 8;
            CP16(ah + dst, Ahi + offA);
            if (TERMS >= 3) CP16(al + dst, Alo + offA);
            const long offB = (n0 + r) * 1024 + k0 + c * 8;
            CP16(bh + dst, Bhi + offB);
            if (TERMS >= 2) CP16(bl + dst, Blo + offB);
        }
        CP_COMMIT();
    };

    auto computeChunk = [&](int s) {
        const uint32_t ah = base + s * STAGE;
        const uint32_t al = ah + 8192;
        const uint32_t bh = ah + 16384;
        const uint32_t bl = ah + 24576;
#pragma unroll
        for (int ks = 0; ks < 2; ks++) {
            uint32_t afh[4][4], afl[4][4], bf[4][2];
            const int arow = wm * 64 + (lane & 15);
            const int akc = ks * 2 + (lane >> 4);
#pragma unroll
            for (int i = 0; i < 4; i++) {
                const uint32_t off = swz(arow + i * 16, akc);
                ldsm_x4(afh[i], ah + off);
                if (TERMS >= 3) ldsm_x4(afl[i], al + off);
            }
            const int brow = wn * 32 + (lane & 7);
            const int bkc = ks * 2 + ((lane >> 3) & 1);
#pragma unroll
            for (int j = 0; j < 4; j++)
                ldsm_x2(bf[j], bh + swz(brow + j * 8, bkc));
#pragma unroll
            for (int i = 0; i < 4; i++)
#pragma unroll
                for (int j = 0; j < 4; j++) mma_f16(acc[i][j], afh[i], bf[j]);
            if (TERMS >= 3) {
#pragma unroll
                for (int i = 0; i < 4; i++)
#pragma unroll
                    for (int j = 0; j < 4; j++) mma_f16(acc[i][j], afl[i], bf[j]);
            }
            if (TERMS >= 2) {
#pragma unroll
                for (int j = 0; j < 4; j++)
                    ldsm_x2(bf[j], bl + swz(brow + j * 8, bkc));
#pragma unroll
                for (int i = 0; i < 4; i++)
#pragma unroll
                    for (int j = 0; j < 4; j++) mma_f16(acc[i][j], afh[i], bf[j]);
            }
        }
    };

    loadChunk(0, 0);
    loadChunk(1, 1);

    for (int ch = 0; ch < 32; ch++) {
        asm volatile("cp.async.wait_group 1;" ::: "memory");
        __syncthreads();
        if (ch + 2 < 32) loadChunk((ch + 2) % 3, ch + 2);
        else CP_COMMIT();
        computeChunk(ch % 3);
    }

    const int gr = lane >> 2, qd = lane & 3;

    if (CLSD) {
        float p[4][2];
#pragma unroll
        for (int i = 0; i < 4; i++) { p[i][0] = 0.f; p[i][1] = 0.f; }
        const float* w2 = w2p + (long)z * H;
#pragma unroll
        for (int j = 0; j < 4; j++) {
            const long c = n0 + wn * 32 + j * 8 + qd * 2;
            const float2 w2v = *(const float2*)&w2[c];
            const float2 bv = *(const float2*)&bias[c];
#pragma unroll
            for (int i = 0; i < 4; i++) {
                const float h0 = fmaxf(acc[i][j][0] * scaleC + bv.x, 0.f);
                const float h1 = fmaxf(acc[i][j][1] * scaleC + bv.y, 0.f);
                p[i][0] += h0 * w2v.x + h1 * w2v.y;
                const float h2 = fmaxf(acc[i][j][2] * scaleC + bv.x, 0.f);
                const float h3 = fmaxf(acc[i][j][3] * scaleC + bv.y, 0.f);
                p[i][1] += h2 * w2v.x + h3 * w2v.y;
            }
        }
#pragma unroll
        for (int i = 0; i < 4; i++) {
            p[i][0] += __shfl_xor_sync(~0u, p[i][0], 1);
            p[i][0] += __shfl_xor_sync(~0u, p[i][0], 2);
            p[i][1] += __shfl_xor_sync(~0u, p[i][1], 1);
            p[i][1] += __shfl_xor_sync(~0u, p[i][1], 2);
            if (qd == 0) {
                const long r = m0 + wm * 64 + i * 16 + gr;
                atomicAdd(&C[r * S + z], p[i][0]);
                atomicAdd(&C[(r + 8) * S + z], p[i][1]);
            }
        }
    } else {
#pragma unroll
        for (int j = 0; j < 4; j++) {
            const long c = n0 + wn * 32 + j * 8 + qd * 2;
            float2 bv = make_float2(0.f, 0.f);
            if (BIAS) bv = *(const float2*)&bias[c];
#pragma unroll
            for (int i = 0; i < 4; i++) {
                const long r0 = m0 + wm * 64 + i * 16 + gr;
                float2 v0 = make_float2(acc[i][j][0] * scaleC + bv.x,
                                        acc[i][j][1] * scaleC + bv.y);
                float2 v1 = make_float2(acc[i][j][2] * scaleC + bv.x,
                                        acc[i][j][3] * scaleC + bv.y);
                if (HOUT) {
                    __half* Ch = (__half*)C;
                    *(__half2*)&Ch[r0 * ldc + c] = __floats2half2_rn(v0.x, v0.y);
                    *(__half2*)&Ch[(r0 + 8) * ldc + c] = __floats2half2_rn(v1.x, v1.y);
                } else {
                    *(float2*)&C[r0 * ldc + c] = v0;
                    *(float2*)&C[(r0 + 8) * ldc + c] = v1;
                }
            }
        }
    }
}

// =============================================================================
// conversion kernels
// =============================================================================
__global__ void split4(const float* __restrict__ src, __half* __restrict__ hi,
                       __half* __restrict__ lo, long n4, float s)
{
    const long i = (long)blockIdx.x * 256 + threadIdx.x;
    if (i >= n4) return;
    float4 v = ((const float4*)src)[i];
    __half h0, h1, h2, h3, l0, l1, l2, l3;
    hsplit(v.x, s, h0, l0);
    hsplit(v.y, s, h1, l1);
    hsplit(v.z, s, h2, l2);
    hsplit(v.w, s, h3, l3);
    __half2 a, b;
    a.x = h0; a.y = h1; b.x = h2; b.y = h3;
    ((__half2*)hi)[2 * i] = a; ((__half2*)hi)[2 * i + 1] = b;
    a.x = l0; a.y = l1; b.x = l2; b.y = l3;
    ((__half2*)lo)[2 * i] = a; ((__half2*)lo)[2 * i + 1] = b;
}

__global__ void split_hi(const float* __restrict__ src, __half* __restrict__ hi,
                         long n4)
{
    const long i = (long)blockIdx.x * 256 + threadIdx.x;
    if (i >= n4) return;
    float4 v = ((const float4*)src)[i];
    __half2 a, b;
    a.x = __float2half_rn(v.x); a.y = __float2half_rn(v.y);
    b.x = __float2half_rn(v.z); b.y = __float2half_rn(v.w);
    ((__half2*)hi)[2 * i] = a; ((__half2*)hi)[2 * i + 1] = b;
}

__global__ void tsplit(const float* __restrict__ src, __half* __restrict__ hi,
                       __half* __restrict__ lo)
{
    __shared__ float t[32][33];
    const int bx = blockIdx.x * 32, by = blockIdx.y * 32;
    const int tx = threadIdx.x;
    for (int j = threadIdx.y; j < 32; j += 8)
        t[j][tx] = src[(long)(by + j) * 1024 + bx + tx];
    __syncthreads();
    for (int j = threadIdx.y; j < 32; j += 8) {
        const long o = (long)(bx + j) * 1024 + by + tx;
        __half h, l;
        hsplit(t[tx][j], SWT, h, l);
        hi[o] = h; lo[o] = l;
    }
}

// fusion = 0.5*(audio+video); convert fusion/audio/video -> x_hi (hi only)
__global__ void avhi()
{
    const long i = (long)blockIdx.x * 256 + threadIdx.x;
    const long n4 = (long)B * D / 4;
    float4 a = ((const float4*)g_av)[i];
    float4 v = ((const float4*)g_av)[n4 + i];
    __half2 p0, p1;
    p0 = __floats2half2_rn(0.5f * (a.x + v.x), 0.5f * (a.y + v.y));
    p1 = __floats2half2_rn(0.5f * (a.z + v.z), 0.5f * (a.w + v.w));
    ((__half2*)g_x_hi)[2 * i] = p0; ((__half2*)g_x_hi)[2 * i + 1] = p1;
    p0 = __floats2half2_rn(a.x, a.y); p1 = __floats2half2_rn(a.z, a.w);
    ((__half2*)g_x_hi)[2 * (n4 + i)] = p0; ((__half2*)g_x_hi)[2 * (n4 + i) + 1] = p1;
    p0 = __floats2half2_rn(v.x, v.y); p1 = __floats2half2_rn(v.z, v.w);
    ((__half2*)g_x_hi)[2 * (2 * n4 + i)] = p0;
    ((__half2*)g_x_hi)[2 * (2 * n4 + i) + 1] = p1;
}

__global__ void zero_d()
{
    g_d[blockIdx.x * 256 + threadIdx.x] = 0.f;
}

__global__ void pack_bias(const float* __restrict__ b0, const float* __restrict__ b1,
                          const float* __restrict__ b2)
{
    const int i = blockIdx.x * 256 + threadIdx.x;
    const int hh = i >> 9, j = i & 511;
    g_hbias[i] = hh == 0 ? b0[j] : (hh == 1 ? b1[j] : b2[j]);
}

// =============================================================================
// bias-derived vectors: one block per output element
// =============================================================================
__global__ void __launch_bounds__(256) vec_pre(
    const float* __restrict__ in_proj_w, const float* __restrict__ in_proj_b,
    const float* __restrict__ out_w, const float* __restrict__ out_b)
{
    const float* wq = in_proj_w;
    const float* wk = in_proj_w + (long)D * D;
    const float* bq = in_proj_b;
    const float* bk = in_proj_b + D;
    const float* bv = in_proj_b + 2 * D;
    __shared__ float rs[3][8];
    const int t = threadIdx.x, w = t >> 5, lane = t & 31;
    const int i = blockIdx.x;
    float v0 = 0.f, v1 = 0.f, v2 = 0.f;
    if (i < D) {
        for (int e = t; e < D; e += 256) {
            v0 = fmaf(bq[e], wk[(long)e * D + i], v0);
            v1 = fmaf(bk[e], wq[(long)e * D + i], v1);
            v2 = fmaf(out_w[(long)i * D + e], bv[e], v2);
        }
    } else {
        for (int e = t; e < D; e += 256) v0 = fmaf(bq[e], bk[e], v0);
    }
#pragma unroll
    for (int o = 16; o > 0; o >>= 1) {
        v0 += __shfl_xor_sync(~0u, v0, o);
        v1 += __shfl_xor_sync(~0u, v1, o);
        v2 += __shfl_xor_sync(~0u, v2, o);
    }
    if (lane == 0) { rs[0][w] = v0; rs[1][w] = v1; rs[2][w] = v2; }
    __syncthreads();
    if (t == 0) {
        float s0 = 0.f, s1 = 0.f, s2 = 0.f;
#pragma unroll
        for (int j = 0; j < 8; j++) { s0 += rs[0][j]; s1 += rs[1][j]; s2 += rs[2][j]; }
        if (i < D) { g_vq[i] = s0; g_vk[i] = s1; g_bcomb[i] = s2 + out_b[i]; }
        else g_c0 = s0;
    }
}

// =============================================================================
// Per-batch attention — scores on HMMA.
// Dynamic smem: q tile (64K, swizzled) | qM tile (64K) | partials (33.8K)
// =============================================================================
constexpr int ATTN_SMEM = 65536 + 65536 + 8 * 32 * 33 * 4;   // 164864

__global__ void __launch_bounds__(256) attn_kernel(
    const float* __restrict__ cls_b2, float* __restrict__ out)
{
    extern __shared__ char dsm[];
    const uint32_t sbase = smem_u32(dsm);
    const uint32_t QOFF = 0, QMOFF = 65536, POFF = 131072;
    float* part = (float*)(dsm + POFF);

    __shared__ float sc[32][33];
    __shared__ float vks[1024];
    __shared__ float dd[32], rk[32], wa[32], wvv[32], da[16], dv[16];

    const int b = blockIdx.x;
    const int tid = threadIdx.x, w = tid >> 5, lane = tid & 31;
    const __half* qbh = g_q_hi + (long)b * S * D;
    const __half* qmbh = g_qM_h + (long)b * S * D;

    // ---- load both tiles (swizzled 32x32-half chunks) via cp.async ----
#pragma unroll
    for (int i = 0; i < 16; i++) {
        const int u = tid + 256 * i;          // 0..4095 16B-units per matrix
        const int r = (u >> 7);               // row 0..31
        const int uu = u & 127;               // unit within row
        const int kc = uu >> 2, c = uu & 3;
        const long src = (long)r * D + uu * 8;
        CP16(sbase + QOFF + kc * 2048 + swz(r, c), qbh + src);
        CP16(sbase + QMOFF + kc * 2048 + swz(r, c), qmbh + src);
    }
    CP_COMMIT();
#pragma unroll
    for (int i = 0; i < 4; i++) vks[tid + 256 * i] = g_vk[tid + 256 * i];
    if (tid < 32) dd[tid] = fmaxf(g_d[b * S + tid] + cls_b2[tid], 0.f);
    asm volatile("cp.async.wait_group 0;" ::: "memory");
    __syncthreads();

    // ---- scores via MMA: warp w covers K-chunks 4w..4w+3 ----
    {
        float acc[2][4][4];
#pragma unroll
        for (int i = 0; i < 2; i++)
#pragma unroll
            for (int j = 0; j < 4; j++)
#pragma unroll
                for (int k = 0; k < 4; k++) acc[i][j][k] = 0.f;
#pragma unroll
        for (int cc = 0; cc < 4; cc++) {
            const uint32_t qc = sbase + QOFF + (4 * w + cc) * 2048;
            const uint32_t qmc = sbase + QMOFF + (4 * w + cc) * 2048;
#pragma unroll
            for (int ks = 0; ks < 2; ks++) {
                uint32_t af[2][4], bf[4][2];
                const int arow = lane & 15;
                const int akc = ks * 2 + (lane >> 4);
#pragma unroll
                for (int i = 0; i < 2; i++)
                    ldsm_x4(af[i], qmc + swz(i * 16 + arow, akc));
                const int brow = lane & 7;
                const int bkc = ks * 2 + ((lane >> 3) & 1);
#pragma unroll
                for (int j = 0; j < 4; j++)
                    ldsm_x2(bf[j], qc + swz(j * 8 + brow, bkc));
#pragma unroll
                for (int i = 0; i < 2; i++)
#pragma unroll
                    for (int j = 0; j < 4; j++) mma_f16(acc[i][j], af[i], bf[j]);
            }
        }
        // store partials
        float* pw = part + w * 1056;
        const int gr = lane >> 2, qd = lane & 3;
#pragma unroll
        for (int i = 0; i < 2; i++)
#pragma unroll
            for (int j = 0; j < 4; j++) {
                const int r = i * 16 + gr, c = j * 8 + qd * 2;
                pw[r * 33 + c] = acc[i][j][0];
                pw[r * 33 + c + 1] = acc[i][j][1];
                pw[(r + 8) * 33 + c] = acc[i][j][2];
                pw[(r + 8) * 33 + c + 1] = acc[i][j][3];
            }
    }
    __syncthreads();

    // ---- reduce partials -> sc; rk = q . vk (8 threads/row, 128 k each) ----
#pragma unroll
    for (int i = 0; i < 4; i++) {
        const int e = tid + 256 * i;
        const int r = e >> 5, c = e & 31;
        float s = 0.f;
#pragma unroll
        for (int ww = 0; ww < 8; ww++) s += part[ww * 1056 + r * 33 + c];
        sc[r][c] = s;
    }
    {
        const int row = tid >> 3, seg = tid & 7;
        float r2 = 0.f;
        for (int j = 0; j < 128; j++) {
            const int k = seg * 128 + j;
            const uint32_t off = QOFF + (k >> 5) * 2048 + swz(row, (k >> 3) & 3) + (k & 7) * 2;
            r2 = fmaf(__half2float(*(const __half*)(dsm + off)), vks[k], r2);
        }
        r2 += __shfl_xor_sync(~0u, r2, 1);
        r2 += __shfl_xor_sync(~0u, r2, 2);
        r2 += __shfl_xor_sync(~0u, r2, 4);
        if (seg == 0) rk[row] = r2;
    }
    __syncthreads();

    // ---- row softmax ----
    const float inv_sqrtD = 0.03125f;
    for (int rr = w * 4; rr < w * 4 + 4; rr++) {
        float v = (sc[rr][lane] + rk[rr] + g_c0) * inv_sqrtD;
        float mx = v;
#pragma unroll
        for (int o = 16; o > 0; o >>= 1) mx = fmaxf(mx, __shfl_xor_sync(~0u, mx, o));
        float e = __expf(v - mx);
        float sum = e;
#pragma unroll
        for (int o = 16; o > 0; o >>= 1) sum += __shfl_xor_sync(~0u, sum, o);
        sc[rr][lane] = e / sum;
    }
    __syncthreads();

    // ---- d softmaxes ----
    if (tid < 32) {
        const bool isA = tid < 16;
        const int i = tid & 15;
        float v = dd[tid];
        float mx = v;
#pragma unroll
        for (int o = 8; o > 0; o >>= 1) mx = fmaxf(mx, __shfl_xor_sync(~0u, mx, o));
        float e = __expf(v - mx);
        float sum = e;
#pragma unroll
        for (int o = 8; o > 0; o >>= 1) sum += __shfl_xor_sync(~0u, sum, o);
        const float p = e / sum;
        if (isA) da[i] = p; else dv[i] = p;
        const long bse = 3L * B * F;
        if (isA) out[bse + (long)b * P + i] = p;
        else     out[bse + (long)B * P + (long)b * P + i] = p;
    }
    __syncthreads();

    if (tid < 32) {
        float a = 0.f, v2 = 0.f;
#pragma unroll
        for (int ss = 0; ss < 16; ss++) a = fmaf(da[ss], sc[ss][tid], a);
#pragma unroll
        for (int ss = 0; ss < 16; ss++) v2 = fmaf(dv[ss], sc[16 + ss][tid], v2);
        wa[tid] = a;
        wvv[tid] = v2;
    }
    __syncthreads();

    // ---- weighted sums over fp16 q tile -> qv hi ----
#pragma unroll
    for (int i = 0; i < 4; i++) {
        const int col = tid + 256 * i;
        const uint32_t cb = QOFF + (col >> 5) * 2048;
        const int cc4 = (col >> 3) & 3;
        const int co = (col & 7) * 2;
        float a = 0.f, v2 = 0.f;
#pragma unroll
        for (int t = 0; t < 32; t++) {
            const float x = __half2float(*(const __half*)(dsm + cb + swz(t, cc4) + co));
            a = fmaf(wa[t], x, a);
            v2 = fmaf(wvv[t], x, v2);
        }
        const long ia = (long)b * D + col;
        g_qv_hi[ia] = __float2half_rn(a);
        g_qv_hi[(long)B * D + ia] = __float2half_rn(v2);
    }
}

__global__ void __launch_bounds__(128) ln_relu(
    const float* __restrict__ gm0, const float* __restrict__ be0,
    const float* __restrict__ gm1, const float* __restrict__ be1,
    const float* __restrict__ gm2, const float* __restrict__ be2,
    float* __restrict__ out)
{
    const int head = blockIdx.y, b = blockIdx.x, tid = threadIdx.x;
    const float* gm = head == 0 ? gm0 : (head == 1 ? gm1 : gm2);
    const float* be = head == 0 ? be0 : (head == 1 ? be1 : be2);
    const float* y = g_y + ((long)head * B + b) * F;

    float4 v = *(const float4*)&y[tid * 4];
    float s = v.x + v.y + v.z + v.w;
    float sq = v.x * v.x + v.y * v.y + v.z * v.z + v.w * v.w;
#pragma unroll
    for (int o = 16; o > 0; o >>= 1) {
        s += __shfl_xor_sync(~0u, s, o);
        sq += __shfl_xor_sync(~0u, sq, o);
    }
    __shared__ float ss[4], ssq[4];
    const int w = tid >> 5;
    if ((tid & 31) == 0) { ss[w] = s; ssq[w] = sq; }
    __syncthreads();
    s = ss[0] + ss[1] + ss[2] + ss[3];
    sq = ssq[0] + ssq[1] + ssq[2] + ssq[3];
    const float mean = s * (1.f / F);
    const float var = sq * (1.f / F) - mean * mean;
    const float rstd = rsqrtf(var + 1e-5f);

    float4 g4 = *(const float4*)&gm[tid * 4];
    float4 b4 = *(const float4*)&be[tid * 4];
    float4 o4;
    o4.x = fmaxf((v.x - mean) * rstd * g4.x + b4.x, 0.f);
    o4.y = fmaxf((v.y - mean) * rstd * g4.y + b4.y, 0.f);
    o4.z = fmaxf((v.z - mean) * rstd * g4.z + b4.z, 0.f);
    o4.w = fmaxf((v.w - mean) * rstd * g4.w + b4.w, 0.f);
    *(float4*)&out[((long)head * B + b) * F + tid * 4] = o4;
}

}  // namespace raff

// =============================================================================
// Launch
// =============================================================================
extern "C" void kernel_launch(void* const* d_in, const int* in_sizes, int n_in,
                              void* d_out, int out_size)
{
    using namespace raff;
    (void)in_sizes; (void)n_in; (void)out_size;

    const float* q         = (const float*)d_in[0];
    const float* in_proj_w = (const float*)d_in[1];
    const float* in_proj_b = (const float*)d_in[2];
    const float* out_w     = (const float*)d_in[3];
    const float* out_b     = (const float*)d_in[4];
    const float* cls_w1    = (const float*)d_in[5];
    const float* cls_b1    = (const float*)d_in[6];
    const float* cls_w2    = (const float*)d_in[7];
    const float* cls_b2    = (const float*)d_in[8];
    const float* fus_w     = (const float*)d_in[9];
    const float* fus_b     = (const float*)d_in[10];
    const float* fus_g     = (const float*)d_in[11];
    const float* fus_be    = (const float*)d_in[12];
    const float* pa_w      = (const float*)d_in[13];
    const float* pa_b      = (const float*)d_in[14];
    const float* pa_g      = (const float*)d_in[15];
    const float* pa_be     = (const float*)d_in[16];
    const float* pv_w      = (const float*)d_in[17];
    const float* pv_b      = (const float*)d_in[18];
    const float* pv_g      = (const float*)d_in[19];
    const float* pv_be     = (const float*)d_in[20];
    float* out = (float*)d_out;

    float *pMC, *pd, *pav, *py, *pvq, *pbcomb, *phb;
    __half *pqMh, *qhi, *w1hi, *uhi, *ulo, *vhi, *vlo,
        *mchi, *mclo, *qvhi, *xhi, *hwhi, *hwlo;
    cudaGetSymbolAddress((void**)&pMC, g_MC);
    cudaGetSymbolAddress((void**)&pqMh, g_qM_h);
    cudaGetSymbolAddress((void**)&pd, g_d);
    cudaGetSymbolAddress((void**)&pav, g_av);
    cudaGetSymbolAddress((void**)&py, g_y);
    cudaGetSymbolAddress((void**)&pvq, g_vq);
    cudaGetSymbolAddress((void**)&pbcomb, g_bcomb);
    cudaGetSymbolAddress((void**)&phb, g_hbias);
    cudaGetSymbolAddress((void**)&qhi, g_q_hi);
    cudaGetSymbolAddress((void**)&w1hi, g_w1_hi);
    cudaGetSymbolAddress((void**)&uhi, g_u_hi);
    cudaGetSymbolAddress((void**)&ulo, g_u_lo);
    cudaGetSymbolAddress((void**)&vhi, g_v_hi);
    cudaGetSymbolAddress((void**)&vlo, g_v_lo);
    cudaGetSymbolAddress((void**)&mchi, g_mc_hi);
    cudaGetSymbolAddress((void**)&mclo, g_mc_lo);
    cudaGetSymbolAddress((void**)&qvhi, g_qv_hi);
    cudaGetSymbolAddress((void**)&xhi, g_x_hi);
    cudaGetSymbolAddress((void**)&hwhi, g_hw_hi);
    cudaGetSymbolAddress((void**)&hwlo, g_hw_lo);

    cudaFuncSetAttribute((const void*)bsgemm<3, false, false, false>,
                         cudaFuncAttributeMaxDynamicSharedMemorySize, GEMM_SMEM);
    cudaFuncSetAttribute((const void*)bsgemm<2, true, false, false>,
                         cudaFuncAttributeMaxDynamicSharedMemorySize, GEMM_SMEM);
    cudaFuncSetAttribute((const void*)bsgemm<1, true, false, true>,
                         cudaFuncAttributeMaxDynamicSharedMemorySize, GEMM_SMEM);
    cudaFuncSetAttribute((const void*)bsgemm<1, false, true, false>,
                         cudaFuncAttributeMaxDynamicSharedMemorySize, GEMM_SMEM);
    cudaFuncSetAttribute((const void*)attn_kernel,
                         cudaFuncAttributeMaxDynamicSharedMemorySize, ATTN_SMEM);

    // 1) tiny precomputations
    vec_pre<<<D + 1, 256>>>(in_proj_w, in_proj_b, out_w, out_b);
    pack_bias<<<6, 256>>>(fus_b, pa_b, pv_b);
    zero_d<<<B * S / 256, 256>>>();

    // 2) conversions of inputs
    split_hi<<<(int)(NQ / 4 / 256), 256>>>(q, qhi, NQ / 4);
    split_hi<<<(int)((long)S * H * D / 4 / 256), 256>>>(cls_w1, w1hi,
                                                        (long)S * H * D / 4);
    split4<<<D * D / 4 / 256, 256>>>(out_w, uhi + (long)D * D, ulo + (long)D * D,
                                     D * D / 4, SWT);
    split4<<<F * D / 4 / 256, 256>>>(fus_w, hwhi, hwlo, (long)F * D / 4, SWT);
    split4<<<F * D / 4 / 256, 256>>>(pa_w, hwhi + (long)F * D, hwlo + (long)F * D,
                                     (long)F * D / 4, SWT);
    split4<<<F * D / 4 / 256, 256>>>(pv_w, hwhi + 2L * F * D, hwlo + 2L * F * D,
                                     (long)F * D / 4, SWT);
    tsplit<<<dim3(32, 32), dim3(32, 8)>>>(in_proj_w + (long)D * D, uhi, ulo);    // WkT
    tsplit<<<dim3(32, 32), dim3(32, 8)>>>(in_proj_w, vhi, vlo);                  // WqT
    tsplit<<<dim3(32, 32), dim3(32, 8)>>>(in_proj_w + 2L * D * D,
                                          vhi + (long)D * D, vlo + (long)D * D); // WvT

    // 3) [Mt; Cov] one z=2 launch (3-term), then split (x32)
    bsgemm<3, false, false, false><<<dim3(8, 8, 2), 256, GEMM_SMEM>>>(
        uhi, ulo, D, (long)D * D, vhi, vlo, (long)D * D,
        pMC, D, (long)D * D, nullptr, 0L, nullptr, SC_WW);
    split4<<<2 * D * D / 4 / 256, 256>>>(pMC, mchi, mclo, 2 * D * D / 4, SWT);

    // 4) qM = q * Mt^T + vq  (1-term, fp16 output)
    bsgemm<1, true, false, true><<<dim3(8, 512), 256, GEMM_SMEM>>>(
        qhi, nullptr, (long)D, 0L, mchi, nullptr, 0L, (float*)pqMh, D, 0L,
        pvq, 0L, nullptr, SC_QW);

    // 5) classifier: h = relu(q w1^T + b1), d += h.w2 (1-term, atomic)
    bsgemm<1, false, true, false><<<dim3(4, 16, 32), 256, GEMM_SMEM>>>(
        qhi, nullptr, (long)S * D, (long)D, w1hi, nullptr, (long)H * D,
        pd, S, 0L, cls_b1, (long)H, cls_w2, 1.f);

    // 6) attention (scores on HMMA) -> d_a/d_v out, qv hi
    attn_kernel<<<B, 256, ATTN_SMEM>>>(cls_b2, out);

    // 7) [audio; video] = qv * Cov^T + bcomb  (2-term)
    bsgemm<2, true, false, false><<<dim3(8, 32), 256, GEMM_SMEM>>>(
        qvhi, nullptr, (long)D, 0L, mchi + (long)D * D, mclo + (long)D * D, 0L,
        pav, D, 0L, pbcomb, 0L, nullptr, SC_QW);

    // 8) fusion + hi-convert of head inputs
    avhi<<<(int)((long)B * D / 4 / 256), 256>>>();

    // 9) heads: one z=3 launch  y = x * W^T + b  (2-term)
    bsgemm<2, true, false, false><<<dim3(4, 16, 3), 256, GEMM_SMEM>>>(
        xhi, nullptr, (long)D, (long)B * D, hwhi, hwlo, (long)F * D,
        py, F, (long)B * F, phb, (long)F, nullptr, SC_QW);

    // 10) LayerNorm + ReLU -> final outputs
    ln_relu<<<dim3(B, 3), 128>>>(fus_g, fus_be, pa_g, pa_be, pv_g, pv_be, out);
}

// round 14
// speedup vs baseline: 6.6020x; 1.0358x over previous
#include <cuda_runtime.h>
#include <cuda_fp16.h>
#include <cstdint>

// =============================================================================
// RAFF_8555574853896 — round 14: stream-forked conversions (overlap with qM),
// K-chunk-64 + x4-B loads for 1-term GEMMs, av GEMM writes fp16 x directly,
// fusion computed from fp16. Everything else as validated round 13.
//
// Algebra:
//   scores = q Mt^T q^T / sqrt(D) + rank-1 bias,  Mt = (Wq^T Wk)^T
//   audio  = (w_a^T q) Cov^T + bcomb,             Cov = out_w Wv
// =============================================================================

namespace raff {

constexpr int B = 2048, S = 32, P = 16, D = 1024, H = 512, F = 512;
constexpr long NQ = (long)B * S * D;

constexpr float SWT = 32.f;
constexpr float SC_QW = 1.f / SWT;
constexpr float SC_WW = 1.f / (SWT * SWT);

// ---------------- static device scratch ----------------
__device__ float g_vq[D], g_vk[D], g_bcomb[D];
__device__ float g_c0;
__device__ float g_MC[2 * D * D];              // [Mt; Cov] fp32
__device__ float g_d[B * S];
__device__ float g_y[3L * B * F];
__device__ float g_hbias[3 * F];

__device__ __half g_qM_h[NQ];                  // qM fp16 (128 MB)
__device__ __half g_q_hi[NQ];
__device__ __half g_w1_hi[(long)S * H * D];
__device__ __half g_u_hi[2 * D * D], g_u_lo[2 * D * D];    // [WkT; out_w] x32
__device__ __half g_v_hi[2 * D * D], g_v_lo[2 * D * D];    // [WqT; WvT] x32
__device__ __half g_mc_hi[2 * D * D], g_mc_lo[2 * D * D];  // [Mt; Cov] x32
__device__ __half g_qv_hi[2L * B * D];
__device__ __half g_x_hi[3L * B * D];          // fusion | audio | video
__device__ __half g_hw_hi[3L * F * D], g_hw_lo[3L * F * D];

// ---------------- PTX helpers (base sm_103-legal) ----------------
__device__ __forceinline__ uint32_t smem_u32(const void* p) {
    uint32_t a;
    asm("{ .reg .u64 t; cvta.to.shared.u64 t, %1; cvt.u32.u64 %0, t; }"
        : "=r"(a) : "l"(p));
    return a;
}
#define CP16(dst, src) \
    asm volatile("cp.async.cg.shared.global [%0], [%1], 16;" :: "r"(dst), "l"(src))
#define CP_COMMIT() asm volatile("cp.async.commit_group;" ::: "memory")

__device__ __forceinline__ void ldsm_x4(uint32_t* r, uint32_t addr) {
    asm volatile("ldmatrix.sync.aligned.m8n8.x4.shared.b16 {%0,%1,%2,%3}, [%4];"
                 : "=r"(r[0]), "=r"(r[1]), "=r"(r[2]), "=r"(r[3]) : "r"(addr));
}
__device__ __forceinline__ void ldsm_x2(uint32_t* r, uint32_t addr) {
    asm volatile("ldmatrix.sync.aligned.m8n8.x2.shared.b16 {%0,%1}, [%2];"
                 : "=r"(r[0]), "=r"(r[1]) : "r"(addr));
}
__device__ __forceinline__ void mma_f16(float* c, const uint32_t* a, const uint32_t* b) {
    asm volatile(
        "mma.sync.aligned.m16n8k16.row.col.f32.f16.f16.f32 "
        "{%0,%1,%2,%3}, {%4,%5,%6,%7}, {%8,%9}, {%0,%1,%2,%3};"
        : "+f"(c[0]), "+f"(c[1]), "+f"(c[2]), "+f"(c[3])
        : "r"(a[0]), "r"(a[1]), "r"(a[2]), "r"(a[3]), "r"(b[0]), "r"(b[1]));
}

// Swizzled address within a 128-row x 64B chunk.
__device__ __forceinline__ uint32_t swz(int r, int c) {
    return (uint32_t)((r * 4 + (c ^ ((r >> 1) & 3))) * 16);
}

__device__ __forceinline__ void hsplit(float x, float s, __half& hi, __half& lo) {
    const float xs = x * s;
    hi = __float2half_rn(xs);
    lo = __float2half_rn(xs - __half2float(hi));
}

// =============================================================================
// fp16 split GEMM. Block 128x128, 8 warps (2m x 4n), warp 64x32, 3 stages.
// TERMS==1: K-chunk 64, B frags via x4.  TERMS>=2: K-chunk 32 (R13 path).
// =============================================================================
constexpr int STAGE = 32768;
constexpr int NSTG = 3;
constexpr int GEMM_SMEM = NSTG * STAGE;

template <int TERMS, bool BIAS, bool CLSD, bool HOUT>
__global__ void __launch_bounds__(256, 2) bsgemm(
    const __half* __restrict__ Ahi, const __half* __restrict__ Alo,
    long lda, long aOffZ,
    const __half* __restrict__ Bhi, const __half* __restrict__ Blo,
    long bOffZ,
    float* __restrict__ C, int ldc, long cOffZ,
    const float* __restrict__ bias, long biasOffZ,
    const float* __restrict__ w2p, float scaleC)
{
    extern __shared__ char dsm[];
    const uint32_t base = smem_u32(dsm);

    const int tid = threadIdx.x, lane = tid & 31, w = tid >> 5;
    const int wm = w & 1, wn = w >> 1;
    const int z = blockIdx.z;
    const long m0 = (long)blockIdx.y * 128;
    const long n0 = (long)blockIdx.x * 128;
    Ahi += z * aOffZ;
    if (TERMS >= 3) Alo += z * aOffZ;
    Bhi += z * bOffZ;
    if (TERMS >= 2) Blo += z * bOffZ;
    C += z * cOffZ;
    if (BIAS || CLSD) bias += z * biasOffZ;

    float acc[4][4][4];
#pragma unroll
    for (int i = 0; i < 4; i++)
#pragma unroll
        for (int j = 0; j < 4; j++)
#pragma unroll
            for (int k = 0; k < 4; k++) acc[i][j][k] = 0.f;

    // ---------- TERMS>=2 path: K-chunk 32 ----------
    auto loadChunk = [&](int s, int kc) {
        const long k0 = (long)kc * 32;
        const uint32_t ah = base + s * STAGE;
        const uint32_t al = ah + 8192;
        const uint32_t bh = ah + 16384;
        const uint32_t bl = ah + 24576;
#pragma unroll
        for (int i = 0; i < 2; i++) {
            const int idx = tid + 256 * i;
            const int r = idx >> 2, c = idx & 3;
            const uint32_t dst = swz(r, c);
            const long offA = (m0 + r) * lda + k0 + c * 8;
            CP16(ah + dst, Ahi + offA);
            if (TERMS >= 3) CP16(al + dst, Alo + offA);
            const long offB = (n0 + r) * 1024 + k0 + c * 8;
            CP16(bh + dst, Bhi + offB);
            if (TERMS >= 2) CP16(bl + dst, Blo + offB);
        }
        CP_COMMIT();
    };

    auto computeChunk = [&](int s) {
        const uint32_t ah = base + s * STAGE;
        const uint32_t al = ah + 8192;
        const uint32_t bh = ah + 16384;
        const uint32_t bl = ah + 24576;
#pragma unroll
        for (int ks = 0; ks < 2; ks++) {
            uint32_t afh[4][4], afl[4][4], bf[4][2];
            const int arow = wm * 64 + (lane & 15);
            const int akc = ks * 2 + (lane >> 4);
#pragma unroll
            for (int i = 0; i < 4; i++) {
                const uint32_t off = swz(arow + i * 16, akc);
                ldsm_x4(afh[i], ah + off);
                if (TERMS >= 3) ldsm_x4(afl[i], al + off);
            }
            const int brow = wn * 32 + (lane & 7);
            const int bkc = ks * 2 + ((lane >> 3) & 1);
#pragma unroll
            for (int j = 0; j < 4; j++)
                ldsm_x2(bf[j], bh + swz(brow + j * 8, bkc));
#pragma unroll
            for (int i = 0; i < 4; i++)
#pragma unroll
                for (int j = 0; j < 4; j++) mma_f16(acc[i][j], afh[i], bf[j]);
            if (TERMS >= 3) {
#pragma unroll
                for (int i = 0; i < 4; i++)
#pragma unroll
                    for (int j = 0; j < 4; j++) mma_f16(acc[i][j], afl[i], bf[j]);
            }
            if (TERMS >= 2) {
#pragma unroll
                for (int j = 0; j < 4; j++)
                    ldsm_x2(bf[j], bl + swz(brow + j * 8, bkc));
#pragma unroll
                for (int i = 0; i < 4; i++)
#pragma unroll
                    for (int j = 0; j < 4; j++) mma_f16(acc[i][j], afh[i], bf[j]);
            }
        }
    };

    // ---------- TERMS==1 path: K-chunk 64 (A 2x8K | B 2x8K per stage) ----------
    auto load64 = [&](int s, int kc) {
        const long k0 = (long)kc * 64;
        const uint32_t ah = base + s * STAGE;
        const uint32_t bh = ah + 16384;
#pragma unroll
        for (int i = 0; i < 4; i++) {
            const int u = tid + 256 * i;         // 0..1023
            const int r = u >> 3, uu = u & 7;
            const int sub = uu >> 2, c = uu & 3;
            const uint32_t dst = sub * 8192 + swz(r, c);
            CP16(ah + dst, Ahi + (m0 + r) * lda + k0 + uu * 8);
            CP16(bh + dst, Bhi + (n0 + r) * 1024 + k0 + uu * 8);
        }
        CP_COMMIT();
    };

    auto compute64 = [&](int s) {
        const uint32_t ah = base + s * STAGE;
        const uint32_t bh = ah + 16384;
#pragma unroll
        for (int sub = 0; sub < 2; sub++) {
            const uint32_t ac = ah + sub * 8192;
            const uint32_t bc = bh + sub * 8192;
#pragma unroll
            for (int ks = 0; ks < 2; ks++) {
                uint32_t af[4][4], bq[2][4];
                const int arow = wm * 64 + (lane & 15);
                const int akc = ks * 2 + (lane >> 4);
#pragma unroll
                for (int i = 0; i < 4; i++)
                    ldsm_x4(af[i], ac + swz(arow + i * 16, akc));
                const int bnr = wn * 32 + ((lane >> 4) & 1) * 8 + (lane & 7);
                const int bkc = ks * 2 + ((lane >> 3) & 1);
#pragma unroll
                for (int jj = 0; jj < 2; jj++)
                    ldsm_x4(bq[jj], bc + swz(bnr + jj * 16, bkc));
#pragma unroll
                for (int i = 0; i < 4; i++)
#pragma unroll
                    for (int j = 0; j < 4; j++)
                        mma_f16(acc[i][j], af[i], &bq[j >> 1][(j & 1) * 2]);
            }
        }
    };

    if (TERMS == 1) {
        load64(0, 0);
        load64(1, 1);
        for (int ch = 0; ch < 16; ch++) {
            asm volatile("cp.async.wait_group 1;" ::: "memory");
            __syncthreads();
            if (ch + 2 < 16) load64((ch + 2) % 3, ch + 2);
            else CP_COMMIT();
            compute64(ch % 3);
        }
    } else {
        loadChunk(0, 0);
        loadChunk(1, 1);
        for (int ch = 0; ch < 32; ch++) {
            asm volatile("cp.async.wait_group 1;" ::: "memory");
            __syncthreads();
            if (ch + 2 < 32) loadChunk((ch + 2) % 3, ch + 2);
            else CP_COMMIT();
            computeChunk(ch % 3);
        }
    }

    const int gr = lane >> 2, qd = lane & 3;

    if (CLSD) {
        float p[4][2];
#pragma unroll
        for (int i = 0; i < 4; i++) { p[i][0] = 0.f; p[i][1] = 0.f; }
        const float* w2 = w2p + (long)z * H;
#pragma unroll
        for (int j = 0; j < 4; j++) {
            const long c = n0 + wn * 32 + j * 8 + qd * 2;
            const float2 w2v = *(const float2*)&w2[c];
            const float2 bv = *(const float2*)&bias[c];
#pragma unroll
            for (int i = 0; i < 4; i++) {
                const float h0 = fmaxf(acc[i][j][0] * scaleC + bv.x, 0.f);
                const float h1 = fmaxf(acc[i][j][1] * scaleC + bv.y, 0.f);
                p[i][0] += h0 * w2v.x + h1 * w2v.y;
                const float h2 = fmaxf(acc[i][j][2] * scaleC + bv.x, 0.f);
                const float h3 = fmaxf(acc[i][j][3] * scaleC + bv.y, 0.f);
                p[i][1] += h2 * w2v.x + h3 * w2v.y;
            }
        }
#pragma unroll
        for (int i = 0; i < 4; i++) {
            p[i][0] += __shfl_xor_sync(~0u, p[i][0], 1);
            p[i][0] += __shfl_xor_sync(~0u, p[i][0], 2);
            p[i][1] += __shfl_xor_sync(~0u, p[i][1], 1);
            p[i][1] += __shfl_xor_sync(~0u, p[i][1], 2);
            if (qd == 0) {
                const long r = m0 + wm * 64 + i * 16 + gr;
                atomicAdd(&C[r * S + z], p[i][0]);
                atomicAdd(&C[(r + 8) * S + z], p[i][1]);
            }
        }
    } else {
#pragma unroll
        for (int j = 0; j < 4; j++) {
            const long c = n0 + wn * 32 + j * 8 + qd * 2;
            float2 bv = make_float2(0.f, 0.f);
            if (BIAS) bv = *(const float2*)&bias[c];
#pragma unroll
            for (int i = 0; i < 4; i++) {
                const long r0 = m0 + wm * 64 + i * 16 + gr;
                float2 v0 = make_float2(acc[i][j][0] * scaleC + bv.x,
                                        acc[i][j][1] * scaleC + bv.y);
                float2 v1 = make_float2(acc[i][j][2] * scaleC + bv.x,
                                        acc[i][j][3] * scaleC + bv.y);
                if (HOUT) {
                    __half* Ch = (__half*)C;
                    *(__half2*)&Ch[r0 * ldc + c] = __floats2half2_rn(v0.x, v0.y);
                    *(__half2*)&Ch[(r0 + 8) * ldc + c] = __floats2half2_rn(v1.x, v1.y);
                } else {
                    *(float2*)&C[r0 * ldc + c] = v0;
                    *(float2*)&C[(r0 + 8) * ldc + c] = v1;
                }
            }
        }
    }
}

// =============================================================================
// conversion kernels
// =============================================================================
__global__ void split4(const float* __restrict__ src, __half* __restrict__ hi,
                       __half* __restrict__ lo, long n4, float s)
{
    const long i = (long)blockIdx.x * 256 + threadIdx.x;
    if (i >= n4) return;
    float4 v = ((const float4*)src)[i];
    __half h0, h1, h2, h3, l0, l1, l2, l3;
    hsplit(v.x, s, h0, l0);
    hsplit(v.y, s, h1, l1);
    hsplit(v.z, s, h2, l2);
    hsplit(v.w, s, h3, l3);
    __half2 a, b;
    a.x = h0; a.y = h1; b.x = h2; b.y = h3;
    ((__half2*)hi)[2 * i] = a; ((__half2*)hi)[2 * i + 1] = b;
    a.x = l0; a.y = l1; b.x = l2; b.y = l3;
    ((__half2*)lo)[2 * i] = a; ((__half2*)lo)[2 * i + 1] = b;
}

__global__ void split_hi(const float* __restrict__ src, __half* __restrict__ hi,
                         long n4)
{
    const long i = (long)blockIdx.x * 256 + threadIdx.x;
    if (i >= n4) return;
    float4 v = ((const float4*)src)[i];
    __half2 a, b;
    a.x = __float2half_rn(v.x); a.y = __float2half_rn(v.y);
    b.x = __float2half_rn(v.z); b.y = __float2half_rn(v.w);
    ((__half2*)hi)[2 * i] = a; ((__half2*)hi)[2 * i + 1] = b;
}

__global__ void tsplit(const float* __restrict__ src, __half* __restrict__ hi,
                       __half* __restrict__ lo)
{
    __shared__ float t[32][33];
    const int bx = blockIdx.x * 32, by = blockIdx.y * 32;
    const int tx = threadIdx.x;
    for (int j = threadIdx.y; j < 32; j += 8)
        t[j][tx] = src[(long)(by + j) * 1024 + bx + tx];
    __syncthreads();
    for (int j = threadIdx.y; j < 32; j += 8) {
        const long o = (long)(bx + j) * 1024 + by + tx;
        __half h, l;
        hsplit(t[tx][j], SWT, h, l);
        hi[o] = h; lo[o] = l;
    }
}

// fusion (fp16) = 0.5 * (audio_fp16 + video_fp16)
__global__ void fuse_half()
{
    const long i = (long)blockIdx.x * 256 + threadIdx.x;   // 4 half2 each
    const __half2* a = (const __half2*)(g_x_hi + (long)B * D);
    const __half2* v = (const __half2*)(g_x_hi + 2L * B * D);
    __half2* f = (__half2*)g_x_hi;
#pragma unroll
    for (int j = 0; j < 4; j++) {
        float2 xf = __half22float2(a[4 * i + j]);
        float2 yf = __half22float2(v[4 * i + j]);
        f[4 * i + j] = __floats2half2_rn(0.5f * (xf.x + yf.x), 0.5f * (xf.y + yf.y));
    }
}

// zero g_d (blocks 0..255) + pack head biases (blocks 256..261)
__global__ void misc_init(const float* __restrict__ b0, const float* __restrict__ b1,
                          const float* __restrict__ b2)
{
    const int blk = blockIdx.x;
    if (blk < 256) { g_d[blk * 256 + threadIdx.x] = 0.f; return; }
    const int i = (blk - 256) * 256 + threadIdx.x;
    if (i < 3 * F) {
        const int hh = i >> 9, j = i & 511;
        g_hbias[i] = hh == 0 ? b0[j] : (hh == 1 ? b1[j] : b2[j]);
    }
}

// =============================================================================
// bias-derived vectors: one block per output element
// =============================================================================
__global__ void __launch_bounds__(256) vec_pre(
    const float* __restrict__ in_proj_w, const float* __restrict__ in_proj_b,
    const float* __restrict__ out_w, const float* __restrict__ out_b)
{
    const float* wq = in_proj_w;
    const float* wk = in_proj_w + (long)D * D;
    const float* bq = in_proj_b;
    const float* bk = in_proj_b + D;
    const float* bv = in_proj_b + 2 * D;
    __shared__ float rs[3][8];
    const int t = threadIdx.x, w = t >> 5, lane = t & 31;
    const int i = blockIdx.x;
    float v0 = 0.f, v1 = 0.f, v2 = 0.f;
    if (i < D) {
        for (int e = t; e < D; e += 256) {
            v0 = fmaf(bq[e], wk[(long)e * D + i], v0);
            v1 = fmaf(bk[e], wq[(long)e * D + i], v1);
            v2 = fmaf(out_w[(long)i * D + e], bv[e], v2);
        }
    } else {
        for (int e = t; e < D; e += 256) v0 = fmaf(bq[e], bk[e], v0);
    }
#pragma unroll
    for (int o = 16; o > 0; o >>= 1) {
        v0 += __shfl_xor_sync(~0u, v0, o);
        v1 += __shfl_xor_sync(~0u, v1, o);
        v2 += __shfl_xor_sync(~0u, v2, o);
    }
    if (lane == 0) { rs[0][w] = v0; rs[1][w] = v1; rs[2][w] = v2; }
    __syncthreads();
    if (t == 0) {
        float s0 = 0.f, s1 = 0.f, s2 = 0.f;
#pragma unroll
        for (int j = 0; j < 8; j++) { s0 += rs[0][j]; s1 += rs[1][j]; s2 += rs[2][j]; }
        if (i < D) { g_vq[i] = s0; g_vk[i] = s1; g_bcomb[i] = s2 + out_b[i]; }
        else g_c0 = s0;
    }
}

// =============================================================================
// Per-batch attention — scores on HMMA (validated round 13, unchanged)
// =============================================================================
constexpr int ATTN_SMEM = 65536 + 65536 + 8 * 32 * 33 * 4;

__global__ void __launch_bounds__(256) attn_kernel(
    const float* __restrict__ cls_b2, float* __restrict__ out)
{
    extern __shared__ char dsm[];
    const uint32_t sbase = smem_u32(dsm);
    const uint32_t QOFF = 0, QMOFF = 65536, POFF = 131072;
    float* part = (float*)(dsm + POFF);

    __shared__ float sc[32][33];
    __shared__ float vks[1024];
    __shared__ float dd[32], rk[32], wa[32], wvv[32], da[16], dv[16];

    const int b = blockIdx.x;
    const int tid = threadIdx.x, w = tid >> 5, lane = tid & 31;
    const __half* qbh = g_q_hi + (long)b * S * D;
    const __half* qmbh = g_qM_h + (long)b * S * D;

#pragma unroll
    for (int i = 0; i < 16; i++) {
        const int u = tid + 256 * i;
        const int r = (u >> 7);
        const int uu = u & 127;
        const int kc = uu >> 2, c = uu & 3;
        const long src = (long)r * D + uu * 8;
        CP16(sbase + QOFF + kc * 2048 + swz(r, c), qbh + src);
        CP16(sbase + QMOFF + kc * 2048 + swz(r, c), qmbh + src);
    }
    CP_COMMIT();
#pragma unroll
    for (int i = 0; i < 4; i++) vks[tid + 256 * i] = g_vk[tid + 256 * i];
    if (tid < 32) dd[tid] = fmaxf(g_d[b * S + tid] + cls_b2[tid], 0.f);
    asm volatile("cp.async.wait_group 0;" ::: "memory");
    __syncthreads();

    {
        float acc[2][4][4];
#pragma unroll
        for (int i = 0; i < 2; i++)
#pragma unroll
            for (int j = 0; j < 4; j++)
#pragma unroll
                for (int k = 0; k < 4; k++) acc[i][j][k] = 0.f;
#pragma unroll
        for (int cc = 0; cc < 4; cc++) {
            const uint32_t qc = sbase + QOFF + (4 * w + cc) * 2048;
            const uint32_t qmc = sbase + QMOFF + (4 * w + cc) * 2048;
#pragma unroll
            for (int ks = 0; ks < 2; ks++) {
                uint32_t af[2][4], bf[4][2];
                const int arow = lane & 15;
                const int akc = ks * 2 + (lane >> 4);
#pragma unroll
                for (int i = 0; i < 2; i++)
                    ldsm_x4(af[i], qmc + swz(i * 16 + arow, akc));
                const int brow = lane & 7;
                const int bkc = ks * 2 + ((lane >> 3) & 1);
#pragma unroll
                for (int j = 0; j < 4; j++)
                    ldsm_x2(bf[j], qc + swz(j * 8 + brow, bkc));
#pragma unroll
                for (int i = 0; i < 2; i++)
#pragma unroll
                    for (int j = 0; j < 4; j++) mma_f16(acc[i][j], af[i], bf[j]);
            }
        }
        float* pw = part + w * 1056;
        const int gr = lane >> 2, qd = lane & 3;
#pragma unroll
        for (int i = 0; i < 2; i++)
#pragma unroll
            for (int j = 0; j < 4; j++) {
                const int r = i * 16 + gr, c = j * 8 + qd * 2;
                pw[r * 33 + c] = acc[i][j][0];
                pw[r * 33 + c + 1] = acc[i][j][1];
                pw[(r + 8) * 33 + c] = acc[i][j][2];
                pw[(r + 8) * 33 + c + 1] = acc[i][j][3];
            }
    }
    __syncthreads();

#pragma unroll
    for (int i = 0; i < 4; i++) {
        const int e = tid + 256 * i;
        const int r = e >> 5, c = e & 31;
        float s = 0.f;
#pragma unroll
        for (int ww = 0; ww < 8; ww++) s += part[ww * 1056 + r * 33 + c];
        sc[r][c] = s;
    }
    {
        const int row = tid >> 3, seg = tid & 7;
        float r2 = 0.f;
        for (int j = 0; j < 128; j++) {
            const int k = seg * 128 + j;
            const uint32_t off = QOFF + (k >> 5) * 2048 + swz(row, (k >> 3) & 3) + (k & 7) * 2;
            r2 = fmaf(__half2float(*(const __half*)(dsm + off)), vks[k], r2);
        }
        r2 += __shfl_xor_sync(~0u, r2, 1);
        r2 += __shfl_xor_sync(~0u, r2, 2);
        r2 += __shfl_xor_sync(~0u, r2, 4);
        if (seg == 0) rk[row] = r2;
    }
    __syncthreads();

    const float inv_sqrtD = 0.03125f;
    for (int rr = w * 4; rr < w * 4 + 4; rr++) {
        float v = (sc[rr][lane] + rk[rr] + g_c0) * inv_sqrtD;
        float mx = v;
#pragma unroll
        for (int o = 16; o > 0; o >>= 1) mx = fmaxf(mx, __shfl_xor_sync(~0u, mx, o));
        float e = __expf(v - mx);
        float sum = e;
#pragma unroll
        for (int o = 16; o > 0; o >>= 1) sum += __shfl_xor_sync(~0u, sum, o);
        sc[rr][lane] = e / sum;
    }
    __syncthreads();

    if (tid < 32) {
        const bool isA = tid < 16;
        const int i = tid & 15;
        float v = dd[tid];
        float mx = v;
#pragma unroll
        for (int o = 8; o > 0; o >>= 1) mx = fmaxf(mx, __shfl_xor_sync(~0u, mx, o));
        float e = __expf(v - mx);
        float sum = e;
#pragma unroll
        for (int o = 8; o > 0; o >>= 1) sum += __shfl_xor_sync(~0u, sum, o);
        const float p = e / sum;
        if (isA) da[i] = p; else dv[i] = p;
        const long bse = 3L * B * F;
        if (isA) out[bse + (long)b * P + i] = p;
        else     out[bse + (long)B * P + (long)b * P + i] = p;
    }
    __syncthreads();

    if (tid < 32) {
        float a = 0.f, v2 = 0.f;
#pragma unroll
        for (int ss = 0; ss < 16; ss++) a = fmaf(da[ss], sc[ss][tid], a);
#pragma unroll
        for (int ss = 0; ss < 16; ss++) v2 = fmaf(dv[ss], sc[16 + ss][tid], v2);
        wa[tid] = a;
        wvv[tid] = v2;
    }
    __syncthreads();

#pragma unroll
    for (int i = 0; i < 4; i++) {
        const int col = tid + 256 * i;
        const uint32_t cb = QOFF + (col >> 5) * 2048;
        const int cc4 = (col >> 3) & 3;
        const int co = (col & 7) * 2;
        float a = 0.f, v2 = 0.f;
#pragma unroll
        for (int t = 0; t < 32; t++) {
            const float x = __half2float(*(const __half*)(dsm + cb + swz(t, cc4) + co));
            a = fmaf(wa[t], x, a);
            v2 = fmaf(wvv[t], x, v2);
        }
        const long ia = (long)b * D + col;
        g_qv_hi[ia] = __float2half_rn(a);
        g_qv_hi[(long)B * D + ia] = __float2half_rn(v2);
    }
}

__global__ void __launch_bounds__(128) ln_relu(
    const float* __restrict__ gm0, const float* __restrict__ be0,
    const float* __restrict__ gm1, const float* __restrict__ be1,
    const float* __restrict__ gm2, const float* __restrict__ be2,
    float* __restrict__ out)
{
    const int head = blockIdx.y, b = blockIdx.x, tid = threadIdx.x;
    const float* gm = head == 0 ? gm0 : (head == 1 ? gm1 : gm2);
    const float* be = head == 0 ? be0 : (head == 1 ? be1 : be2);
    const float* y = g_y + ((long)head * B + b) * F;

    float4 v = *(const float4*)&y[tid * 4];
    float s = v.x + v.y + v.z + v.w;
    float sq = v.x * v.x + v.y * v.y + v.z * v.z + v.w * v.w;
#pragma unroll
    for (int o = 16; o > 0; o >>= 1) {
        s += __shfl_xor_sync(~0u, s, o);
        sq += __shfl_xor_sync(~0u, sq, o);
    }
    __shared__ float ss[4], ssq[4];
    const int w = tid >> 5;
    if ((tid & 31) == 0) { ss[w] = s; ssq[w] = sq; }
    __syncthreads();
    s = ss[0] + ss[1] + ss[2] + ss[3];
    sq = ssq[0] + ssq[1] + ssq[2] + ssq[3];
    const float mean = s * (1.f / F);
    const float var = sq * (1.f / F) - mean * mean;
    const float rstd = rsqrtf(var + 1e-5f);

    float4 g4 = *(const float4*)&gm[tid * 4];
    float4 b4 = *(const float4*)&be[tid * 4];
    float4 o4;
    o4.x = fmaxf((v.x - mean) * rstd * g4.x + b4.x, 0.f);
    o4.y = fmaxf((v.y - mean) * rstd * g4.y + b4.y, 0.f);
    o4.z = fmaxf((v.z - mean) * rstd * g4.z + b4.z, 0.f);
    o4.w = fmaxf((v.w - mean) * rstd * g4.w + b4.w, 0.f);
    *(float4*)&out[((long)head * B + b) * F + tid * 4] = o4;
}

}  // namespace raff

// =============================================================================
// Launch
// =============================================================================
extern "C" void kernel_launch(void* const* d_in, const int* in_sizes, int n_in,
                              void* d_out, int out_size)
{
    using namespace raff;
    (void)in_sizes; (void)n_in; (void)out_size;

    const float* q         = (const float*)d_in[0];
    const float* in_proj_w = (const float*)d_in[1];
    const float* in_proj_b = (const float*)d_in[2];
    const float* out_w     = (const float*)d_in[3];
    const float* out_b     = (const float*)d_in[4];
    const float* cls_w1    = (const float*)d_in[5];
    const float* cls_b1    = (const float*)d_in[6];
    const float* cls_w2    = (const float*)d_in[7];
    const float* cls_b2    = (const float*)d_in[8];
    const float* fus_w     = (const float*)d_in[9];
    const float* fus_b     = (const float*)d_in[10];
    const float* fus_g     = (const float*)d_in[11];
    const float* fus_be    = (const float*)d_in[12];
    const float* pa_w      = (const float*)d_in[13];
    const float* pa_b      = (const float*)d_in[14];
    const float* pa_g      = (const float*)d_in[15];
    const float* pa_be     = (const float*)d_in[16];
    const float* pv_w      = (const float*)d_in[17];
    const float* pv_b      = (const float*)d_in[18];
    const float* pv_g      = (const float*)d_in[19];
    const float* pv_be     = (const float*)d_in[20];
    float* out = (float*)d_out;

    float *pMC, *pd, *py, *pvq, *pbcomb, *phb;
    __half *pqMh, *qhi, *w1hi, *uhi, *ulo, *vhi, *vlo,
        *mchi, *mclo, *qvhi, *xhi, *hwhi, *hwlo;
    cudaGetSymbolAddress((void**)&pMC, g_MC);
    cudaGetSymbolAddress((void**)&pqMh, g_qM_h);
    cudaGetSymbolAddress((void**)&pd, g_d);
    cudaGetSymbolAddress((void**)&py, g_y);
    cudaGetSymbolAddress((void**)&pvq, g_vq);
    cudaGetSymbolAddress((void**)&pbcomb, g_bcomb);
    cudaGetSymbolAddress((void**)&phb, g_hbias);
    cudaGetSymbolAddress((void**)&qhi, g_q_hi);
    cudaGetSymbolAddress((void**)&w1hi, g_w1_hi);
    cudaGetSymbolAddress((void**)&uhi, g_u_hi);
    cudaGetSymbolAddress((void**)&ulo, g_u_lo);
    cudaGetSymbolAddress((void**)&vhi, g_v_hi);
    cudaGetSymbolAddress((void**)&vlo, g_v_lo);
    cudaGetSymbolAddress((void**)&mchi, g_mc_hi);
    cudaGetSymbolAddress((void**)&mclo, g_mc_lo);
    cudaGetSymbolAddress((void**)&qvhi, g_qv_hi);
    cudaGetSymbolAddress((void**)&xhi, g_x_hi);
    cudaGetSymbolAddress((void**)&hwhi, g_hw_hi);
    cudaGetSymbolAddress((void**)&hwlo, g_hw_lo);

    cudaFuncSetAttribute((const void*)bsgemm<3, false, false, false>,
                         cudaFuncAttributeMaxDynamicSharedMemorySize, GEMM_SMEM);
    cudaFuncSetAttribute((const void*)bsgemm<2, true, false, true>,
                         cudaFuncAttributeMaxDynamicSharedMemorySize, GEMM_SMEM);
    cudaFuncSetAttribute((const void*)bsgemm<2, true, false, false>,
                         cudaFuncAttributeMaxDynamicSharedMemorySize, GEMM_SMEM);
    cudaFuncSetAttribute((const void*)bsgemm<1, true, false, true>,
                         cudaFuncAttributeMaxDynamicSharedMemorySize, GEMM_SMEM);
    cudaFuncSetAttribute((const void*)bsgemm<1, false, true, false>,
                         cudaFuncAttributeMaxDynamicSharedMemorySize, GEMM_SMEM);
    cudaFuncSetAttribute((const void*)attn_kernel,
                         cudaFuncAttributeMaxDynamicSharedMemorySize, ATTN_SMEM);

    // side stream + events: created once on the correctness call (no capture),
    // reused during graph capture as a parallel branch.
    static cudaStream_t s1 = nullptr;
    static cudaEvent_t ef = nullptr, ej = nullptr;
    if (!s1) {
        cudaStreamCreateWithFlags(&s1, cudaStreamNonBlocking);
        cudaEventCreateWithFlags(&ef, cudaEventDisableTiming);
        cudaEventCreateWithFlags(&ej, cudaEventDisableTiming);
    }

    // 1) tiny precomputations (main stream)
    vec_pre<<<D + 1, 256>>>(in_proj_w, in_proj_b, out_w, out_b);
    misc_init<<<262, 256>>>(fus_b, pa_b, pv_b);

    // ---- fork: independent conversions on side stream ----
    cudaEventRecord(ef, 0);
    cudaStreamWaitEvent(s1, ef, 0);
    split_hi<<<(int)((long)S * H * D / 4 / 256), 256, 0, s1>>>(
        cls_w1, w1hi, (long)S * H * D / 4);
    split4<<<F * D / 4 / 256, 256, 0, s1>>>(fus_w, hwhi, hwlo, (long)F * D / 4, SWT);
    split4<<<F * D / 4 / 256, 256, 0, s1>>>(pa_w, hwhi + (long)F * D,
                                            hwlo + (long)F * D, (long)F * D / 4, SWT);
    split4<<<F * D / 4 / 256, 256, 0, s1>>>(pv_w, hwhi + 2L * F * D,
                                            hwlo + 2L * F * D, (long)F * D / 4, SWT);
    cudaEventRecord(ej, s1);

    // ---- main stream: critical path ----
    split_hi<<<(int)(NQ / 4 / 256), 256>>>(q, qhi, NQ / 4);
    split4<<<D * D / 4 / 256, 256>>>(out_w, uhi + (long)D * D, ulo + (long)D * D,
                                     D * D / 4, SWT);
    tsplit<<<dim3(32, 32), dim3(32, 8)>>>(in_proj_w + (long)D * D, uhi, ulo);    // WkT
    tsplit<<<dim3(32, 32), dim3(32, 8)>>>(in_proj_w, vhi, vlo);                  // WqT
    tsplit<<<dim3(32, 32), dim3(32, 8)>>>(in_proj_w + 2L * D * D,
                                          vhi + (long)D * D, vlo + (long)D * D); // WvT

    // [Mt; Cov] (3-term), then split (x32)
    bsgemm<3, false, false, false><<<dim3(8, 8, 2), 256, GEMM_SMEM>>>(
        uhi, ulo, D, (long)D * D, vhi, vlo, (long)D * D,
        pMC, D, (long)D * D, nullptr, 0L, nullptr, SC_WW);
    split4<<<2 * D * D / 4 / 256, 256>>>(pMC, mchi, mclo, 2 * D * D / 4, SWT);

    // qM = q * Mt^T + vq  (1-term, K64, fp16 output)
    bsgemm<1, true, false, true><<<dim3(8, 512), 256, GEMM_SMEM>>>(
        qhi, nullptr, (long)D, 0L, mchi, nullptr, 0L, (float*)pqMh, D, 0L,
        pvq, 0L, nullptr, SC_QW);

    // ---- join side stream (cls needs w1hi; heads need hw) ----
    cudaStreamWaitEvent(0, ej, 0);

    // classifier (1-term, K64, fused layer 2, atomic)
    bsgemm<1, false, true, false><<<dim3(4, 16, 32), 256, GEMM_SMEM>>>(
        qhi, nullptr, (long)S * D, (long)D, w1hi, nullptr, (long)H * D,
        pd, S, 0L, cls_b1, (long)H, cls_w2, 1.f);

    // attention (scores on HMMA) -> d_a/d_v out, qv hi
    attn_kernel<<<B, 256, ATTN_SMEM>>>(cls_b2, out);

    // [audio; video] = qv * Cov^T + bcomb  (2-term, fp16 out -> x_hi[B*D..3B*D))
    bsgemm<2, true, false, true><<<dim3(8, 32), 256, GEMM_SMEM>>>(
        qvhi, nullptr, (long)D, 0L, mchi + (long)D * D, mclo + (long)D * D, 0L,
        (float*)(xhi + (long)B * D), D, 0L, pbcomb, 0L, nullptr, SC_QW);

    // fusion (fp16) from audio/video fp16
    fuse_half<<<(int)((long)B * D / 8 / 256), 256>>>();

    // heads: one z=3 launch  y = x * W^T + b  (2-term)
    bsgemm<2, true, false, false><<<dim3(4, 16, 3), 256, GEMM_SMEM>>>(
        xhi, nullptr, (long)D, (long)B * D, hwhi, hwlo, (long)F * D,
        py, F, (long)B * F, phb, (long)F, nullptr, SC_QW);

    // LayerNorm + ReLU -> final outputs
    ln_relu<<<dim3(B, 3), 128>>>(fus_g, fus_be, pa_g, pa_be, pv_g, pv_be, out);
}